// round 1
// baseline (speedup 1.0000x reference)
#include <cuda_runtime.h>
#include <math.h>

// ---------------- scratch (static device globals; no allocation) ----------------
__device__ float g_cnn[32768 * 128];     // CNN output per frame
__device__ float g_feats[32768 * 64];    // after FC+BN stack
__device__ float g_xg[32768 * 512];      // precomputed x @ enc_w_ih^T + enc_b
__device__ float g_hbuf[2][1024 * 128];  // h ping-pong
__device__ float g_c[1024 * 128];        // cell state (in-place)
__device__ float g_wdec[512 * 128];      // dec_w_ih + dec_w_hh
__device__ float g_hdec[10][1024 * 128]; // decoder h history for output head

// ---------------- CNN: conv1+relu+pool, conv2+relu+pool ----------------
// 4 frames per block, 128 threads. Padded smem tiles avoid bounds checks.
#define FPB 4
__global__ void cnn_kernel(const float* __restrict__ obs,
                           const float* __restrict__ w1, const float* __restrict__ b1,
                           const float* __restrict__ w2, const float* __restrict__ b2)
{
    __shared__ float s_in[FPB][4][12][12];   // 10x10 + 1 pad each side
    __shared__ float s_p1[FPB][16][7][7];    // 5x5 pooled + 1 pad each side
    __shared__ float s_w1[576];
    __shared__ float s_b1[16];
    __shared__ float s_w2[4608];
    __shared__ float s_b2[32];

    int tid = threadIdx.x; // 128
    for (int i = tid; i < FPB * 4 * 144; i += 128) ((float*)s_in)[i] = 0.f;
    for (int i = tid; i < FPB * 16 * 49; i += 128) ((float*)s_p1)[i] = 0.f;
    for (int i = tid; i < 576; i += 128) s_w1[i] = w1[i];
    if (tid < 16) s_b1[tid] = b1[tid];
    for (int i = tid; i < 4608; i += 128) s_w2[i] = w2[i];
    if (tid < 32) s_b2[tid] = b2[tid];
    __syncthreads();

    int f0 = blockIdx.x * FPB;
    for (int i = tid; i < FPB * 400; i += 128) {
        int f = i / 400, rem = i % 400;
        int ic = rem / 100, p = rem % 100, y = p / 10, x = p % 10;
        s_in[f][ic][y + 1][x + 1] = obs[(long)f0 * 400 + i];
    }
    __syncthreads();

    // phase 1: conv1 (3x3 SAME, 4->16) + relu + maxpool2 -> s_p1 interior
    if (tid < FPB * 25) {
        int f = tid / 25, pp = tid % 25, py = pp / 5, px = pp % 5;
        float patch[4][4][4];
#pragma unroll
        for (int ic = 0; ic < 4; ic++)
#pragma unroll
            for (int r = 0; r < 4; r++)
#pragma unroll
                for (int cc = 0; cc < 4; cc++)
                    patch[ic][r][cc] = s_in[f][ic][2 * py + r][2 * px + cc];
        for (int oc = 0; oc < 16; oc++) {
            float a0 = s_b1[oc], a1 = a0, a2 = a0, a3 = a0;
#pragma unroll
            for (int ic = 0; ic < 4; ic++)
#pragma unroll
                for (int ky = 0; ky < 3; ky++)
#pragma unroll
                    for (int kx = 0; kx < 3; kx++) {
                        float w = s_w1[(oc * 4 + ic) * 9 + ky * 3 + kx];
                        a0 += patch[ic][ky][kx] * w;
                        a1 += patch[ic][ky][kx + 1] * w;
                        a2 += patch[ic][ky + 1][kx] * w;
                        a3 += patch[ic][ky + 1][kx + 1] * w;
                    }
            float m = fmaxf(fmaxf(fmaxf(a0, a1), fmaxf(a2, a3)), 0.f);
            s_p1[f][oc][py + 1][px + 1] = m;
        }
    }
    __syncthreads();

    // phase 2: conv2 (3x3 SAME, 16->32) + relu + maxpool2 (floor: only 4x4 region)
    if (tid < FPB * 16) {
        int f = tid >> 4, ocg = (tid >> 2) & 3, pq = tid & 3;
        int py2 = pq >> 1, px2 = pq & 1;
        float acc[8][4];
#pragma unroll
        for (int a = 0; a < 8; a++) {
            float bb = s_b2[ocg * 8 + a];
#pragma unroll
            for (int p = 0; p < 4; p++) acc[a][p] = bb;
        }
        for (int ic = 0; ic < 16; ic++)
#pragma unroll
            for (int ky = 0; ky < 3; ky++)
#pragma unroll
                for (int kx = 0; kx < 3; kx++) {
                    float iv[4];
#pragma unroll
                    for (int p = 0; p < 4; p++) {
                        int dy2 = p >> 1, dx2 = p & 1;
                        iv[p] = s_p1[f][ic][2 * py2 + dy2 + ky][2 * px2 + dx2 + kx];
                    }
#pragma unroll
                    for (int a = 0; a < 8; a++) {
                        float w = s_w2[((ocg * 8 + a) * 16 + ic) * 9 + ky * 3 + kx];
#pragma unroll
                        for (int p = 0; p < 4; p++) acc[a][p] += iv[p] * w;
                    }
                }
#pragma unroll
        for (int a = 0; a < 8; a++) {
            float m = fmaxf(fmaxf(fmaxf(acc[a][0], acc[a][1]), fmaxf(acc[a][2], acc[a][3])), 0.f);
            g_cnn[(long)(f0 + f) * 128 + (ocg * 8 + a) * 4 + pq] = m;
        }
    }
}

// ---------------- FC stack: fc1+bn1+relu -> fc2+bn2+relu ----------------
// 64 rows per block, 256 threads. 4x8 / 2x8 register tiles.
__global__ void fc_kernel(const float* __restrict__ fc1w, const float* __restrict__ fc1b,
                          const float* __restrict__ g1, const float* __restrict__ be1,
                          const float* __restrict__ m1, const float* __restrict__ v1,
                          const float* __restrict__ fc2w, const float* __restrict__ fc2b,
                          const float* __restrict__ g2, const float* __restrict__ be2,
                          const float* __restrict__ m2, const float* __restrict__ v2)
{
    __shared__ float xs[64 * 128];
    __shared__ float ms[64 * 128];
    int tid = threadIdx.x;
    long r0 = (long)blockIdx.x * 64;
    for (int i = tid; i < 64 * 128; i += 256) xs[i] = g_cnn[r0 * 128 + i];
    __syncthreads();

    int tj = tid & 31, tr = tid >> 5;
    {
        float acc[4][8];
#pragma unroll
        for (int a = 0; a < 4; a++)
#pragma unroll
            for (int b = 0; b < 8; b++) acc[a][b] = 0.f;
        for (int k = 0; k < 128; k++) {
            float hv[8];
#pragma unroll
            for (int b = 0; b < 8; b++) hv[b] = xs[(tr * 8 + b) * 128 + k];
#pragma unroll
            for (int a = 0; a < 4; a++) {
                float wv = fc1w[(tj + 32 * a) * 128 + k];
#pragma unroll
                for (int b = 0; b < 8; b++) acc[a][b] += wv * hv[b];
            }
        }
#pragma unroll
        for (int a = 0; a < 4; a++) {
            int j = tj + 32 * a;
            float s = g1[j] * rsqrtf(v1[j] + 1e-5f);
            float bb = (fc1b[j] - m1[j]) * s + be1[j];
#pragma unroll
            for (int b = 0; b < 8; b++)
                ms[(tr * 8 + b) * 128 + j] = fmaxf(acc[a][b] * s + bb, 0.f);
        }
    }
    __syncthreads();
    {
        float acc[2][8];
#pragma unroll
        for (int a = 0; a < 2; a++)
#pragma unroll
            for (int b = 0; b < 8; b++) acc[a][b] = 0.f;
        for (int k = 0; k < 128; k++) {
            float hv[8];
#pragma unroll
            for (int b = 0; b < 8; b++) hv[b] = ms[(tr * 8 + b) * 128 + k];
#pragma unroll
            for (int a = 0; a < 2; a++) {
                float wv = fc2w[(tj + 32 * a) * 128 + k];
#pragma unroll
                for (int b = 0; b < 8; b++) acc[a][b] += wv * hv[b];
            }
        }
#pragma unroll
        for (int a = 0; a < 2; a++) {
            int j = tj + 32 * a;
            float s = g2[j] * rsqrtf(v2[j] + 1e-5f);
            float bb = (fc2b[j] - m2[j]) * s + be2[j];
#pragma unroll
            for (int b = 0; b < 8; b++)
                g_feats[(r0 + tr * 8 + b) * 64 + j] = fmaxf(acc[a][b] * s + bb, 0.f);
        }
    }
}

// ---------------- encoder x-projection: xg = feats @ enc_w_ih^T + enc_b ----------------
// 32 rows x 512 cols per block, 512 threads, 8x4 register tile.
__global__ void xproj_kernel(const float* __restrict__ wih, const float* __restrict__ eb)
{
    __shared__ float xs[32 * 64];
    int tid = threadIdx.x; // 512
    long r0 = (long)blockIdx.x * 32;
    for (int i = tid; i < 32 * 64; i += 512) xs[i] = g_feats[r0 * 64 + i];
    __syncthreads();

    int tj = tid & 63, tr = tid >> 6; // tr 0..7 -> rows tr*4..+3
    float acc[8][4];
#pragma unroll
    for (int a = 0; a < 8; a++)
#pragma unroll
        for (int b = 0; b < 4; b++) acc[a][b] = 0.f;
    for (int k = 0; k < 64; k++) {
        float hv[4];
#pragma unroll
        for (int b = 0; b < 4; b++) hv[b] = xs[(tr * 4 + b) * 64 + k];
#pragma unroll
        for (int a = 0; a < 8; a++) {
            float wv = wih[(tj + 64 * a) * 64 + k];
#pragma unroll
            for (int b = 0; b < 4; b++) acc[a][b] += wv * hv[b];
        }
    }
#pragma unroll
    for (int a = 0; a < 8; a++) {
        int j = tj + 64 * a;
        float bj = eb[j];
#pragma unroll
        for (int b = 0; b < 4; b++)
            g_xg[(r0 + tr * 4 + b) * 512 + j] = acc[a][b] + bj;
    }
}

// ---------------- prep: W_dec = dec_w_ih + dec_w_hh; zero h0, c0 ----------------
__global__ void prep_kernel(const float* __restrict__ dwi, const float* __restrict__ dwh)
{
    int i = blockIdx.x * 256 + threadIdx.x;
    if (i < 512 * 128) g_wdec[i] = dwi[i] + dwh[i];
    if (i < 1024 * 128) { g_hbuf[0][i] = 0.f; g_c[i] = 0.f; }
}

// ---------------- one LSTM step (encoder or decoder) ----------------
// block tile: 32 batch x 32 hidden units (all 4 gates). grid (32,4), 256 thr.
// dynamic smem: ws[128][129] (gate-major rows, padded) + hs[32][128].
__global__ void lstm_step_kernel(int hin_sel, int hout_sel,
                                 const float* __restrict__ w_enc,
                                 const float* __restrict__ bias,
                                 int t, int is_dec, int s)
{
    extern __shared__ float sm[];
    float* ws = sm;                  // 128*129
    float* hs = sm + 128 * 129;      // 32*128
    const float* w = is_dec ? g_wdec : w_enc;
    const float* h_in = g_hbuf[hin_sel];
    float* h_out = g_hbuf[hout_sel];

    int tid = threadIdx.x;
    int b0 = blockIdx.x * 32;
    int u0 = blockIdx.y * 32;

    // ws row j_local = gate*32 + u_local  <->  global row gate*128 + u0 + u_local
    for (int idx = tid; idx < 128 * 128; idx += 256) {
        int jl = idx >> 7, k = idx & 127;
        int gate = jl >> 5, ul = jl & 31;
        ws[jl * 129 + k] = w[(gate * 128 + u0 + ul) * 128 + k];
    }
    for (int idx = tid; idx < 32 * 128; idx += 256)
        hs[idx] = h_in[b0 * 128 + idx];
    __syncthreads();

    int tj = tid & 31;  // u_local
    int tr = tid >> 5;  // 0..7; rows tr + 8*b
    float acc[4][4];
#pragma unroll
    for (int a = 0; a < 4; a++)
#pragma unroll
        for (int b = 0; b < 4; b++) acc[a][b] = 0.f;

#pragma unroll 4
    for (int k = 0; k < 128; k++) {
        float wv[4], hv[4];
#pragma unroll
        for (int a = 0; a < 4; a++) wv[a] = ws[(a * 32 + tj) * 129 + k];
#pragma unroll
        for (int b = 0; b < 4; b++) hv[b] = hs[(tr + 8 * b) * 128 + k];
#pragma unroll
        for (int a = 0; a < 4; a++)
#pragma unroll
            for (int b = 0; b < 4; b++) acc[a][b] += wv[a] * hv[b];
    }

    int u = u0 + tj;
#pragma unroll
    for (int b = 0; b < 4; b++) {
        int brow = b0 + tr + 8 * b;
        float gi = acc[0][b], gf = acc[1][b], gg = acc[2][b], go = acc[3][b];
        if (!is_dec) {
            const float* xr = g_xg + ((long)brow * 32 + t) * 512;
            gi += xr[0 * 128 + u];
            gf += xr[1 * 128 + u];
            gg += xr[2 * 128 + u];
            go += xr[3 * 128 + u];
        } else {
            gi += bias[0 * 128 + u];
            gf += bias[1 * 128 + u];
            gg += bias[2 * 128 + u];
            go += bias[3 * 128 + u];
        }
        float si = 1.f / (1.f + __expf(-gi));
        float sf = 1.f / (1.f + __expf(-gf));
        float so = 1.f / (1.f + __expf(-go));
        float tg = tanhf(gg);
        int ci = brow * 128 + u;
        float cn = sf * g_c[ci] + si * tg;
        g_c[ci] = cn;
        float hn = so * tanhf(cn);
        h_out[ci] = hn;
        if (is_dec) g_hdec[s][ci] = hn;
    }
}

// ---------------- output head: out[b,s,v] = hdec[s,b,:] @ out_w[v,:] + out_b[v] ----------------
__global__ void head_kernel(const float* __restrict__ ow, const float* __restrict__ ob,
                            float* __restrict__ out)
{
    __shared__ float hsm[64 * 129];
    __shared__ float wsm[12 * 129];
    __shared__ float bsm[12];
    int tid = threadIdx.x;
    int s = blockIdx.y, b0 = blockIdx.x * 64;
    for (int i = tid; i < 64 * 128; i += 256) {
        int r = i >> 7, k = i & 127;
        hsm[r * 129 + k] = g_hdec[s][(b0 + r) * 128 + k];
    }
    for (int i = tid; i < 12 * 128; i += 256) {
        int r = i / 128, k = i % 128;
        wsm[r * 129 + k] = ow[i];
    }
    if (tid < 12) bsm[tid] = ob[tid];
    __syncthreads();
    for (int it = tid; it < 64 * 12; it += 256) {
        int b = it / 12, v = it % 12;
        float acc = bsm[v];
        for (int k = 0; k < 128; k++) acc += hsm[b * 129 + k] * wsm[v * 129 + k];
        out[(long)(b0 + b) * 120 + s * 12 + v] = acc;
    }
}

// ---------------- launcher ----------------
extern "C" void kernel_launch(void* const* d_in, const int* in_sizes, int n_in,
                              void* d_out, int out_size)
{
    const float* obs    = (const float*)d_in[0];
    const float* c1w    = (const float*)d_in[1];
    const float* c1b    = (const float*)d_in[2];
    const float* c2w    = (const float*)d_in[3];
    const float* c2b    = (const float*)d_in[4];
    const float* fc1w   = (const float*)d_in[5];
    const float* fc1b   = (const float*)d_in[6];
    const float* bn1g   = (const float*)d_in[7];
    const float* bn1b   = (const float*)d_in[8];
    const float* bn1m   = (const float*)d_in[9];
    const float* bn1v   = (const float*)d_in[10];
    const float* fc2w   = (const float*)d_in[11];
    const float* fc2b   = (const float*)d_in[12];
    const float* bn2g   = (const float*)d_in[13];
    const float* bn2b   = (const float*)d_in[14];
    const float* bn2m   = (const float*)d_in[15];
    const float* bn2v   = (const float*)d_in[16];
    // d_in[17] = enc_w_ih
    const float* encwih = (const float*)d_in[17];
    const float* encwhh = (const float*)d_in[18];
    const float* encb   = (const float*)d_in[19];
    const float* decwih = (const float*)d_in[20];
    const float* decwhh = (const float*)d_in[21];
    const float* decb   = (const float*)d_in[22];
    const float* outw   = (const float*)d_in[23];
    const float* outb   = (const float*)d_in[24];
    float* out = (float*)d_out;

    const int lstm_smem = (128 * 129 + 32 * 128) * 4; // 82432 B
    cudaFuncSetAttribute(lstm_step_kernel, cudaFuncAttributeMaxDynamicSharedMemorySize, lstm_smem);

    prep_kernel<<<512, 256>>>(decwih, decwhh);
    cnn_kernel<<<32768 / FPB, 128>>>(obs, c1w, c1b, c2w, c2b);
    fc_kernel<<<512, 256>>>(fc1w, fc1b, bn1g, bn1b, bn1m, bn1v,
                            fc2w, fc2b, bn2g, bn2b, bn2m, bn2v);
    xproj_kernel<<<1024, 512>>>(encwih, encb);

    dim3 lgrid(32, 4);
    for (int t = 0; t < 32; t++)
        lstm_step_kernel<<<lgrid, 256, lstm_smem>>>(t & 1, (t + 1) & 1, encwhh, nullptr, t, 0, 0);
    // decoder: x_in == h (carry returns (h,h,c)), so W = w_ih + w_hh precombined
    for (int s = 0; s < 10; s++)
        lstm_step_kernel<<<lgrid, 256, lstm_smem>>>(s & 1, (s + 1) & 1, nullptr, decb, 0, 1, s);

    dim3 hgrid(16, 10);
    head_kernel<<<hgrid, 256>>>(outw, outb, out);
}

// round 3
// speedup vs baseline: 1.9288x; 1.9288x over previous
#include <cuda_runtime.h>
#include <math.h>

// ---------------- scratch (static device globals; no allocation) ----------------
__device__ float g_cnn[32768 * 128];     // CNN output per frame
__device__ float g_feats[32768 * 64];    // after FC+BN stack
__device__ float g_xg[32768 * 512];      // precomputed x @ enc_w_ih^T + enc_b
__device__ float g_hbuf[2][1024 * 128];  // h ping-pong
__device__ float g_c[1024 * 128];        // cell state (in-place)
__device__ float g_wdec[512 * 128];      // dec_w_ih + dec_w_hh
__device__ float g_hdec[10][1024 * 128]; // decoder h history for output head

// ---------------- CNN: conv1+relu+pool, conv2+relu+pool ----------------
#define FPB 4
__global__ void cnn_kernel(const float* __restrict__ obs,
                           const float* __restrict__ w1, const float* __restrict__ b1,
                           const float* __restrict__ w2, const float* __restrict__ b2)
{
    __shared__ float s_in[FPB][4][12][12];   // 10x10 + 1 pad each side
    __shared__ float s_p1[FPB][16][7][7];    // 5x5 pooled + 1 pad each side
    __shared__ float s_w1[576];
    __shared__ float s_b1[16];
    __shared__ float s_w2[4608];
    __shared__ float s_b2[32];

    int tid = threadIdx.x; // 128
    for (int i = tid; i < FPB * 4 * 144; i += 128) ((float*)s_in)[i] = 0.f;
    for (int i = tid; i < FPB * 16 * 49; i += 128) ((float*)s_p1)[i] = 0.f;
    for (int i = tid; i < 576; i += 128) s_w1[i] = w1[i];
    if (tid < 16) s_b1[tid] = b1[tid];
    for (int i = tid; i < 4608; i += 128) s_w2[i] = w2[i];
    if (tid < 32) s_b2[tid] = b2[tid];
    __syncthreads();

    int f0 = blockIdx.x * FPB;
    for (int i = tid; i < FPB * 400; i += 128) {
        int f = i / 400, rem = i % 400;
        int ic = rem / 100, p = rem % 100, y = p / 10, x = p % 10;
        s_in[f][ic][y + 1][x + 1] = obs[(long)f0 * 400 + i];
    }
    __syncthreads();

    // phase 1: conv1 (3x3 SAME, 4->16) + relu + maxpool2 -> s_p1 interior
    if (tid < FPB * 25) {
        int f = tid / 25, pp = tid % 25, py = pp / 5, px = pp % 5;
        float patch[4][4][4];
#pragma unroll
        for (int ic = 0; ic < 4; ic++)
#pragma unroll
            for (int r = 0; r < 4; r++)
#pragma unroll
                for (int cc = 0; cc < 4; cc++)
                    patch[ic][r][cc] = s_in[f][ic][2 * py + r][2 * px + cc];
        for (int oc = 0; oc < 16; oc++) {
            float a0 = s_b1[oc], a1 = a0, a2 = a0, a3 = a0;
#pragma unroll
            for (int ic = 0; ic < 4; ic++)
#pragma unroll
                for (int ky = 0; ky < 3; ky++)
#pragma unroll
                    for (int kx = 0; kx < 3; kx++) {
                        float w = s_w1[(oc * 4 + ic) * 9 + ky * 3 + kx];
                        a0 += patch[ic][ky][kx] * w;
                        a1 += patch[ic][ky][kx + 1] * w;
                        a2 += patch[ic][ky + 1][kx] * w;
                        a3 += patch[ic][ky + 1][kx + 1] * w;
                    }
            float m = fmaxf(fmaxf(fmaxf(a0, a1), fmaxf(a2, a3)), 0.f);
            s_p1[f][oc][py + 1][px + 1] = m;
        }
    }
    __syncthreads();

    // phase 2: conv2 (3x3 SAME, 16->32) + relu + maxpool2 (floor: only 4x4 region)
    if (tid < FPB * 16) {
        int f = tid >> 4, ocg = (tid >> 2) & 3, pq = tid & 3;
        int py2 = pq >> 1, px2 = pq & 1;
        float acc[8][4];
#pragma unroll
        for (int a = 0; a < 8; a++) {
            float bb = s_b2[ocg * 8 + a];
#pragma unroll
            for (int p = 0; p < 4; p++) acc[a][p] = bb;
        }
        for (int ic = 0; ic < 16; ic++)
#pragma unroll
            for (int ky = 0; ky < 3; ky++)
#pragma unroll
                for (int kx = 0; kx < 3; kx++) {
                    float iv[4];
#pragma unroll
                    for (int p = 0; p < 4; p++) {
                        int dy2 = p >> 1, dx2 = p & 1;
                        iv[p] = s_p1[f][ic][2 * py2 + dy2 + ky][2 * px2 + dx2 + kx];
                    }
#pragma unroll
                    for (int a = 0; a < 8; a++) {
                        float w = s_w2[((ocg * 8 + a) * 16 + ic) * 9 + ky * 3 + kx];
#pragma unroll
                        for (int p = 0; p < 4; p++) acc[a][p] += iv[p] * w;
                    }
                }
#pragma unroll
        for (int a = 0; a < 8; a++) {
            float m = fmaxf(fmaxf(fmaxf(acc[a][0], acc[a][1]), fmaxf(acc[a][2], acc[a][3])), 0.f);
            g_cnn[(long)(f0 + f) * 128 + (ocg * 8 + a) * 4 + pq] = m;
        }
    }
}

// ---------------- FC stack: fc1+bn1+relu -> fc2+bn2+relu ----------------
// 64 rows per block, 256 threads. Weights staged in PADDED smem (conflict-free
// lane-strided reads). dynamic smem.
__global__ void fc_kernel(const float* __restrict__ fc1w, const float* __restrict__ fc1b,
                          const float* __restrict__ g1, const float* __restrict__ be1,
                          const float* __restrict__ m1, const float* __restrict__ v1,
                          const float* __restrict__ fc2w, const float* __restrict__ fc2b,
                          const float* __restrict__ g2, const float* __restrict__ be2,
                          const float* __restrict__ m2, const float* __restrict__ v2)
{
    extern __shared__ float sm[];
    float* w1s = sm;                    // 128*129
    float* w2s = w1s + 128 * 129;       // 64*129
    float* xs  = w2s + 64 * 129;        // 64*128
    float* ms  = xs + 64 * 128;         // 64*128

    int tid = threadIdx.x;
    long r0 = (long)blockIdx.x * 64;
    for (int i = tid; i < 128 * 128; i += 256) {
        int j = i >> 7, k = i & 127;
        w1s[j * 129 + k] = fc1w[i];
    }
    for (int i = tid; i < 64 * 128; i += 256) {
        int j = i >> 7, k = i & 127;
        w2s[j * 129 + k] = fc2w[i];
    }
    for (int i = tid; i < 64 * 128; i += 256) xs[i] = g_cnn[r0 * 128 + i];
    __syncthreads();

    int tj = tid & 31, tr = tid >> 5;
    {
        float acc[4][8];
#pragma unroll
        for (int a = 0; a < 4; a++)
#pragma unroll
            for (int b = 0; b < 8; b++) acc[a][b] = 0.f;
        for (int k = 0; k < 128; k++) {
            float hv[8];
#pragma unroll
            for (int b = 0; b < 8; b++) hv[b] = xs[(tr * 8 + b) * 128 + k];
#pragma unroll
            for (int a = 0; a < 4; a++) {
                float wv = w1s[(tj + 32 * a) * 129 + k];
#pragma unroll
                for (int b = 0; b < 8; b++) acc[a][b] += wv * hv[b];
            }
        }
#pragma unroll
        for (int a = 0; a < 4; a++) {
            int j = tj + 32 * a;
            float s = g1[j] * rsqrtf(v1[j] + 1e-5f);
            float bb = (fc1b[j] - m1[j]) * s + be1[j];
#pragma unroll
            for (int b = 0; b < 8; b++)
                ms[(tr * 8 + b) * 128 + j] = fmaxf(acc[a][b] * s + bb, 0.f);
        }
    }
    __syncthreads();
    {
        float acc[2][8];
#pragma unroll
        for (int a = 0; a < 2; a++)
#pragma unroll
            for (int b = 0; b < 8; b++) acc[a][b] = 0.f;
        for (int k = 0; k < 128; k++) {
            float hv[8];
#pragma unroll
            for (int b = 0; b < 8; b++) hv[b] = ms[(tr * 8 + b) * 128 + k];
#pragma unroll
            for (int a = 0; a < 2; a++) {
                float wv = w2s[(tj + 32 * a) * 129 + k];
#pragma unroll
                for (int b = 0; b < 8; b++) acc[a][b] += wv * hv[b];
            }
        }
#pragma unroll
        for (int a = 0; a < 2; a++) {
            int j = tj + 32 * a;
            float s = g2[j] * rsqrtf(v2[j] + 1e-5f);
            float bb = (fc2b[j] - m2[j]) * s + be2[j];
#pragma unroll
            for (int b = 0; b < 8; b++)
                g_feats[(r0 + tr * 8 + b) * 64 + j] = fmaxf(acc[a][b] * s + bb, 0.f);
        }
    }
}

// ---------------- encoder x-projection GEMM ----------------
// xg[m, j] = feats[m, :64] . wih[j, :64] + eb[j];  M=32768, N=512, K=64.
// 128x128 tile per block, 256 threads, 8x8 register tile, k-major smem.
// PAD = 132 (multiple of 4) so float4 smem loads are 16B-aligned.
#define XPAD 132
__global__ void xproj_kernel(const float* __restrict__ wih, const float* __restrict__ eb)
{
    extern __shared__ float sm[];
    float* As = sm;                // [64][XPAD]  (k, m)
    float* Bs = sm + 64 * XPAD;    // [64][XPAD]  (k, j)

    int tid = threadIdx.x;
    long r0 = (long)blockIdx.x * 128;
    int j0 = blockIdx.y * 128;

    for (int i = tid; i < 128 * 64; i += 256) {
        int m = i >> 6, k = i & 63;
        As[k * XPAD + m] = g_feats[(r0 + m) * 64 + k];
    }
    for (int i = tid; i < 128 * 64; i += 256) {
        int j = i >> 6, k = i & 63;
        Bs[k * XPAD + j] = wih[(j0 + j) * 64 + k];
    }
    __syncthreads();

    int tx = tid & 15, ty = tid >> 4;
    int m0 = ty * 8, n0 = tx * 8;
    float acc[8][8];
#pragma unroll
    for (int i = 0; i < 8; i++)
#pragma unroll
        for (int j = 0; j < 8; j++) acc[i][j] = 0.f;

    for (int k = 0; k < 64; k++) {
        float a[8], b[8];
        float4 a0 = *(const float4*)&As[k * XPAD + m0];
        float4 a1 = *(const float4*)&As[k * XPAD + m0 + 4];
        float4 b0 = *(const float4*)&Bs[k * XPAD + n0];
        float4 b1 = *(const float4*)&Bs[k * XPAD + n0 + 4];
        a[0]=a0.x; a[1]=a0.y; a[2]=a0.z; a[3]=a0.w; a[4]=a1.x; a[5]=a1.y; a[6]=a1.z; a[7]=a1.w;
        b[0]=b0.x; b[1]=b0.y; b[2]=b0.z; b[3]=b0.w; b[4]=b1.x; b[5]=b1.y; b[6]=b1.z; b[7]=b1.w;
#pragma unroll
        for (int i = 0; i < 8; i++)
#pragma unroll
            for (int j = 0; j < 8; j++) acc[i][j] += a[i] * b[j];
    }

#pragma unroll
    for (int i = 0; i < 8; i++) {
        long row = (r0 + m0 + i) * 512 + j0 + n0;
#pragma unroll
        for (int j = 0; j < 8; j++)
            g_xg[row + j] = acc[i][j] + eb[j0 + n0 + j];
    }
}

// ---------------- prep: W_dec = dec_w_ih + dec_w_hh; zero h0, c0 ----------------
__global__ void prep_kernel(const float* __restrict__ dwi, const float* __restrict__ dwh)
{
    int i = blockIdx.x * 256 + threadIdx.x;
    if (i < 512 * 128) g_wdec[i] = dwi[i] + dwh[i];
    if (i < 1024 * 128) { g_hbuf[0][i] = 0.f; g_c[i] = 0.f; }
}

// ---------------- one LSTM step (encoder or decoder) ----------------
__global__ void lstm_step_kernel(int hin_sel, int hout_sel,
                                 const float* __restrict__ w_enc,
                                 const float* __restrict__ bias,
                                 int t, int is_dec, int s)
{
    extern __shared__ float sm[];
    float* ws = sm;                  // 128*129
    float* hs = sm + 128 * 129;      // 32*128
    const float* w = is_dec ? g_wdec : w_enc;
    const float* h_in = g_hbuf[hin_sel];
    float* h_out = g_hbuf[hout_sel];

    int tid = threadIdx.x;
    int b0 = blockIdx.x * 32;
    int u0 = blockIdx.y * 32;

    for (int idx = tid; idx < 128 * 128; idx += 256) {
        int jl = idx >> 7, k = idx & 127;
        int gate = jl >> 5, ul = jl & 31;
        ws[jl * 129 + k] = w[(gate * 128 + u0 + ul) * 128 + k];
    }
    for (int idx = tid; idx < 32 * 128; idx += 256)
        hs[idx] = h_in[b0 * 128 + idx];
    __syncthreads();

    int tj = tid & 31;
    int tr = tid >> 5;
    float acc[4][4];
#pragma unroll
    for (int a = 0; a < 4; a++)
#pragma unroll
        for (int b = 0; b < 4; b++) acc[a][b] = 0.f;

#pragma unroll 4
    for (int k = 0; k < 128; k++) {
        float wv[4], hv[4];
#pragma unroll
        for (int a = 0; a < 4; a++) wv[a] = ws[(a * 32 + tj) * 129 + k];
#pragma unroll
        for (int b = 0; b < 4; b++) hv[b] = hs[(tr + 8 * b) * 128 + k];
#pragma unroll
        for (int a = 0; a < 4; a++)
#pragma unroll
            for (int b = 0; b < 4; b++) acc[a][b] += wv[a] * hv[b];
    }

    int u = u0 + tj;
#pragma unroll
    for (int b = 0; b < 4; b++) {
        int brow = b0 + tr + 8 * b;
        float gi = acc[0][b], gf = acc[1][b], gg = acc[2][b], go = acc[3][b];
        if (!is_dec) {
            const float* xr = g_xg + ((long)brow * 32 + t) * 512;
            gi += xr[0 * 128 + u];
            gf += xr[1 * 128 + u];
            gg += xr[2 * 128 + u];
            go += xr[3 * 128 + u];
        } else {
            gi += bias[0 * 128 + u];
            gf += bias[1 * 128 + u];
            gg += bias[2 * 128 + u];
            go += bias[3 * 128 + u];
        }
        float si = 1.f / (1.f + __expf(-gi));
        float sf = 1.f / (1.f + __expf(-gf));
        float so = 1.f / (1.f + __expf(-go));
        float tg = tanhf(gg);
        int ci = brow * 128 + u;
        float cn = sf * g_c[ci] + si * tg;
        g_c[ci] = cn;
        float hn = so * tanhf(cn);
        h_out[ci] = hn;
        if (is_dec) g_hdec[s][ci] = hn;
    }
}

// ---------------- output head ----------------
__global__ void head_kernel(const float* __restrict__ ow, const float* __restrict__ ob,
                            float* __restrict__ out)
{
    __shared__ float hsm[64 * 129];
    __shared__ float wsm[12 * 129];
    __shared__ float bsm[12];
    int tid = threadIdx.x;
    int s = blockIdx.y, b0 = blockIdx.x * 64;
    for (int i = tid; i < 64 * 128; i += 256) {
        int r = i >> 7, k = i & 127;
        hsm[r * 129 + k] = g_hdec[s][(b0 + r) * 128 + k];
    }
    for (int i = tid; i < 12 * 128; i += 256) {
        int r = i / 128, k = i % 128;
        wsm[r * 129 + k] = ow[i];
    }
    if (tid < 12) bsm[tid] = ob[tid];
    __syncthreads();
    for (int it = tid; it < 64 * 12; it += 256) {
        int b = it / 12, v = it % 12;
        float acc = bsm[v];
        for (int k = 0; k < 128; k++) acc += hsm[b * 129 + k] * wsm[v * 129 + k];
        out[(long)(b0 + b) * 120 + s * 12 + v] = acc;
    }
}

// ---------------- launcher ----------------
extern "C" void kernel_launch(void* const* d_in, const int* in_sizes, int n_in,
                              void* d_out, int out_size)
{
    const float* obs    = (const float*)d_in[0];
    const float* c1w    = (const float*)d_in[1];
    const float* c1b    = (const float*)d_in[2];
    const float* c2w    = (const float*)d_in[3];
    const float* c2b    = (const float*)d_in[4];
    const float* fc1w   = (const float*)d_in[5];
    const float* fc1b   = (const float*)d_in[6];
    const float* bn1g   = (const float*)d_in[7];
    const float* bn1b   = (const float*)d_in[8];
    const float* bn1m   = (const float*)d_in[9];
    const float* bn1v   = (const float*)d_in[10];
    const float* fc2w   = (const float*)d_in[11];
    const float* fc2b   = (const float*)d_in[12];
    const float* bn2g   = (const float*)d_in[13];
    const float* bn2b   = (const float*)d_in[14];
    const float* bn2m   = (const float*)d_in[15];
    const float* bn2v   = (const float*)d_in[16];
    const float* encwih = (const float*)d_in[17];
    const float* encwhh = (const float*)d_in[18];
    const float* encb   = (const float*)d_in[19];
    const float* decwih = (const float*)d_in[20];
    const float* decwhh = (const float*)d_in[21];
    const float* decb   = (const float*)d_in[22];
    const float* outw   = (const float*)d_in[23];
    const float* outb   = (const float*)d_in[24];
    float* out = (float*)d_out;

    const int lstm_smem  = (128 * 129 + 32 * 128) * 4;                // 82432 B
    const int fc_smem    = (128 * 129 + 64 * 129 + 64 * 128 * 2) * 4; // 164608 B
    const int xproj_smem = (64 * XPAD * 2) * 4;                       // 67584 B
    cudaFuncSetAttribute(lstm_step_kernel, cudaFuncAttributeMaxDynamicSharedMemorySize, lstm_smem);
    cudaFuncSetAttribute(fc_kernel, cudaFuncAttributeMaxDynamicSharedMemorySize, fc_smem);
    cudaFuncSetAttribute(xproj_kernel, cudaFuncAttributeMaxDynamicSharedMemorySize, xproj_smem);

    prep_kernel<<<512, 256>>>(decwih, decwhh);
    cnn_kernel<<<32768 / FPB, 128>>>(obs, c1w, c1b, c2w, c2b);
    fc_kernel<<<512, 256, fc_smem>>>(fc1w, fc1b, bn1g, bn1b, bn1m, bn1v,
                                     fc2w, fc2b, bn2g, bn2b, bn2m, bn2v);
    dim3 xgrid(256, 4);
    xproj_kernel<<<xgrid, 256, xproj_smem>>>(encwih, encb);

    dim3 lgrid(32, 4);
    for (int t = 0; t < 32; t++)
        lstm_step_kernel<<<lgrid, 256, lstm_smem>>>(t & 1, (t + 1) & 1, encwhh, nullptr, t, 0, 0);
    for (int s = 0; s < 10; s++)
        lstm_step_kernel<<<lgrid, 256, lstm_smem>>>(s & 1, (s + 1) & 1, nullptr, decb, 0, 1, s);

    dim3 hgrid(16, 10);
    head_kernel<<<hgrid, 256>>>(outw, outb, out);
}

// round 4
// speedup vs baseline: 2.5261x; 1.3097x over previous
#include <cuda_runtime.h>
#include <math.h>

// ---------------- scratch (static device globals; no allocation) ----------------
__device__ float g_cnn[32768 * 128];     // CNN output per frame
__device__ float g_feats[32768 * 64];    // after FC+BN stack
__device__ float g_xg[32768 * 512];      // precomputed x @ enc_w_ih^T + enc_b
__device__ float g_hbuf[2][1024 * 128];  // h ping-pong
__device__ float g_hdec[10][1024 * 128]; // decoder h history for output head

// grid barrier state
__device__ unsigned g_cnt = 0;
__device__ volatile unsigned g_gen = 0;

#define NBLK 128

__device__ __forceinline__ void fma2(unsigned long long& d,
                                     unsigned long long a, unsigned long long b) {
    asm("fma.rn.f32x2 %0, %1, %2, %0;" : "+l"(d) : "l"(a), "l"(b));
}
__device__ __forceinline__ float f2sum(unsigned long long v) {
    float lo = __uint_as_float((unsigned)(v & 0xffffffffull));
    float hi = __uint_as_float((unsigned)(v >> 32));
    return lo + hi;
}

// ---------------- CNN: conv1+relu+pool, conv2+relu+pool (unchanged) ----------------
#define FPB 4
__global__ void cnn_kernel(const float* __restrict__ obs,
                           const float* __restrict__ w1, const float* __restrict__ b1,
                           const float* __restrict__ w2, const float* __restrict__ b2)
{
    __shared__ float s_in[FPB][4][12][12];
    __shared__ float s_p1[FPB][16][7][7];
    __shared__ float s_w1[576];
    __shared__ float s_b1[16];
    __shared__ float s_w2[4608];
    __shared__ float s_b2[32];

    int tid = threadIdx.x; // 128
    for (int i = tid; i < FPB * 4 * 144; i += 128) ((float*)s_in)[i] = 0.f;
    for (int i = tid; i < FPB * 16 * 49; i += 128) ((float*)s_p1)[i] = 0.f;
    for (int i = tid; i < 576; i += 128) s_w1[i] = w1[i];
    if (tid < 16) s_b1[tid] = b1[tid];
    for (int i = tid; i < 4608; i += 128) s_w2[i] = w2[i];
    if (tid < 32) s_b2[tid] = b2[tid];
    __syncthreads();

    int f0 = blockIdx.x * FPB;
    for (int i = tid; i < FPB * 400; i += 128) {
        int f = i / 400, rem = i % 400;
        int ic = rem / 100, p = rem % 100, y = p / 10, x = p % 10;
        s_in[f][ic][y + 1][x + 1] = obs[(long)f0 * 400 + i];
    }
    __syncthreads();

    if (tid < FPB * 25) {
        int f = tid / 25, pp = tid % 25, py = pp / 5, px = pp % 5;
        float patch[4][4][4];
#pragma unroll
        for (int ic = 0; ic < 4; ic++)
#pragma unroll
            for (int r = 0; r < 4; r++)
#pragma unroll
                for (int cc = 0; cc < 4; cc++)
                    patch[ic][r][cc] = s_in[f][ic][2 * py + r][2 * px + cc];
        for (int oc = 0; oc < 16; oc++) {
            float a0 = s_b1[oc], a1 = a0, a2 = a0, a3 = a0;
#pragma unroll
            for (int ic = 0; ic < 4; ic++)
#pragma unroll
                for (int ky = 0; ky < 3; ky++)
#pragma unroll
                    for (int kx = 0; kx < 3; kx++) {
                        float w = s_w1[(oc * 4 + ic) * 9 + ky * 3 + kx];
                        a0 += patch[ic][ky][kx] * w;
                        a1 += patch[ic][ky][kx + 1] * w;
                        a2 += patch[ic][ky + 1][kx] * w;
                        a3 += patch[ic][ky + 1][kx + 1] * w;
                    }
            float m = fmaxf(fmaxf(fmaxf(a0, a1), fmaxf(a2, a3)), 0.f);
            s_p1[f][oc][py + 1][px + 1] = m;
        }
    }
    __syncthreads();

    if (tid < FPB * 16) {
        int f = tid >> 4, ocg = (tid >> 2) & 3, pq = tid & 3;
        int py2 = pq >> 1, px2 = pq & 1;
        float acc[8][4];
#pragma unroll
        for (int a = 0; a < 8; a++) {
            float bb = s_b2[ocg * 8 + a];
#pragma unroll
            for (int p = 0; p < 4; p++) acc[a][p] = bb;
        }
        for (int ic = 0; ic < 16; ic++)
#pragma unroll
            for (int ky = 0; ky < 3; ky++)
#pragma unroll
                for (int kx = 0; kx < 3; kx++) {
                    float iv[4];
#pragma unroll
                    for (int p = 0; p < 4; p++) {
                        int dy2 = p >> 1, dx2 = p & 1;
                        iv[p] = s_p1[f][ic][2 * py2 + dy2 + ky][2 * px2 + dx2 + kx];
                    }
#pragma unroll
                    for (int a = 0; a < 8; a++) {
                        float w = s_w2[((ocg * 8 + a) * 16 + ic) * 9 + ky * 3 + kx];
#pragma unroll
                        for (int p = 0; p < 4; p++) acc[a][p] += iv[p] * w;
                    }
                }
#pragma unroll
        for (int a = 0; a < 8; a++) {
            float m = fmaxf(fmaxf(fmaxf(acc[a][0], acc[a][1]), fmaxf(acc[a][2], acc[a][3])), 0.f);
            g_cnn[(long)(f0 + f) * 128 + (ocg * 8 + a) * 4 + pq] = m;
        }
    }
}

// ---------------- FC stack: fc1+bn1+relu -> fc2+bn2+relu (f32x2 + swizzle) ----------------
// 64 rows per block, 256 threads. Weight rows XOR-swizzled in 16B chunks.
__global__ void __launch_bounds__(256) fc_kernel(
    const float* __restrict__ fc1w, const float* __restrict__ fc1b,
    const float* __restrict__ g1, const float* __restrict__ be1,
    const float* __restrict__ m1, const float* __restrict__ v1,
    const float* __restrict__ fc2w, const float* __restrict__ fc2b,
    const float* __restrict__ g2, const float* __restrict__ be2,
    const float* __restrict__ m2, const float* __restrict__ v2)
{
    extern __shared__ float sm[];
    float* w1s = sm;                  // 128 rows x 128 (swizzled)
    float* w2s = w1s + 128 * 128;     // 64 rows x 128 (swizzled)
    float* xs  = w2s + 64 * 128;      // 64 x 128 plain
    float* ms  = xs + 64 * 128;       // 64 x 128 plain

    int tid = threadIdx.x;
    long r0 = (long)blockIdx.x * 64;
    for (int i = tid; i < 128 * 128; i += 256) {
        int row = i >> 7, k = i & 127;
        w1s[row * 128 + ((((k >> 2) ^ (row & 7)) << 2) | (k & 3))] = fc1w[i];
    }
    for (int i = tid; i < 64 * 128; i += 256) {
        int row = i >> 7, k = i & 127;
        w2s[row * 128 + ((((k >> 2) ^ (row & 7)) << 2) | (k & 3))] = fc2w[i];
    }
    for (int i = tid; i < 64 * 128; i += 256) xs[i] = g_cnn[r0 * 128 + i];
    __syncthreads();

    int tj = tid & 31, tr = tid >> 5;
    int key = tj & 7;
    {
        unsigned long long acc2[4][8];
#pragma unroll
        for (int a = 0; a < 4; a++)
#pragma unroll
            for (int b = 0; b < 8; b++) acc2[a][b] = 0ull;
        for (int kk = 0; kk < 32; kk++) {
            int pk = (kk ^ key) << 2;
            ulonglong2 w2v[4], h2v[8];
#pragma unroll
            for (int a = 0; a < 4; a++)
                w2v[a] = *reinterpret_cast<const ulonglong2*>(&w1s[(tj + 32 * a) * 128 + pk]);
#pragma unroll
            for (int b = 0; b < 8; b++)
                h2v[b] = *reinterpret_cast<const ulonglong2*>(&xs[(tr * 8 + b) * 128 + (kk << 2)]);
#pragma unroll
            for (int a = 0; a < 4; a++)
#pragma unroll
                for (int b = 0; b < 8; b++) {
                    fma2(acc2[a][b], w2v[a].x, h2v[b].x);
                    fma2(acc2[a][b], w2v[a].y, h2v[b].y);
                }
        }
#pragma unroll
        for (int a = 0; a < 4; a++) {
            int j = tj + 32 * a;
            float s = g1[j] * rsqrtf(v1[j] + 1e-5f);
            float bb = (fc1b[j] - m1[j]) * s + be1[j];
#pragma unroll
            for (int b = 0; b < 8; b++)
                ms[(tr * 8 + b) * 128 + j] = fmaxf(f2sum(acc2[a][b]) * s + bb, 0.f);
        }
    }
    __syncthreads();
    {
        unsigned long long acc2[2][8];
#pragma unroll
        for (int a = 0; a < 2; a++)
#pragma unroll
            for (int b = 0; b < 8; b++) acc2[a][b] = 0ull;
        for (int kk = 0; kk < 32; kk++) {
            int pk = (kk ^ key) << 2;
            ulonglong2 w2v[2], h2v[8];
#pragma unroll
            for (int a = 0; a < 2; a++)
                w2v[a] = *reinterpret_cast<const ulonglong2*>(&w2s[(tj + 32 * a) * 128 + pk]);
#pragma unroll
            for (int b = 0; b < 8; b++)
                h2v[b] = *reinterpret_cast<const ulonglong2*>(&ms[(tr * 8 + b) * 128 + (kk << 2)]);
#pragma unroll
            for (int a = 0; a < 2; a++)
#pragma unroll
                for (int b = 0; b < 8; b++) {
                    fma2(acc2[a][b], w2v[a].x, h2v[b].x);
                    fma2(acc2[a][b], w2v[a].y, h2v[b].y);
                }
        }
#pragma unroll
        for (int a = 0; a < 2; a++) {
            int j = tj + 32 * a;
            float s = g2[j] * rsqrtf(v2[j] + 1e-5f);
            float bb = (fc2b[j] - m2[j]) * s + be2[j];
#pragma unroll
            for (int b = 0; b < 8; b++)
                g_feats[(r0 + tr * 8 + b) * 64 + j] = fmaxf(f2sum(acc2[a][b]) * s + bb, 0.f);
        }
    }
}

// ---------------- encoder x-projection GEMM (f32x2 + swizzle) ----------------
// xg[m, j] = feats[m, :64] . wih[j, :64] + eb[j];  M=32768, N=512, K=64.
// 128x128 tile, 512 threads, per-thread 4m x 8n.
__global__ void __launch_bounds__(512) xproj_kernel(const float* __restrict__ wih,
                                                    const float* __restrict__ eb)
{
    extern __shared__ float sm[];
    float* As = sm;              // [128][64] plain (m-major, k contiguous)
    float* Bs = sm + 128 * 64;   // [128][64] swizzled (j-major, k contiguous)

    int tid = threadIdx.x;
    long r0 = (long)blockIdx.x * 128;
    int j0 = blockIdx.y * 128;

    for (int i = tid; i < 128 * 64; i += 512) As[i] = g_feats[r0 * 64 + i];
    for (int i = tid; i < 128 * 64; i += 512) {
        int j = i >> 6, k = i & 63;
        Bs[j * 64 + ((((k >> 2) ^ ((j >> 3) & 7)) << 2) | (k & 3))] = wih[(long)(j0 + j) * 64 + k];
    }
    __syncthreads();

    int tx = tid & 15, ty = tid >> 4; // ty 0..31
    int m0 = ty * 4, n0 = tx * 8;
    int key = tx & 7;

    unsigned long long acc2[4][8];
#pragma unroll
    for (int i = 0; i < 4; i++)
#pragma unroll
        for (int j = 0; j < 8; j++) acc2[i][j] = 0ull;

    for (int kk = 0; kk < 16; kk++) {
        int pk = (kk ^ key) << 2;
        ulonglong2 a2[4], b2[8];
#pragma unroll
        for (int i = 0; i < 4; i++)
            a2[i] = *reinterpret_cast<const ulonglong2*>(&As[(m0 + i) * 64 + (kk << 2)]);
#pragma unroll
        for (int j = 0; j < 8; j++)
            b2[j] = *reinterpret_cast<const ulonglong2*>(&Bs[(n0 + j) * 64 + pk]);
#pragma unroll
        for (int i = 0; i < 4; i++)
#pragma unroll
            for (int j = 0; j < 8; j++) {
                fma2(acc2[i][j], a2[i].x, b2[j].x);
                fma2(acc2[i][j], a2[i].y, b2[j].y);
            }
    }

#pragma unroll
    for (int i = 0; i < 4; i++) {
        long row = (r0 + m0 + i) * 512 + j0 + n0;
        float o[8];
#pragma unroll
        for (int j = 0; j < 8; j++) o[j] = f2sum(acc2[i][j]) + eb[j0 + n0 + j];
        *(float4*)&g_xg[row]     = make_float4(o[0], o[1], o[2], o[3]);
        *(float4*)&g_xg[row + 4] = make_float4(o[4], o[5], o[6], o[7]);
    }
}

// ---------------- persistent LSTM: all 32 encoder + 10 decoder steps ----------------
// 128 blocks (all co-resident), 256 threads. Weights in smem once, c in registers.
__device__ __forceinline__ void grid_barrier() {
    __syncthreads();
    if (threadIdx.x == 0) {
        __threadfence();
        unsigned gen = g_gen;
        if (atomicAdd(&g_cnt, 1) == NBLK - 1) {
            g_cnt = 0;
            __threadfence();
            g_gen = gen + 1;
        } else {
            while (g_gen == gen) __nanosleep(64);
        }
        __threadfence();
    }
    __syncthreads();
}

__global__ void __launch_bounds__(256, 1) lstm_persistent(
    const float* __restrict__ encw, const float* __restrict__ dwi,
    const float* __restrict__ dwh, const float* __restrict__ decb)
{
    extern __shared__ float sm[];
    float* wse = sm;                  // 128 rows x 128 (swizzled) encoder slice
    float* wsd = sm + 128 * 128;      // 128 rows x 128 (swizzled) decoder slice (ih+hh)
    float* hs  = sm + 2 * 128 * 128;  // 32 x 128 plain

    int tid = threadIdx.x;
    int b0 = (blockIdx.x & 31) * 32;
    int u0 = (blockIdx.x >> 5) * 32;

    // stage weights (once): row = gate*32 + ul  <->  global gate*128 + u0 + ul
    for (int i = tid; i < 128 * 128; i += 256) {
        int row = i >> 7, k = i & 127;
        int grow = ((row >> 5) * 128) + u0 + (row & 31);
        int pk = ((((k >> 2) ^ (row & 7)) << 2) | (k & 3));
        wse[row * 128 + pk] = encw[grow * 128 + k];
        wsd[row * 128 + pk] = dwi[grow * 128 + k] + dwh[grow * 128 + k];
    }
    for (int i = tid; i < 32 * 128; i += 256) hs[i] = 0.f;
    __syncthreads();

    int tj = tid & 31, tr = tid >> 5;
    int key = tj & 7;
    int u = u0 + tj;
    float db[4];
#pragma unroll
    for (int a = 0; a < 4; a++) db[a] = decb[a * 128 + u];

    float c[4];
#pragma unroll
    for (int b = 0; b < 4; b++) c[b] = 0.f;

    for (int step = 0; step < 42; step++) {
        const float* ws = (step < 32) ? wse : wsd;
        unsigned long long acc2[4][4];
#pragma unroll
        for (int a = 0; a < 4; a++)
#pragma unroll
            for (int b = 0; b < 4; b++) acc2[a][b] = 0ull;

        for (int kk = 0; kk < 32; kk++) {
            int pk = (kk ^ key) << 2;
            ulonglong2 w2v[4], h2v[4];
#pragma unroll
            for (int a = 0; a < 4; a++)
                w2v[a] = *reinterpret_cast<const ulonglong2*>(&ws[(a * 32 + tj) * 128 + pk]);
#pragma unroll
            for (int b = 0; b < 4; b++)
                h2v[b] = *reinterpret_cast<const ulonglong2*>(&hs[(tr + 8 * b) * 128 + (kk << 2)]);
#pragma unroll
            for (int a = 0; a < 4; a++)
#pragma unroll
                for (int b = 0; b < 4; b++) {
                    fma2(acc2[a][b], w2v[a].x, h2v[b].x);
                    fma2(acc2[a][b], w2v[a].y, h2v[b].y);
                }
        }

        int wsel = step & 1;
        float* h_out = g_hbuf[wsel];
#pragma unroll
        for (int b = 0; b < 4; b++) {
            int brow = b0 + tr + 8 * b;
            float gi = f2sum(acc2[0][b]);
            float gf = f2sum(acc2[1][b]);
            float gg = f2sum(acc2[2][b]);
            float go = f2sum(acc2[3][b]);
            if (step < 32) {
                const float* xr = g_xg + ((long)brow * 32 + step) * 512;
                gi += xr[0 * 128 + u];
                gf += xr[1 * 128 + u];
                gg += xr[2 * 128 + u];
                go += xr[3 * 128 + u];
            } else {
                gi += db[0]; gf += db[1]; gg += db[2]; go += db[3];
            }
            float si = 1.f / (1.f + __expf(-gi));
            float sf = 1.f / (1.f + __expf(-gf));
            float so = 1.f / (1.f + __expf(-go));
            float tg = tanhf(gg);
            float cn = sf * c[b] + si * tg;
            c[b] = cn;
            float hn = so * tanhf(cn);
            int ci = brow * 128 + u;
            h_out[ci] = hn;
            if (step >= 32) g_hdec[step - 32][ci] = hn;
        }

        if (step < 41) {
            grid_barrier();
            // reload hs from the buffer just written
            const float4* src = (const float4*)&g_hbuf[wsel][b0 * 128];
            float4* dst = (float4*)hs;
            for (int i = tid; i < 32 * 128 / 4; i += 256) dst[i] = src[i];
            __syncthreads();
        }
    }
}

// ---------------- output head ----------------
__global__ void head_kernel(const float* __restrict__ ow, const float* __restrict__ ob,
                            float* __restrict__ out)
{
    __shared__ float hsm[64 * 129];
    __shared__ float wsm[12 * 129];
    __shared__ float bsm[12];
    int tid = threadIdx.x;
    int s = blockIdx.y, b0 = blockIdx.x * 64;
    for (int i = tid; i < 64 * 128; i += 256) {
        int r = i >> 7, k = i & 127;
        hsm[r * 129 + k] = g_hdec[s][(b0 + r) * 128 + k];
    }
    for (int i = tid; i < 12 * 128; i += 256) {
        int r = i / 128, k = i % 128;
        wsm[r * 129 + k] = ow[i];
    }
    if (tid < 12) bsm[tid] = ob[tid];
    __syncthreads();
    for (int it = tid; it < 64 * 12; it += 256) {
        int b = it / 12, v = it % 12;
        float acc = bsm[v];
        for (int k = 0; k < 128; k++) acc += hsm[b * 129 + k] * wsm[v * 129 + k];
        out[(long)(b0 + b) * 120 + s * 12 + v] = acc;
    }
}

// ---------------- launcher ----------------
extern "C" void kernel_launch(void* const* d_in, const int* in_sizes, int n_in,
                              void* d_out, int out_size)
{
    const float* obs    = (const float*)d_in[0];
    const float* c1w    = (const float*)d_in[1];
    const float* c1b    = (const float*)d_in[2];
    const float* c2w    = (const float*)d_in[3];
    const float* c2b    = (const float*)d_in[4];
    const float* fc1w   = (const float*)d_in[5];
    const float* fc1b   = (const float*)d_in[6];
    const float* bn1g   = (const float*)d_in[7];
    const float* bn1b   = (const float*)d_in[8];
    const float* bn1m   = (const float*)d_in[9];
    const float* bn1v   = (const float*)d_in[10];
    const float* fc2w   = (const float*)d_in[11];
    const float* fc2b   = (const float*)d_in[12];
    const float* bn2g   = (const float*)d_in[13];
    const float* bn2b   = (const float*)d_in[14];
    const float* bn2m   = (const float*)d_in[15];
    const float* bn2v   = (const float*)d_in[16];
    const float* encwih = (const float*)d_in[17];
    const float* encwhh = (const float*)d_in[18];
    const float* encb   = (const float*)d_in[19];
    const float* decwih = (const float*)d_in[20];
    const float* decwhh = (const float*)d_in[21];
    const float* decb   = (const float*)d_in[22];
    const float* outw   = (const float*)d_in[23];
    const float* outb   = (const float*)d_in[24];
    float* out = (float*)d_out;

    const int fc_smem    = (128 * 128 + 64 * 128 * 3) * 4;       // 163840 B
    const int xproj_smem = (128 * 64 * 2) * 4;                   // 65536 B
    const int lstm_smem  = (2 * 128 * 128 + 32 * 128) * 4;       // 147456 B
    cudaFuncSetAttribute(fc_kernel, cudaFuncAttributeMaxDynamicSharedMemorySize, fc_smem);
    cudaFuncSetAttribute(xproj_kernel, cudaFuncAttributeMaxDynamicSharedMemorySize, xproj_smem);
    cudaFuncSetAttribute(lstm_persistent, cudaFuncAttributeMaxDynamicSharedMemorySize, lstm_smem);

    cnn_kernel<<<32768 / FPB, 128>>>(obs, c1w, c1b, c2w, c2b);
    fc_kernel<<<512, 256, fc_smem>>>(fc1w, fc1b, bn1g, bn1b, bn1m, bn1v,
                                     fc2w, fc2b, bn2g, bn2b, bn2m, bn2v);
    dim3 xgrid(256, 4);
    xproj_kernel<<<xgrid, 512, xproj_smem>>>(encwih, encb);

    lstm_persistent<<<NBLK, 256, lstm_smem>>>(encwhh, decwih, decwhh, decb);

    dim3 hgrid(16, 10);
    head_kernel<<<hgrid, 256>>>(outw, outb, out);
}

// round 5
// speedup vs baseline: 2.7866x; 1.1031x over previous
#include <cuda_runtime.h>
#include <math.h>

// ---------------- scratch (static device globals; no allocation) ----------------
__device__ float g_cnn[32768 * 128];     // CNN output per frame
__device__ float g_feats[32768 * 64];    // after FC+BN stack
__device__ float g_xg[32768 * 512];      // precomputed x @ enc_w_ih^T + enc_b
__device__ float g_hbuf[2][1024 * 128];  // h ping-pong
__device__ float g_hdec[10][1024 * 128]; // decoder h history for output head

// grid barrier state
__device__ unsigned g_cnt = 0;
__device__ volatile unsigned g_gen = 0;

#define NBLK 128
#define WPAD 132   // weight row pad: 132 % 32 == 4 -> consecutive rows hit banks +4 apart

__device__ __forceinline__ void fma2(unsigned long long& d,
                                     unsigned long long a, unsigned long long b) {
    asm("fma.rn.f32x2 %0, %1, %2, %0;" : "+l"(d) : "l"(a), "l"(b));
}
__device__ __forceinline__ float f2sum(unsigned long long v) {
    float lo = __uint_as_float((unsigned)(v & 0xffffffffull));
    float hi = __uint_as_float((unsigned)(v >> 32));
    return lo + hi;
}

// ---------------- CNN: conv1+relu+pool, conv2+relu+pool ----------------
#define FPB 4
__global__ void cnn_kernel(const float* __restrict__ obs,
                           const float* __restrict__ w1, const float* __restrict__ b1,
                           const float* __restrict__ w2, const float* __restrict__ b2)
{
    __shared__ float s_in[FPB][4][12][12];   // 10x10 + 1 pad each side
    __shared__ float s_p1[FPB][16][7][7];    // 5x5 pooled + 1 pad each side
    __shared__ float s_w1[576];
    __shared__ float s_b1[16];
    __shared__ float s_w2t[144 * 33];        // [ic*9+q][oc] padded 33
    __shared__ float s_b2[32];

    int tid = threadIdx.x; // 128
    for (int i = tid; i < FPB * 4 * 144; i += 128) ((float*)s_in)[i] = 0.f;
    for (int i = tid; i < FPB * 16 * 49; i += 128) ((float*)s_p1)[i] = 0.f;
    for (int i = tid; i < 576; i += 128) s_w1[i] = w1[i];
    if (tid < 16) s_b1[tid] = b1[tid];
    // w2 global [oc][ic*9+q]; store transposed padded: s_w2t[r*33 + oc]
    for (int i = tid; i < 4608; i += 128) {
        int oc = i / 144, r = i % 144;
        s_w2t[r * 33 + oc] = w2[i];
    }
    if (tid < 32) s_b2[tid] = b2[tid];
    __syncthreads();

    int f0 = blockIdx.x * FPB;
    for (int i = tid; i < FPB * 400; i += 128) {
        int f = i / 400, rem = i % 400;
        int ic = rem / 100, p = rem % 100, y = p / 10, x = p % 10;
        s_in[f][ic][y + 1][x + 1] = obs[(long)f0 * 400 + i];
    }
    __syncthreads();

    // phase 1: conv1 (3x3 SAME, 4->16) + relu + maxpool2 -> s_p1 interior
    if (tid < FPB * 25) {
        int f = tid / 25, pp = tid % 25, py = pp / 5, px = pp % 5;
        float patch[4][4][4];
#pragma unroll
        for (int ic = 0; ic < 4; ic++)
#pragma unroll
            for (int r = 0; r < 4; r++)
#pragma unroll
                for (int cc = 0; cc < 4; cc++)
                    patch[ic][r][cc] = s_in[f][ic][2 * py + r][2 * px + cc];
        for (int oc = 0; oc < 16; oc++) {
            float a0 = s_b1[oc], a1 = a0, a2 = a0, a3 = a0;
#pragma unroll
            for (int ic = 0; ic < 4; ic++)
#pragma unroll
                for (int ky = 0; ky < 3; ky++)
#pragma unroll
                    for (int kx = 0; kx < 3; kx++) {
                        float w = s_w1[(oc * 4 + ic) * 9 + ky * 3 + kx];
                        a0 += patch[ic][ky][kx] * w;
                        a1 += patch[ic][ky][kx + 1] * w;
                        a2 += patch[ic][ky + 1][kx] * w;
                        a3 += patch[ic][ky + 1][kx + 1] * w;
                    }
            float m = fmaxf(fmaxf(fmaxf(a0, a1), fmaxf(a2, a3)), 0.f);
            s_p1[f][oc][py + 1][px + 1] = m;
        }
    }
    __syncthreads();

    // phase 2: conv2 (3x3 SAME, 16->32) + relu + maxpool2.
    // lane = oc (conflict-free w reads), f = tid>>5 (warp-uniform -> s_p1 broadcast).
    {
        int oc = tid & 31, f = tid >> 5;
        float acc[16];
        float bb = s_b2[oc];
#pragma unroll
        for (int p = 0; p < 16; p++) acc[p] = bb;
        for (int ic = 0; ic < 16; ic++) {
#pragma unroll
            for (int ky = 0; ky < 3; ky++)
#pragma unroll
                for (int kx = 0; kx < 3; kx++) {
                    float w = s_w2t[(ic * 9 + ky * 3 + kx) * 33 + oc];
#pragma unroll
                    for (int y = 0; y < 4; y++)
#pragma unroll
                        for (int x = 0; x < 4; x++)
                            acc[y * 4 + x] += s_p1[f][ic][y + ky][x + kx] * w;
                }
        }
#pragma unroll
        for (int py = 0; py < 2; py++)
#pragma unroll
            for (int px = 0; px < 2; px++) {
                float m = fmaxf(fmaxf(acc[(2 * py) * 4 + 2 * px], acc[(2 * py) * 4 + 2 * px + 1]),
                                fmaxf(acc[(2 * py + 1) * 4 + 2 * px], acc[(2 * py + 1) * 4 + 2 * px + 1]));
                g_cnn[(long)(f0 + f) * 128 + oc * 4 + py * 2 + px] = fmaxf(m, 0.f);
            }
    }
}

// ---------------- FC stack: fc1+bn1+relu -> fc2+bn2+relu (f32x2, pad-132) ----------------
__global__ void __launch_bounds__(256) fc_kernel(
    const float* __restrict__ fc1w, const float* __restrict__ fc1b,
    const float* __restrict__ g1, const float* __restrict__ be1,
    const float* __restrict__ m1, const float* __restrict__ v1,
    const float* __restrict__ fc2w, const float* __restrict__ fc2b,
    const float* __restrict__ g2, const float* __restrict__ be2,
    const float* __restrict__ m2, const float* __restrict__ v2)
{
    extern __shared__ float sm[];
    float* w1s = sm;                   // 128 rows x WPAD
    float* w2s = w1s + 128 * WPAD;     // 64 rows x WPAD
    float* xs  = w2s + 64 * WPAD;      // 64 x 128 plain
    float* ms  = xs + 64 * 128;        // 64 x 128 plain

    int tid = threadIdx.x;
    long r0 = (long)blockIdx.x * 64;
    for (int i = tid; i < 128 * 128; i += 256) {
        int row = i >> 7, k = i & 127;
        w1s[row * WPAD + k] = fc1w[i];
    }
    for (int i = tid; i < 64 * 128; i += 256) {
        int row = i >> 7, k = i & 127;
        w2s[row * WPAD + k] = fc2w[i];
    }
    for (int i = tid; i < 64 * 128; i += 256) xs[i] = g_cnn[r0 * 128 + i];
    __syncthreads();

    int tj = tid & 31, tr = tid >> 5;
    {
        unsigned long long acc2[4][8];
#pragma unroll
        for (int a = 0; a < 4; a++)
#pragma unroll
            for (int b = 0; b < 8; b++) acc2[a][b] = 0ull;
        for (int kk = 0; kk < 32; kk++) {
            ulonglong2 w2v[4], h2v[8];
#pragma unroll
            for (int a = 0; a < 4; a++)
                w2v[a] = *reinterpret_cast<const ulonglong2*>(&w1s[(tj + 32 * a) * WPAD + (kk << 2)]);
#pragma unroll
            for (int b = 0; b < 8; b++)
                h2v[b] = *reinterpret_cast<const ulonglong2*>(&xs[(tr * 8 + b) * 128 + (kk << 2)]);
#pragma unroll
            for (int a = 0; a < 4; a++)
#pragma unroll
                for (int b = 0; b < 8; b++) {
                    fma2(acc2[a][b], w2v[a].x, h2v[b].x);
                    fma2(acc2[a][b], w2v[a].y, h2v[b].y);
                }
        }
#pragma unroll
        for (int a = 0; a < 4; a++) {
            int j = tj + 32 * a;
            float s = g1[j] * rsqrtf(v1[j] + 1e-5f);
            float bb = (fc1b[j] - m1[j]) * s + be1[j];
#pragma unroll
            for (int b = 0; b < 8; b++)
                ms[(tr * 8 + b) * 128 + j] = fmaxf(f2sum(acc2[a][b]) * s + bb, 0.f);
        }
    }
    __syncthreads();
    {
        unsigned long long acc2[2][8];
#pragma unroll
        for (int a = 0; a < 2; a++)
#pragma unroll
            for (int b = 0; b < 8; b++) acc2[a][b] = 0ull;
        for (int kk = 0; kk < 32; kk++) {
            ulonglong2 w2v[2], h2v[8];
#pragma unroll
            for (int a = 0; a < 2; a++)
                w2v[a] = *reinterpret_cast<const ulonglong2*>(&w2s[(tj + 32 * a) * WPAD + (kk << 2)]);
#pragma unroll
            for (int b = 0; b < 8; b++)
                h2v[b] = *reinterpret_cast<const ulonglong2*>(&ms[(tr * 8 + b) * 128 + (kk << 2)]);
#pragma unroll
            for (int a = 0; a < 2; a++)
#pragma unroll
                for (int b = 0; b < 8; b++) {
                    fma2(acc2[a][b], w2v[a].x, h2v[b].x);
                    fma2(acc2[a][b], w2v[a].y, h2v[b].y);
                }
        }
#pragma unroll
        for (int a = 0; a < 2; a++) {
            int j = tj + 32 * a;
            float s = g2[j] * rsqrtf(v2[j] + 1e-5f);
            float bb = (fc2b[j] - m2[j]) * s + be2[j];
#pragma unroll
            for (int b = 0; b < 8; b++)
                g_feats[(r0 + tr * 8 + b) * 64 + j] = fmaxf(f2sum(acc2[a][b]) * s + bb, 0.f);
        }
    }
}

// ---------------- encoder x-projection GEMM (f32x2, pad-68 B, strided n-cols) ----------------
// xg[m, j] = feats[m, :64] . wih[j, :64] + eb[j];  M=32768, N=512, K=64.
#define BPAD 68   // 68 % 32 == 4
__global__ void __launch_bounds__(512) xproj_kernel(const float* __restrict__ wih,
                                                    const float* __restrict__ eb)
{
    extern __shared__ float sm[];
    float* As = sm;               // [128][64] plain (m-major)
    float* Bs = sm + 128 * 64;    // [128][BPAD] (j-major, padded)

    int tid = threadIdx.x;
    long r0 = (long)blockIdx.x * 128;
    int j0 = blockIdx.y * 128;

    for (int i = tid; i < 128 * 64; i += 512) As[i] = g_feats[r0 * 64 + i];
    for (int i = tid; i < 128 * 64; i += 512) {
        int j = i >> 6, k = i & 63;
        Bs[j * BPAD + k] = wih[(long)(j0 + j) * 64 + k];
    }
    __syncthreads();

    int tx = tid & 15, ty = tid >> 4; // ty 0..31
    int m0 = ty * 4;
    // thread's n-columns: tx + 16*jj (consecutive lanes -> consecutive rows -> conflict-free)

    unsigned long long acc2[4][8];
#pragma unroll
    for (int i = 0; i < 4; i++)
#pragma unroll
        for (int j = 0; j < 8; j++) acc2[i][j] = 0ull;

    for (int kk = 0; kk < 16; kk++) {
        ulonglong2 a2[4], b2[8];
#pragma unroll
        for (int i = 0; i < 4; i++)
            a2[i] = *reinterpret_cast<const ulonglong2*>(&As[(m0 + i) * 64 + (kk << 2)]);
#pragma unroll
        for (int j = 0; j < 8; j++)
            b2[j] = *reinterpret_cast<const ulonglong2*>(&Bs[(tx + 16 * j) * BPAD + (kk << 2)]);
#pragma unroll
        for (int i = 0; i < 4; i++)
#pragma unroll
            for (int j = 0; j < 8; j++) {
                fma2(acc2[i][j], a2[i].x, b2[j].x);
                fma2(acc2[i][j], a2[i].y, b2[j].y);
            }
    }

#pragma unroll
    for (int i = 0; i < 4; i++) {
        long row = (r0 + m0 + i) * 512 + j0;
#pragma unroll
        for (int j = 0; j < 8; j++) {
            int col = tx + 16 * j;
            g_xg[row + col] = f2sum(acc2[i][j]) + eb[j0 + col];
        }
    }
}

// ---------------- persistent LSTM: all 32 encoder + 10 decoder steps ----------------
__device__ __forceinline__ void grid_barrier() {
    __syncthreads();
    if (threadIdx.x == 0) {
        __threadfence();
        unsigned gen = g_gen;
        if (atomicAdd(&g_cnt, 1) == NBLK - 1) {
            g_cnt = 0;
            __threadfence();
            g_gen = gen + 1;
        } else {
            while (g_gen == gen) __nanosleep(64);
        }
        __threadfence();
    }
    __syncthreads();
}

__global__ void __launch_bounds__(256, 1) lstm_persistent(
    const float* __restrict__ encw, const float* __restrict__ dwi,
    const float* __restrict__ dwh, const float* __restrict__ decb)
{
    extern __shared__ float sm[];
    float* wse = sm;                   // 128 rows x WPAD encoder slice
    float* wsd = sm + 128 * WPAD;      // 128 rows x WPAD decoder slice (ih+hh)
    float* hs  = sm + 2 * 128 * WPAD;  // 32 x 128 plain

    int tid = threadIdx.x;
    int b0 = (blockIdx.x & 31) * 32;
    int u0 = (blockIdx.x >> 5) * 32;

    // stage weights once: row = gate*32 + ul  <->  global gate*128 + u0 + ul
    for (int i = tid; i < 128 * 128; i += 256) {
        int row = i >> 7, k = i & 127;
        int grow = ((row >> 5) * 128) + u0 + (row & 31);
        wse[row * WPAD + k] = encw[grow * 128 + k];
        wsd[row * WPAD + k] = dwi[grow * 128 + k] + dwh[grow * 128 + k];
    }
    for (int i = tid; i < 32 * 128; i += 256) hs[i] = 0.f;
    __syncthreads();

    int tj = tid & 31, tr = tid >> 5;
    int u = u0 + tj;
    float db[4];
#pragma unroll
    for (int a = 0; a < 4; a++) db[a] = decb[a * 128 + u];

    float c[4];
#pragma unroll
    for (int b = 0; b < 4; b++) c[b] = 0.f;

    for (int step = 0; step < 42; step++) {
        const float* ws = (step < 32) ? wse : wsd;
        unsigned long long acc2[4][4];
#pragma unroll
        for (int a = 0; a < 4; a++)
#pragma unroll
            for (int b = 0; b < 4; b++) acc2[a][b] = 0ull;

        for (int kk = 0; kk < 32; kk++) {
            ulonglong2 w2v[4], h2v[4];
#pragma unroll
            for (int a = 0; a < 4; a++)
                w2v[a] = *reinterpret_cast<const ulonglong2*>(&ws[(a * 32 + tj) * WPAD + (kk << 2)]);
#pragma unroll
            for (int b = 0; b < 4; b++)
                h2v[b] = *reinterpret_cast<const ulonglong2*>(&hs[(tr + 8 * b) * 128 + (kk << 2)]);
#pragma unroll
            for (int a = 0; a < 4; a++)
#pragma unroll
                for (int b = 0; b < 4; b++) {
                    fma2(acc2[a][b], w2v[a].x, h2v[b].x);
                    fma2(acc2[a][b], w2v[a].y, h2v[b].y);
                }
        }

        int wsel = step & 1;
        float* h_out = g_hbuf[wsel];
#pragma unroll
        for (int b = 0; b < 4; b++) {
            int brow = b0 + tr + 8 * b;
            float gi = f2sum(acc2[0][b]);
            float gf = f2sum(acc2[1][b]);
            float gg = f2sum(acc2[2][b]);
            float go = f2sum(acc2[3][b]);
            if (step < 32) {
                const float* xr = g_xg + ((long)brow * 32 + step) * 512;
                gi += xr[0 * 128 + u];
                gf += xr[1 * 128 + u];
                gg += xr[2 * 128 + u];
                go += xr[3 * 128 + u];
            } else {
                gi += db[0]; gf += db[1]; gg += db[2]; go += db[3];
            }
            float si = 1.f / (1.f + __expf(-gi));
            float sf = 1.f / (1.f + __expf(-gf));
            float so = 1.f / (1.f + __expf(-go));
            float tg = tanhf(gg);
            float cn = sf * c[b] + si * tg;
            c[b] = cn;
            float hn = so * tanhf(cn);
            int ci = brow * 128 + u;
            h_out[ci] = hn;
            if (step >= 32) g_hdec[step - 32][ci] = hn;
        }

        if (step < 41) {
            grid_barrier();
            const float4* src = (const float4*)&g_hbuf[wsel][b0 * 128];
            float4* dst = (float4*)hs;
            for (int i = tid; i < 32 * 128 / 4; i += 256) dst[i] = src[i];
            __syncthreads();
        }
    }
}

// ---------------- output head ----------------
__global__ void head_kernel(const float* __restrict__ ow, const float* __restrict__ ob,
                            float* __restrict__ out)
{
    __shared__ float hsm[64 * 129];
    __shared__ float wsm[12 * 129];
    __shared__ float bsm[12];
    int tid = threadIdx.x;
    int s = blockIdx.y, b0 = blockIdx.x * 64;
    for (int i = tid; i < 64 * 128; i += 256) {
        int r = i >> 7, k = i & 127;
        hsm[r * 129 + k] = g_hdec[s][(b0 + r) * 128 + k];
    }
    for (int i = tid; i < 12 * 128; i += 256) {
        int r = i / 128, k = i % 128;
        wsm[r * 129 + k] = ow[i];
    }
    if (tid < 12) bsm[tid] = ob[tid];
    __syncthreads();
    for (int it = tid; it < 64 * 12; it += 256) {
        int b = it / 12, v = it % 12;
        float acc = bsm[v];
        for (int k = 0; k < 128; k++) acc += hsm[b * 129 + k] * wsm[v * 129 + k];
        out[(long)(b0 + b) * 120 + s * 12 + v] = acc;
    }
}

// ---------------- launcher ----------------
extern "C" void kernel_launch(void* const* d_in, const int* in_sizes, int n_in,
                              void* d_out, int out_size)
{
    const float* obs    = (const float*)d_in[0];
    const float* c1w    = (const float*)d_in[1];
    const float* c1b    = (const float*)d_in[2];
    const float* c2w    = (const float*)d_in[3];
    const float* c2b    = (const float*)d_in[4];
    const float* fc1w   = (const float*)d_in[5];
    const float* fc1b   = (const float*)d_in[6];
    const float* bn1g   = (const float*)d_in[7];
    const float* bn1b   = (const float*)d_in[8];
    const float* bn1m   = (const float*)d_in[9];
    const float* bn1v   = (const float*)d_in[10];
    const float* fc2w   = (const float*)d_in[11];
    const float* fc2b   = (const float*)d_in[12];
    const float* bn2g   = (const float*)d_in[13];
    const float* bn2b   = (const float*)d_in[14];
    const float* bn2m   = (const float*)d_in[15];
    const float* bn2v   = (const float*)d_in[16];
    const float* encwih = (const float*)d_in[17];
    const float* encwhh = (const float*)d_in[18];
    const float* encb   = (const float*)d_in[19];
    const float* decwih = (const float*)d_in[20];
    const float* decwhh = (const float*)d_in[21];
    const float* decb   = (const float*)d_in[22];
    const float* outw   = (const float*)d_in[23];
    const float* outb   = (const float*)d_in[24];
    float* out = (float*)d_out;

    const int fc_smem    = (128 * WPAD + 64 * WPAD + 64 * 128 * 2) * 4;
    const int xproj_smem = (128 * 64 + 128 * BPAD) * 4;
    const int lstm_smem  = (2 * 128 * WPAD + 32 * 128) * 4;
    cudaFuncSetAttribute(fc_kernel, cudaFuncAttributeMaxDynamicSharedMemorySize, fc_smem);
    cudaFuncSetAttribute(xproj_kernel, cudaFuncAttributeMaxDynamicSharedMemorySize, xproj_smem);
    cudaFuncSetAttribute(lstm_persistent, cudaFuncAttributeMaxDynamicSharedMemorySize, lstm_smem);

    cnn_kernel<<<32768 / FPB, 128>>>(obs, c1w, c1b, c2w, c2b);
    fc_kernel<<<512, 256, fc_smem>>>(fc1w, fc1b, bn1g, bn1b, bn1m, bn1v,
                                     fc2w, fc2b, bn2g, bn2b, bn2m, bn2v);
    dim3 xgrid(256, 4);
    xproj_kernel<<<xgrid, 512, xproj_smem>>>(encwih, encb);

    lstm_persistent<<<NBLK, 256, lstm_smem>>>(encwhh, decwih, decwhh, decb);

    dim3 hgrid(16, 10);
    head_kernel<<<hgrid, 256>>>(outw, outb, out);
}

// round 6
// speedup vs baseline: 3.2938x; 1.1820x over previous
#include <cuda_runtime.h>
#include <math.h>

// ---------------- scratch (static device globals; no allocation) ----------------
__device__ float g_cnn[32768 * 128];     // CNN output per frame
__device__ float g_feats[32768 * 64];    // after FC+BN stack
__device__ float g_xg[32768 * 512];      // precomputed x @ enc_w_ih^T + enc_b
__device__ float g_hdec[10][1024 * 128]; // decoder h history for output head

#define WPAD 132   // weight row pad: 132 % 32 == 4 -> consecutive rows hit banks +4 apart

__device__ __forceinline__ void fma2(unsigned long long& d,
                                     unsigned long long a, unsigned long long b) {
    asm("fma.rn.f32x2 %0, %1, %2, %0;" : "+l"(d) : "l"(a), "l"(b));
}
__device__ __forceinline__ float f2sum(unsigned long long v) {
    float lo = __uint_as_float((unsigned)(v & 0xffffffffull));
    float hi = __uint_as_float((unsigned)(v >> 32));
    return lo + hi;
}
__device__ __forceinline__ unsigned smem_u32(const void* p) {
    unsigned a;
    asm("{ .reg .u64 t; cvta.to.shared.u64 t, %1; cvt.u32.u64 %0, t; }" : "=r"(a) : "l"(p));
    return a;
}

// ---------------- CNN: conv1+relu+pool, conv2+relu+pool ----------------
#define FPB 4
__global__ void cnn_kernel(const float* __restrict__ obs,
                           const float* __restrict__ w1, const float* __restrict__ b1,
                           const float* __restrict__ w2, const float* __restrict__ b2)
{
    __shared__ float s_in[FPB][4][12][12];   // 10x10 + 1 pad each side
    __shared__ float s_p1[FPB][16][7][7];    // 5x5 pooled + 1 pad each side
    __shared__ float s_w1[576];
    __shared__ float s_b1[16];
    __shared__ float s_w2t[144 * 33];        // [ic*9+q][oc] padded 33
    __shared__ float s_b2[32];

    int tid = threadIdx.x; // 128
    for (int i = tid; i < FPB * 4 * 144; i += 128) ((float*)s_in)[i] = 0.f;
    for (int i = tid; i < FPB * 16 * 49; i += 128) ((float*)s_p1)[i] = 0.f;
    for (int i = tid; i < 576; i += 128) s_w1[i] = w1[i];
    if (tid < 16) s_b1[tid] = b1[tid];
    for (int i = tid; i < 4608; i += 128) {
        int oc = i / 144, r = i % 144;
        s_w2t[r * 33 + oc] = w2[i];
    }
    if (tid < 32) s_b2[tid] = b2[tid];
    __syncthreads();

    int f0 = blockIdx.x * FPB;
    for (int i = tid; i < FPB * 400; i += 128) {
        int f = i / 400, rem = i % 400;
        int ic = rem / 100, p = rem % 100, y = p / 10, x = p % 10;
        s_in[f][ic][y + 1][x + 1] = obs[(long)f0 * 400 + i];
    }
    __syncthreads();

    if (tid < FPB * 25) {
        int f = tid / 25, pp = tid % 25, py = pp / 5, px = pp % 5;
        float patch[4][4][4];
#pragma unroll
        for (int ic = 0; ic < 4; ic++)
#pragma unroll
            for (int r = 0; r < 4; r++)
#pragma unroll
                for (int cc = 0; cc < 4; cc++)
                    patch[ic][r][cc] = s_in[f][ic][2 * py + r][2 * px + cc];
        for (int oc = 0; oc < 16; oc++) {
            float a0 = s_b1[oc], a1 = a0, a2 = a0, a3 = a0;
#pragma unroll
            for (int ic = 0; ic < 4; ic++)
#pragma unroll
                for (int ky = 0; ky < 3; ky++)
#pragma unroll
                    for (int kx = 0; kx < 3; kx++) {
                        float w = s_w1[(oc * 4 + ic) * 9 + ky * 3 + kx];
                        a0 += patch[ic][ky][kx] * w;
                        a1 += patch[ic][ky][kx + 1] * w;
                        a2 += patch[ic][ky + 1][kx] * w;
                        a3 += patch[ic][ky + 1][kx + 1] * w;
                    }
            float m = fmaxf(fmaxf(fmaxf(a0, a1), fmaxf(a2, a3)), 0.f);
            s_p1[f][oc][py + 1][px + 1] = m;
        }
    }
    __syncthreads();

    {
        int oc = tid & 31, f = tid >> 5;
        float acc[16];
        float bb = s_b2[oc];
#pragma unroll
        for (int p = 0; p < 16; p++) acc[p] = bb;
        for (int ic = 0; ic < 16; ic++) {
#pragma unroll
            for (int ky = 0; ky < 3; ky++)
#pragma unroll
                for (int kx = 0; kx < 3; kx++) {
                    float w = s_w2t[(ic * 9 + ky * 3 + kx) * 33 + oc];
#pragma unroll
                    for (int y = 0; y < 4; y++)
#pragma unroll
                        for (int x = 0; x < 4; x++)
                            acc[y * 4 + x] += s_p1[f][ic][y + ky][x + kx] * w;
                }
        }
#pragma unroll
        for (int py = 0; py < 2; py++)
#pragma unroll
            for (int px = 0; px < 2; px++) {
                float m = fmaxf(fmaxf(acc[(2 * py) * 4 + 2 * px], acc[(2 * py) * 4 + 2 * px + 1]),
                                fmaxf(acc[(2 * py + 1) * 4 + 2 * px], acc[(2 * py + 1) * 4 + 2 * px + 1]));
                g_cnn[(long)(f0 + f) * 128 + oc * 4 + py * 2 + px] = fmaxf(m, 0.f);
            }
    }
}

// ---------------- FC stack: fc1+bn1+relu -> fc2+bn2+relu (f32x2, pad-132) ----------------
__global__ void __launch_bounds__(256) fc_kernel(
    const float* __restrict__ fc1w, const float* __restrict__ fc1b,
    const float* __restrict__ g1, const float* __restrict__ be1,
    const float* __restrict__ m1, const float* __restrict__ v1,
    const float* __restrict__ fc2w, const float* __restrict__ fc2b,
    const float* __restrict__ g2, const float* __restrict__ be2,
    const float* __restrict__ m2, const float* __restrict__ v2)
{
    extern __shared__ float sm[];
    float* w1s = sm;                   // 128 rows x WPAD
    float* w2s = w1s + 128 * WPAD;     // 64 rows x WPAD
    float* xs  = w2s + 64 * WPAD;      // 64 x 128 plain
    float* ms  = xs + 64 * 128;        // 64 x 128 plain

    int tid = threadIdx.x;
    long r0 = (long)blockIdx.x * 64;
    for (int i = tid; i < 128 * 128; i += 256) {
        int row = i >> 7, k = i & 127;
        w1s[row * WPAD + k] = fc1w[i];
    }
    for (int i = tid; i < 64 * 128; i += 256) {
        int row = i >> 7, k = i & 127;
        w2s[row * WPAD + k] = fc2w[i];
    }
    for (int i = tid; i < 64 * 128; i += 256) xs[i] = g_cnn[r0 * 128 + i];
    __syncthreads();

    int tj = tid & 31, tr = tid >> 5;
    {
        unsigned long long acc2[4][8];
#pragma unroll
        for (int a = 0; a < 4; a++)
#pragma unroll
            for (int b = 0; b < 8; b++) acc2[a][b] = 0ull;
        for (int kk = 0; kk < 32; kk++) {
            ulonglong2 w2v[4], h2v[8];
#pragma unroll
            for (int a = 0; a < 4; a++)
                w2v[a] = *reinterpret_cast<const ulonglong2*>(&w1s[(tj + 32 * a) * WPAD + (kk << 2)]);
#pragma unroll
            for (int b = 0; b < 8; b++)
                h2v[b] = *reinterpret_cast<const ulonglong2*>(&xs[(tr * 8 + b) * 128 + (kk << 2)]);
#pragma unroll
            for (int a = 0; a < 4; a++)
#pragma unroll
                for (int b = 0; b < 8; b++) {
                    fma2(acc2[a][b], w2v[a].x, h2v[b].x);
                    fma2(acc2[a][b], w2v[a].y, h2v[b].y);
                }
        }
#pragma unroll
        for (int a = 0; a < 4; a++) {
            int j = tj + 32 * a;
            float s = g1[j] * rsqrtf(v1[j] + 1e-5f);
            float bb = (fc1b[j] - m1[j]) * s + be1[j];
#pragma unroll
            for (int b = 0; b < 8; b++)
                ms[(tr * 8 + b) * 128 + j] = fmaxf(f2sum(acc2[a][b]) * s + bb, 0.f);
        }
    }
    __syncthreads();
    {
        unsigned long long acc2[2][8];
#pragma unroll
        for (int a = 0; a < 2; a++)
#pragma unroll
            for (int b = 0; b < 8; b++) acc2[a][b] = 0ull;
        for (int kk = 0; kk < 32; kk++) {
            ulonglong2 w2v[2], h2v[8];
#pragma unroll
            for (int a = 0; a < 2; a++)
                w2v[a] = *reinterpret_cast<const ulonglong2*>(&w2s[(tj + 32 * a) * WPAD + (kk << 2)]);
#pragma unroll
            for (int b = 0; b < 8; b++)
                h2v[b] = *reinterpret_cast<const ulonglong2*>(&ms[(tr * 8 + b) * 128 + (kk << 2)]);
#pragma unroll
            for (int a = 0; a < 2; a++)
#pragma unroll
                for (int b = 0; b < 8; b++) {
                    fma2(acc2[a][b], w2v[a].x, h2v[b].x);
                    fma2(acc2[a][b], w2v[a].y, h2v[b].y);
                }
        }
#pragma unroll
        for (int a = 0; a < 2; a++) {
            int j = tj + 32 * a;
            float s = g2[j] * rsqrtf(v2[j] + 1e-5f);
            float bb = (fc2b[j] - m2[j]) * s + be2[j];
#pragma unroll
            for (int b = 0; b < 8; b++)
                g_feats[(r0 + tr * 8 + b) * 64 + j] = fmaxf(f2sum(acc2[a][b]) * s + bb, 0.f);
        }
    }
}

// ---------------- encoder x-projection GEMM (f32x2, pad, strided n-cols) ----------------
#define BPAD 68   // 68 % 32 == 4
__global__ void __launch_bounds__(512) xproj_kernel(const float* __restrict__ wih,
                                                    const float* __restrict__ eb)
{
    extern __shared__ float sm[];
    float* As = sm;               // [128][64] plain (m-major)
    float* Bs = sm + 128 * 64;    // [128][BPAD] (j-major, padded)

    int tid = threadIdx.x;
    long r0 = (long)blockIdx.x * 128;
    int j0 = blockIdx.y * 128;

    for (int i = tid; i < 128 * 64; i += 512) As[i] = g_feats[r0 * 64 + i];
    for (int i = tid; i < 128 * 64; i += 512) {
        int j = i >> 6, k = i & 63;
        Bs[j * BPAD + k] = wih[(long)(j0 + j) * 64 + k];
    }
    __syncthreads();

    int tx = tid & 15, ty = tid >> 4; // ty 0..31
    int m0 = ty * 4;

    unsigned long long acc2[4][8];
#pragma unroll
    for (int i = 0; i < 4; i++)
#pragma unroll
        for (int j = 0; j < 8; j++) acc2[i][j] = 0ull;

    for (int kk = 0; kk < 16; kk++) {
        ulonglong2 a2[4], b2[8];
#pragma unroll
        for (int i = 0; i < 4; i++)
            a2[i] = *reinterpret_cast<const ulonglong2*>(&As[(m0 + i) * 64 + (kk << 2)]);
#pragma unroll
        for (int j = 0; j < 8; j++)
            b2[j] = *reinterpret_cast<const ulonglong2*>(&Bs[(tx + 16 * j) * BPAD + (kk << 2)]);
#pragma unroll
        for (int i = 0; i < 4; i++)
#pragma unroll
            for (int j = 0; j < 8; j++) {
                fma2(acc2[i][j], a2[i].x, b2[j].x);
                fma2(acc2[i][j], a2[i].y, b2[j].y);
            }
    }

#pragma unroll
    for (int i = 0; i < 4; i++) {
        long row = (r0 + m0 + i) * 512 + j0;
#pragma unroll
        for (int j = 0; j < 8; j++) {
            int col = tx + 16 * j;
            g_xg[row + col] = f2sum(acc2[i][j]) + eb[j0 + col];
        }
    }
}

// ---------------- persistent LSTM: clusters of 4, h via DSMEM, no grid barrier --------
// grid 128 = 32 clusters x 4 CTAs (u-tiles). Each cluster owns 32 batches.
// hs double-buffered; one barrier.cluster per step.
__global__ void __launch_bounds__(256, 1) __cluster_dims__(4, 1, 1)
lstm_persistent(const float* __restrict__ encw, const float* __restrict__ dwi,
                const float* __restrict__ dwh, const float* __restrict__ decb)
{
    extern __shared__ float sm[];
    float* wse = sm;                   // 128 rows x WPAD encoder slice
    float* wsd = sm + 128 * WPAD;      // 128 rows x WPAD decoder slice (ih+hh)
    float* hs  = sm + 2 * 128 * WPAD;  // 2 buffers x 32 x 128

    int tid = threadIdx.x;
    unsigned rank = blockIdx.x & 3;    // cluster_ctarank (cluster_dims x=4)
    int b0 = (blockIdx.x >> 2) * 32;   // batch tile (per cluster)
    int u0 = rank * 32;                // unit tile (per CTA)

    // stage weights once: row = gate*32 + ul  <->  global gate*128 + u0 + ul
    for (int i = tid; i < 128 * 128; i += 256) {
        int row = i >> 7, k = i & 127;
        int grow = ((row >> 5) * 128) + u0 + (row & 31);
        wse[row * WPAD + k] = encw[grow * 128 + k];
        wsd[row * WPAD + k] = dwi[grow * 128 + k] + dwh[grow * 128 + k];
    }
    for (int i = tid; i < 32 * 128; i += 256) hs[i] = 0.f;  // buffer 0 only

    // DSMEM base addresses of hs in all 4 cluster CTAs
    unsigned hs_local = smem_u32(hs);
    unsigned rb[4];
#pragma unroll
    for (int r = 0; r < 4; r++)
        asm("mapa.shared::cluster.u32 %0, %1, %2;" : "=r"(rb[r]) : "r"(hs_local), "r"(r));

    __syncthreads();
    // make sure every CTA finished init before any peer writes into our hs[1]
    asm volatile("barrier.cluster.arrive.aligned;" ::: "memory");
    asm volatile("barrier.cluster.wait.aligned;" ::: "memory");

    int tj = tid & 31, tr = tid >> 5;
    int u = u0 + tj;
    float db[4];
#pragma unroll
    for (int a = 0; a < 4; a++) db[a] = decb[a * 128 + u];

    float c[4];
#pragma unroll
    for (int b = 0; b < 4; b++) c[b] = 0.f;

    int pread = 0;
    for (int step = 0; step < 42; step++) {
        const float* ws = (step < 32) ? wse : wsd;
        const float* hsr = hs + pread * (32 * 128);

        // prefetch per-step additive gate inputs (xg for encoder, bias for decoder)
        float xn[4][4];
        if (step < 32) {
#pragma unroll
            for (int b = 0; b < 4; b++) {
                const float* xr = g_xg + ((long)(b0 + tr + 8 * b) * 32 + step) * 512;
#pragma unroll
                for (int a = 0; a < 4; a++) xn[b][a] = xr[a * 128 + u];
            }
        } else {
#pragma unroll
            for (int b = 0; b < 4; b++)
#pragma unroll
                for (int a = 0; a < 4; a++) xn[b][a] = db[a];
        }

        unsigned long long acc2[4][4];
#pragma unroll
        for (int a = 0; a < 4; a++)
#pragma unroll
            for (int b = 0; b < 4; b++) acc2[a][b] = 0ull;

        for (int kk = 0; kk < 32; kk++) {
            ulonglong2 w2v[4], h2v[4];
#pragma unroll
            for (int a = 0; a < 4; a++)
                w2v[a] = *reinterpret_cast<const ulonglong2*>(&ws[(a * 32 + tj) * WPAD + (kk << 2)]);
#pragma unroll
            for (int b = 0; b < 4; b++)
                h2v[b] = *reinterpret_cast<const ulonglong2*>(&hsr[(tr + 8 * b) * 128 + (kk << 2)]);
#pragma unroll
            for (int a = 0; a < 4; a++)
#pragma unroll
                for (int b = 0; b < 4; b++) {
                    fma2(acc2[a][b], w2v[a].x, h2v[b].x);
                    fma2(acc2[a][b], w2v[a].y, h2v[b].y);
                }
        }

        unsigned woff = (unsigned)((1 - pread) * (32 * 128 * 4));
#pragma unroll
        for (int b = 0; b < 4; b++) {
            int rloc = tr + 8 * b;          // row within batch tile
            float gi = f2sum(acc2[0][b]) + xn[b][0];
            float gf = f2sum(acc2[1][b]) + xn[b][1];
            float gg = f2sum(acc2[2][b]) + xn[b][2];
            float go = f2sum(acc2[3][b]) + xn[b][3];
            float si = 1.f / (1.f + __expf(-gi));
            float sf = 1.f / (1.f + __expf(-gf));
            float so = 1.f / (1.f + __expf(-go));
            float tg = tanhf(gg);
            float cn = sf * c[b] + si * tg;
            c[b] = cn;
            float hn = so * tanhf(cn);
            if (step < 41) {
                unsigned eoff = woff + (unsigned)(rloc * 128 + u) * 4u;
#pragma unroll
                for (int r = 0; r < 4; r++)
                    asm volatile("st.shared::cluster.f32 [%0], %1;"
                                 :: "r"(rb[r] + eoff), "f"(hn) : "memory");
            }
            if (step >= 32) g_hdec[step - 32][(b0 + rloc) * 128 + u] = hn;
        }

        if (step < 41) {
            asm volatile("barrier.cluster.arrive.aligned;" ::: "memory");
            asm volatile("barrier.cluster.wait.aligned;" ::: "memory");
            pread ^= 1;
        }
    }

    // final cluster sync before exit (no peer writes may target our smem after this)
    asm volatile("barrier.cluster.arrive.aligned;" ::: "memory");
    asm volatile("barrier.cluster.wait.aligned;" ::: "memory");
}

// ---------------- output head ----------------
__global__ void head_kernel(const float* __restrict__ ow, const float* __restrict__ ob,
                            float* __restrict__ out)
{
    __shared__ float hsm[64 * 129];
    __shared__ float wsm[12 * 129];
    __shared__ float bsm[12];
    int tid = threadIdx.x;
    int s = blockIdx.y, b0 = blockIdx.x * 64;
    for (int i = tid; i < 64 * 128; i += 256) {
        int r = i >> 7, k = i & 127;
        hsm[r * 129 + k] = g_hdec[s][(b0 + r) * 128 + k];
    }
    for (int i = tid; i < 12 * 128; i += 256) {
        int r = i / 128, k = i % 128;
        wsm[r * 129 + k] = ow[i];
    }
    if (tid < 12) bsm[tid] = ob[tid];
    __syncthreads();
    for (int it = tid; it < 64 * 12; it += 256) {
        int b = it / 12, v = it % 12;
        float acc = bsm[v];
        for (int k = 0; k < 128; k++) acc += hsm[b * 129 + k] * wsm[v * 129 + k];
        out[(long)(b0 + b) * 120 + s * 12 + v] = acc;
    }
}

// ---------------- launcher ----------------
extern "C" void kernel_launch(void* const* d_in, const int* in_sizes, int n_in,
                              void* d_out, int out_size)
{
    const float* obs    = (const float*)d_in[0];
    const float* c1w    = (const float*)d_in[1];
    const float* c1b    = (const float*)d_in[2];
    const float* c2w    = (const float*)d_in[3];
    const float* c2b    = (const float*)d_in[4];
    const float* fc1w   = (const float*)d_in[5];
    const float* fc1b   = (const float*)d_in[6];
    const float* bn1g   = (const float*)d_in[7];
    const float* bn1b   = (const float*)d_in[8];
    const float* bn1m   = (const float*)d_in[9];
    const float* bn1v   = (const float*)d_in[10];
    const float* fc2w   = (const float*)d_in[11];
    const float* fc2b   = (const float*)d_in[12];
    const float* bn2g   = (const float*)d_in[13];
    const float* bn2b   = (const float*)d_in[14];
    const float* bn2m   = (const float*)d_in[15];
    const float* bn2v   = (const float*)d_in[16];
    const float* encwih = (const float*)d_in[17];
    const float* encwhh = (const float*)d_in[18];
    const float* encb   = (const float*)d_in[19];
    const float* decwih = (const float*)d_in[20];
    const float* decwhh = (const float*)d_in[21];
    const float* decb   = (const float*)d_in[22];
    const float* outw   = (const float*)d_in[23];
    const float* outb   = (const float*)d_in[24];
    float* out = (float*)d_out;

    const int fc_smem    = (128 * WPAD + 64 * WPAD + 64 * 128 * 2) * 4;
    const int xproj_smem = (128 * 64 + 128 * BPAD) * 4;
    const int lstm_smem  = (2 * 128 * WPAD + 2 * 32 * 128) * 4;   // 167936 B
    cudaFuncSetAttribute(fc_kernel, cudaFuncAttributeMaxDynamicSharedMemorySize, fc_smem);
    cudaFuncSetAttribute(xproj_kernel, cudaFuncAttributeMaxDynamicSharedMemorySize, xproj_smem);
    cudaFuncSetAttribute(lstm_persistent, cudaFuncAttributeMaxDynamicSharedMemorySize, lstm_smem);

    cnn_kernel<<<32768 / FPB, 128>>>(obs, c1w, c1b, c2w, c2b);
    fc_kernel<<<512, 256, fc_smem>>>(fc1w, fc1b, bn1g, bn1b, bn1m, bn1v,
                                     fc2w, fc2b, bn2g, bn2b, bn2m, bn2v);
    dim3 xgrid(256, 4);
    xproj_kernel<<<xgrid, 512, xproj_smem>>>(encwih, encb);

    lstm_persistent<<<128, 256, lstm_smem>>>(encwhh, decwih, decwhh, decb);

    dim3 hgrid(16, 10);
    head_kernel<<<hgrid, 256>>>(outw, outb, out);
}

// round 7
// speedup vs baseline: 3.3698x; 1.0231x over previous
#include <cuda_runtime.h>
#include <math.h>

// ---------------- scratch (static device globals; no allocation) ----------------
__device__ float g_cnn[32768 * 128];     // CNN output per frame
__device__ float g_feats[32768 * 64];    // after FC+BN stack
__device__ float g_xg[32768 * 512];      // precomputed x @ enc_w_ih^T + enc_b
__device__ float g_hdec[10][1024 * 128]; // decoder h history for output head

#define WPAD 132   // weight row pad: 132 % 32 == 4

__device__ __forceinline__ void fma2(unsigned long long& d,
                                     unsigned long long a, unsigned long long b) {
    asm("fma.rn.f32x2 %0, %1, %2, %0;" : "+l"(d) : "l"(a), "l"(b));
}
__device__ __forceinline__ unsigned long long pack2(float v) {
    unsigned long long r;
    asm("mov.b64 %0, {%1, %1};" : "=l"(r) : "f"(v));
    return r;
}
__device__ __forceinline__ float ulo(unsigned long long v) {
    return __uint_as_float((unsigned)(v & 0xffffffffull));
}
__device__ __forceinline__ float uhi(unsigned long long v) {
    return __uint_as_float((unsigned)(v >> 32));
}
__device__ __forceinline__ float f2sum(unsigned long long v) { return ulo(v) + uhi(v); }
__device__ __forceinline__ unsigned smem_u32(const void* p) {
    unsigned a;
    asm("{ .reg .u64 t; cvta.to.shared.u64 t, %1; cvt.u32.u64 %0, t; }" : "=r"(a) : "l"(p));
    return a;
}

// ---------------- CNN: frame-pair packed f32x2 ----------------
// 4 frames per block = 2 frame-pairs; values for frames (2fp, 2fp+1) live in
// one packed f32x2 register. Interleaved smem layouts give direct LDS.64 pairs.
#define FPB 4
__global__ void __launch_bounds__(128) cnn_kernel(
    const float* __restrict__ obs,
    const float* __restrict__ w1, const float* __restrict__ b1,
    const float* __restrict__ w2, const float* __restrict__ b2)
{
    __shared__ float s_ini[4 * 12 * 12 * 4];   // [ic][y][x][f], zero-padded border
    __shared__ float s_p1i[16 * 7 * 7 * 4];    // [oc][r][c][f], zero-padded border
    __shared__ float s_w1[576];
    __shared__ float s_b1[16];
    __shared__ float s_w2t[144 * 33];          // [ic*9+q][oc] padded 33
    __shared__ float s_b2[32];

    int tid = threadIdx.x; // 128
    for (int i = tid; i < 4 * 144 * 4; i += 128) s_ini[i] = 0.f;
    for (int i = tid; i < 16 * 49 * 4; i += 128) s_p1i[i] = 0.f;
    for (int i = tid; i < 576; i += 128) s_w1[i] = w1[i];
    if (tid < 16) s_b1[tid] = b1[tid];
    for (int i = tid; i < 4608; i += 128) {
        int oc = i / 144, r = i % 144;
        s_w2t[r * 33 + oc] = w2[i];
    }
    if (tid < 32) s_b2[tid] = b2[tid];
    __syncthreads();

    int f0 = blockIdx.x * FPB;
    for (int i = tid; i < FPB * 400; i += 128) {
        int f = i / 400, rem = i % 400;
        int ic = rem / 100, p = rem % 100, y = p / 10, x = p % 10;
        s_ini[((ic * 12 + y + 1) * 12 + x + 1) * 4 + f] = obs[(long)f0 * 400 + i];
    }
    __syncthreads();

    // phase 1: conv1 (3x3 SAME, 4->16) + relu + maxpool2.
    // 100 threads: (fp, ocg, pos). Each: 8 ocs x 4 positions x 2 frames packed.
    if (tid < 100) {
        int fp = tid / 50, rem = tid % 50, ocg = rem / 25, pos = rem % 25;
        int py = pos / 5, px = pos % 5;
        unsigned long long acc2[8][4];
#pragma unroll
        for (int o = 0; o < 8; o++) {
            unsigned long long bp = pack2(s_b1[ocg * 8 + o]);
#pragma unroll
            for (int p = 0; p < 4; p++) acc2[o][p] = bp;
        }
#pragma unroll
        for (int ic = 0; ic < 4; ic++) {
            unsigned long long patch2[4][4];
#pragma unroll
            for (int r = 0; r < 4; r++)
#pragma unroll
                for (int cc = 0; cc < 4; cc++)
                    patch2[r][cc] = *(const unsigned long long*)
                        &s_ini[((ic * 12 + 2 * py + r) * 12 + 2 * px + cc) * 4 + fp * 2];
#pragma unroll
            for (int o = 0; o < 8; o++) {
                int oc = ocg * 8 + o;
#pragma unroll
                for (int ky = 0; ky < 3; ky++)
#pragma unroll
                    for (int kx = 0; kx < 3; kx++) {
                        unsigned long long wp = pack2(s_w1[(oc * 4 + ic) * 9 + ky * 3 + kx]);
                        fma2(acc2[o][0], patch2[ky][kx], wp);
                        fma2(acc2[o][1], patch2[ky][kx + 1], wp);
                        fma2(acc2[o][2], patch2[ky + 1][kx], wp);
                        fma2(acc2[o][3], patch2[ky + 1][kx + 1], wp);
                    }
            }
        }
#pragma unroll
        for (int o = 0; o < 8; o++) {
            int oc = ocg * 8 + o;
            float mlo = fmaxf(fmaxf(ulo(acc2[o][0]), ulo(acc2[o][1])),
                              fmaxf(ulo(acc2[o][2]), ulo(acc2[o][3])));
            float mhi = fmaxf(fmaxf(uhi(acc2[o][0]), uhi(acc2[o][1])),
                              fmaxf(uhi(acc2[o][2]), uhi(acc2[o][3])));
            int base = ((oc * 7 + py + 1) * 7 + px + 1) * 4 + fp * 2;
            s_p1i[base] = fmaxf(mlo, 0.f);
            s_p1i[base + 1] = fmaxf(mhi, 0.f);
        }
    }
    __syncthreads();

    // phase 2: conv2 (3x3 SAME, 16->32) + relu + maxpool2(floor -> 4x4 region).
    // 128 threads: (half, fp, oc). Input pairs loaded directly with LDS.64.
    {
        int half = tid >> 6, fp = (tid >> 5) & 1, oc = tid & 31;
        unsigned long long acc2[2][4];
        unsigned long long bp = pack2(s_b2[oc]);
#pragma unroll
        for (int yl = 0; yl < 2; yl++)
#pragma unroll
            for (int x = 0; x < 4; x++) acc2[yl][x] = bp;

        for (int ic = 0; ic < 16; ic++) {
            unsigned long long in2[4][6];
#pragma unroll
            for (int rl = 0; rl < 4; rl++)
#pragma unroll
                for (int cc = 0; cc < 6; cc++)
                    in2[rl][cc] = *(const unsigned long long*)
                        &s_p1i[((ic * 7 + 2 * half + rl) * 7 + cc) * 4 + fp * 2];
#pragma unroll
            for (int ky = 0; ky < 3; ky++)
#pragma unroll
                for (int kx = 0; kx < 3; kx++) {
                    unsigned long long wp = pack2(s_w2t[(ic * 9 + ky * 3 + kx) * 33 + oc]);
#pragma unroll
                    for (int yl = 0; yl < 2; yl++)
#pragma unroll
                        for (int x = 0; x < 4; x++)
                            fma2(acc2[yl][x], in2[yl + ky][x + kx], wp);
                }
        }
#pragma unroll
        for (int px = 0; px < 2; px++) {
            float mlo = fmaxf(fmaxf(ulo(acc2[0][2 * px]), ulo(acc2[0][2 * px + 1])),
                              fmaxf(ulo(acc2[1][2 * px]), ulo(acc2[1][2 * px + 1])));
            float mhi = fmaxf(fmaxf(uhi(acc2[0][2 * px]), uhi(acc2[0][2 * px + 1])),
                              fmaxf(uhi(acc2[1][2 * px]), uhi(acc2[1][2 * px + 1])));
            long fr = f0 + fp * 2;
            g_cnn[fr * 128 + oc * 4 + half * 2 + px] = fmaxf(mlo, 0.f);
            g_cnn[(fr + 1) * 128 + oc * 4 + half * 2 + px] = fmaxf(mhi, 0.f);
        }
    }
}

// ---------------- FC stack: fc1+bn1+relu -> fc2+bn2+relu (f32x2, pad-132) ----------------
__global__ void __launch_bounds__(256) fc_kernel(
    const float* __restrict__ fc1w, const float* __restrict__ fc1b,
    const float* __restrict__ g1, const float* __restrict__ be1,
    const float* __restrict__ m1, const float* __restrict__ v1,
    const float* __restrict__ fc2w, const float* __restrict__ fc2b,
    const float* __restrict__ g2, const float* __restrict__ be2,
    const float* __restrict__ m2, const float* __restrict__ v2)
{
    extern __shared__ float sm[];
    float* w1s = sm;                   // 128 rows x WPAD
    float* w2s = w1s + 128 * WPAD;     // 64 rows x WPAD
    float* xs  = w2s + 64 * WPAD;      // 64 x 128 plain
    float* ms  = xs + 64 * 128;        // 64 x 128 plain

    int tid = threadIdx.x;
    long r0 = (long)blockIdx.x * 64;
    for (int i = tid; i < 128 * 128; i += 256) {
        int row = i >> 7, k = i & 127;
        w1s[row * WPAD + k] = fc1w[i];
    }
    for (int i = tid; i < 64 * 128; i += 256) {
        int row = i >> 7, k = i & 127;
        w2s[row * WPAD + k] = fc2w[i];
    }
    for (int i = tid; i < 64 * 128; i += 256) xs[i] = g_cnn[r0 * 128 + i];
    __syncthreads();

    int tj = tid & 31, tr = tid >> 5;
    {
        unsigned long long acc2[4][8];
#pragma unroll
        for (int a = 0; a < 4; a++)
#pragma unroll
            for (int b = 0; b < 8; b++) acc2[a][b] = 0ull;
        for (int kk = 0; kk < 32; kk++) {
            ulonglong2 w2v[4], h2v[8];
#pragma unroll
            for (int a = 0; a < 4; a++)
                w2v[a] = *reinterpret_cast<const ulonglong2*>(&w1s[(tj + 32 * a) * WPAD + (kk << 2)]);
#pragma unroll
            for (int b = 0; b < 8; b++)
                h2v[b] = *reinterpret_cast<const ulonglong2*>(&xs[(tr * 8 + b) * 128 + (kk << 2)]);
#pragma unroll
            for (int a = 0; a < 4; a++)
#pragma unroll
                for (int b = 0; b < 8; b++) {
                    fma2(acc2[a][b], w2v[a].x, h2v[b].x);
                    fma2(acc2[a][b], w2v[a].y, h2v[b].y);
                }
        }
#pragma unroll
        for (int a = 0; a < 4; a++) {
            int j = tj + 32 * a;
            float s = g1[j] * rsqrtf(v1[j] + 1e-5f);
            float bb = (fc1b[j] - m1[j]) * s + be1[j];
#pragma unroll
            for (int b = 0; b < 8; b++)
                ms[(tr * 8 + b) * 128 + j] = fmaxf(f2sum(acc2[a][b]) * s + bb, 0.f);
        }
    }
    __syncthreads();
    {
        unsigned long long acc2[2][8];
#pragma unroll
        for (int a = 0; a < 2; a++)
#pragma unroll
            for (int b = 0; b < 8; b++) acc2[a][b] = 0ull;
        for (int kk = 0; kk < 32; kk++) {
            ulonglong2 w2v[2], h2v[8];
#pragma unroll
            for (int a = 0; a < 2; a++)
                w2v[a] = *reinterpret_cast<const ulonglong2*>(&w2s[(tj + 32 * a) * WPAD + (kk << 2)]);
#pragma unroll
            for (int b = 0; b < 8; b++)
                h2v[b] = *reinterpret_cast<const ulonglong2*>(&ms[(tr * 8 + b) * 128 + (kk << 2)]);
#pragma unroll
            for (int a = 0; a < 2; a++)
#pragma unroll
                for (int b = 0; b < 8; b++) {
                    fma2(acc2[a][b], w2v[a].x, h2v[b].x);
                    fma2(acc2[a][b], w2v[a].y, h2v[b].y);
                }
        }
#pragma unroll
        for (int a = 0; a < 2; a++) {
            int j = tj + 32 * a;
            float s = g2[j] * rsqrtf(v2[j] + 1e-5f);
            float bb = (fc2b[j] - m2[j]) * s + be2[j];
#pragma unroll
            for (int b = 0; b < 8; b++)
                g_feats[(r0 + tr * 8 + b) * 64 + j] = fmaxf(f2sum(acc2[a][b]) * s + bb, 0.f);
        }
    }
}

// ---------------- encoder x-projection GEMM (f32x2, pad, strided n-cols) ----------------
#define BPAD 68   // 68 % 32 == 4
__global__ void __launch_bounds__(512) xproj_kernel(const float* __restrict__ wih,
                                                    const float* __restrict__ eb)
{
    extern __shared__ float sm[];
    float* As = sm;               // [128][64] plain (m-major)
    float* Bs = sm + 128 * 64;    // [128][BPAD] (j-major, padded)

    int tid = threadIdx.x;
    long r0 = (long)blockIdx.x * 128;
    int j0 = blockIdx.y * 128;

    for (int i = tid; i < 128 * 64; i += 512) As[i] = g_feats[r0 * 64 + i];
    for (int i = tid; i < 128 * 64; i += 512) {
        int j = i >> 6, k = i & 63;
        Bs[j * BPAD + k] = wih[(long)(j0 + j) * 64 + k];
    }
    __syncthreads();

    int tx = tid & 15, ty = tid >> 4; // ty 0..31
    int m0 = ty * 4;

    unsigned long long acc2[4][8];
#pragma unroll
    for (int i = 0; i < 4; i++)
#pragma unroll
        for (int j = 0; j < 8; j++) acc2[i][j] = 0ull;

    for (int kk = 0; kk < 16; kk++) {
        ulonglong2 a2[4], b2[8];
#pragma unroll
        for (int i = 0; i < 4; i++)
            a2[i] = *reinterpret_cast<const ulonglong2*>(&As[(m0 + i) * 64 + (kk << 2)]);
#pragma unroll
        for (int j = 0; j < 8; j++)
            b2[j] = *reinterpret_cast<const ulonglong2*>(&Bs[(tx + 16 * j) * BPAD + (kk << 2)]);
#pragma unroll
        for (int i = 0; i < 4; i++)
#pragma unroll
            for (int j = 0; j < 8; j++) {
                fma2(acc2[i][j], a2[i].x, b2[j].x);
                fma2(acc2[i][j], a2[i].y, b2[j].y);
            }
    }

#pragma unroll
    for (int i = 0; i < 4; i++) {
        long row = (r0 + m0 + i) * 512 + j0;
#pragma unroll
        for (int j = 0; j < 8; j++) {
            int col = tx + 16 * j;
            g_xg[row + col] = f2sum(acc2[i][j]) + eb[j0 + col];
        }
    }
}

// ---------------- persistent LSTM: clusters of 4, h via DSMEM, 16 warps/CTA ----------
// grid 128 = 32 clusters x 4 CTAs (u-tiles). Each warp owns 2 batch rows.
__global__ void __launch_bounds__(512, 1) __cluster_dims__(4, 1, 1)
lstm_persistent(const float* __restrict__ encw, const float* __restrict__ dwi,
                const float* __restrict__ dwh, const float* __restrict__ decb)
{
    extern __shared__ float sm[];
    float* wse = sm;                   // 128 rows x WPAD encoder slice
    float* wsd = sm + 128 * WPAD;      // 128 rows x WPAD decoder slice (ih+hh)
    float* hs  = sm + 2 * 128 * WPAD;  // 2 buffers x 32 x 128

    int tid = threadIdx.x;
    unsigned rank = blockIdx.x & 3;
    int b0 = (blockIdx.x >> 2) * 32;   // batch tile (per cluster)
    int u0 = rank * 32;                // unit tile (per CTA)

    for (int i = tid; i < 128 * 128; i += 512) {
        int row = i >> 7, k = i & 127;
        int grow = ((row >> 5) * 128) + u0 + (row & 31);
        wse[row * WPAD + k] = encw[grow * 128 + k];
        wsd[row * WPAD + k] = dwi[grow * 128 + k] + dwh[grow * 128 + k];
    }
    for (int i = tid; i < 32 * 128; i += 512) hs[i] = 0.f;  // buffer 0 only

    unsigned hs_local = smem_u32(hs);
    unsigned rb[4];
#pragma unroll
    for (int r = 0; r < 4; r++)
        asm("mapa.shared::cluster.u32 %0, %1, %2;" : "=r"(rb[r]) : "r"(hs_local), "r"(r));

    __syncthreads();
    asm volatile("barrier.cluster.arrive.aligned;" ::: "memory");
    asm volatile("barrier.cluster.wait.aligned;" ::: "memory");

    int tj = tid & 31, tr = tid >> 5;  // tr 0..15 -> batch rows tr, tr+16
    int u = u0 + tj;
    float db[4];
#pragma unroll
    for (int a = 0; a < 4; a++) db[a] = decb[a * 128 + u];

    float c[2] = {0.f, 0.f};

    int pread = 0;
    for (int step = 0; step < 42; step++) {
        const float* ws = (step < 32) ? wse : wsd;
        const float* hsr = hs + pread * (32 * 128);

        float xn[2][4];
        if (step < 32) {
#pragma unroll
            for (int b = 0; b < 2; b++) {
                const float* xr = g_xg + ((long)(b0 + tr + 16 * b) * 32 + step) * 512;
#pragma unroll
                for (int a = 0; a < 4; a++) xn[b][a] = xr[a * 128 + u];
            }
        } else {
#pragma unroll
            for (int b = 0; b < 2; b++)
#pragma unroll
                for (int a = 0; a < 4; a++) xn[b][a] = db[a];
        }

        unsigned long long acc2[4][2];
#pragma unroll
        for (int a = 0; a < 4; a++)
#pragma unroll
            for (int b = 0; b < 2; b++) acc2[a][b] = 0ull;

        for (int kk = 0; kk < 32; kk++) {
            ulonglong2 w2v[4], h2v[2];
#pragma unroll
            for (int a = 0; a < 4; a++)
                w2v[a] = *reinterpret_cast<const ulonglong2*>(&ws[(a * 32 + tj) * WPAD + (kk << 2)]);
#pragma unroll
            for (int b = 0; b < 2; b++)
                h2v[b] = *reinterpret_cast<const ulonglong2*>(&hsr[(tr + 16 * b) * 128 + (kk << 2)]);
#pragma unroll
            for (int a = 0; a < 4; a++)
#pragma unroll
                for (int b = 0; b < 2; b++) {
                    fma2(acc2[a][b], w2v[a].x, h2v[b].x);
                    fma2(acc2[a][b], w2v[a].y, h2v[b].y);
                }
        }

        unsigned woff = (unsigned)((1 - pread) * (32 * 128 * 4));
#pragma unroll
        for (int b = 0; b < 2; b++) {
            int rloc = tr + 16 * b;
            float gi = f2sum(acc2[0][b]) + xn[b][0];
            float gf = f2sum(acc2[1][b]) + xn[b][1];
            float gg = f2sum(acc2[2][b]) + xn[b][2];
            float go = f2sum(acc2[3][b]) + xn[b][3];
            float si = 1.f / (1.f + __expf(-gi));
            float sf = 1.f / (1.f + __expf(-gf));
            float so = 1.f / (1.f + __expf(-go));
            float tg = tanhf(gg);
            float cn = sf * c[b] + si * tg;
            c[b] = cn;
            float hn = so * tanhf(cn);
            if (step < 41) {
                unsigned eoff = woff + (unsigned)(rloc * 128 + u) * 4u;
#pragma unroll
                for (int r = 0; r < 4; r++)
                    asm volatile("st.shared::cluster.f32 [%0], %1;"
                                 :: "r"(rb[r] + eoff), "f"(hn) : "memory");
            }
            if (step >= 32) g_hdec[step - 32][(b0 + rloc) * 128 + u] = hn;
        }

        if (step < 41) {
            asm volatile("barrier.cluster.arrive.aligned;" ::: "memory");
            asm volatile("barrier.cluster.wait.aligned;" ::: "memory");
            pread ^= 1;
        }
    }

    asm volatile("barrier.cluster.arrive.aligned;" ::: "memory");
    asm volatile("barrier.cluster.wait.aligned;" ::: "memory");
}

// ---------------- output head ----------------
__global__ void head_kernel(const float* __restrict__ ow, const float* __restrict__ ob,
                            float* __restrict__ out)
{
    __shared__ float hsm[64 * 129];
    __shared__ float wsm[12 * 129];
    __shared__ float bsm[12];
    int tid = threadIdx.x;
    int s = blockIdx.y, b0 = blockIdx.x * 64;
    for (int i = tid; i < 64 * 128; i += 256) {
        int r = i >> 7, k = i & 127;
        hsm[r * 129 + k] = g_hdec[s][(b0 + r) * 128 + k];
    }
    for (int i = tid; i < 12 * 128; i += 256) {
        int r = i / 128, k = i % 128;
        wsm[r * 129 + k] = ow[i];
    }
    if (tid < 12) bsm[tid] = ob[tid];
    __syncthreads();
    for (int it = tid; it < 64 * 12; it += 256) {
        int b = it / 12, v = it % 12;
        float acc = bsm[v];
        for (int k = 0; k < 128; k++) acc += hsm[b * 129 + k] * wsm[v * 129 + k];
        out[(long)(b0 + b) * 120 + s * 12 + v] = acc;
    }
}

// ---------------- launcher ----------------
extern "C" void kernel_launch(void* const* d_in, const int* in_sizes, int n_in,
                              void* d_out, int out_size)
{
    const float* obs    = (const float*)d_in[0];
    const float* c1w    = (const float*)d_in[1];
    const float* c1b    = (const float*)d_in[2];
    const float* c2w    = (const float*)d_in[3];
    const float* c2b    = (const float*)d_in[4];
    const float* fc1w   = (const float*)d_in[5];
    const float* fc1b   = (const float*)d_in[6];
    const float* bn1g   = (const float*)d_in[7];
    const float* bn1b   = (const float*)d_in[8];
    const float* bn1m   = (const float*)d_in[9];
    const float* bn1v   = (const float*)d_in[10];
    const float* fc2w   = (const float*)d_in[11];
    const float* fc2b   = (const float*)d_in[12];
    const float* bn2g   = (const float*)d_in[13];
    const float* bn2b   = (const float*)d_in[14];
    const float* bn2m   = (const float*)d_in[15];
    const float* bn2v   = (const float*)d_in[16];
    const float* encwih = (const float*)d_in[17];
    const float* encwhh = (const float*)d_in[18];
    const float* encb   = (const float*)d_in[19];
    const float* decwih = (const float*)d_in[20];
    const float* decwhh = (const float*)d_in[21];
    const float* decb   = (const float*)d_in[22];
    const float* outw   = (const float*)d_in[23];
    const float* outb   = (const float*)d_in[24];
    float* out = (float*)d_out;

    const int fc_smem    = (128 * WPAD + 64 * WPAD + 64 * 128 * 2) * 4;
    const int xproj_smem = (128 * 64 + 128 * BPAD) * 4;
    const int lstm_smem  = (2 * 128 * WPAD + 2 * 32 * 128) * 4;   // 167936 B
    cudaFuncSetAttribute(fc_kernel, cudaFuncAttributeMaxDynamicSharedMemorySize, fc_smem);
    cudaFuncSetAttribute(xproj_kernel, cudaFuncAttributeMaxDynamicSharedMemorySize, xproj_smem);
    cudaFuncSetAttribute(lstm_persistent, cudaFuncAttributeMaxDynamicSharedMemorySize, lstm_smem);

    cnn_kernel<<<32768 / FPB, 128>>>(obs, c1w, c1b, c2w, c2b);
    fc_kernel<<<512, 256, fc_smem>>>(fc1w, fc1b, bn1g, bn1b, bn1m, bn1v,
                                     fc2w, fc2b, bn2g, bn2b, bn2m, bn2v);
    dim3 xgrid(256, 4);
    xproj_kernel<<<xgrid, 512, xproj_smem>>>(encwih, encb);

    lstm_persistent<<<128, 512, lstm_smem>>>(encwhh, decwih, decwhh, decb);

    dim3 hgrid(16, 10);
    head_kernel<<<hgrid, 256>>>(outw, outb, out);
}

// round 8
// speedup vs baseline: 3.5658x; 1.0581x over previous
#include <cuda_runtime.h>
#include <math.h>

// ---------------- scratch (static device globals; no allocation) ----------------
__device__ float g_cnn[32768 * 128];     // CNN output per frame
__device__ float g_feats[32768 * 64];    // after FC+BN stack
__device__ float g_xg[32768 * 512];      // precomputed x @ enc_w_ih^T + enc_b
__device__ float g_hdec[10][1024 * 128]; // decoder h history for output head

#define WPAD 132   // weight row pad: 132 % 32 == 4 (conflict-free LDS.128 phases)

__device__ __forceinline__ void fma2(unsigned long long& d,
                                     unsigned long long a, unsigned long long b) {
    asm("fma.rn.f32x2 %0, %1, %2, %0;" : "+l"(d) : "l"(a), "l"(b));
}
__device__ __forceinline__ unsigned long long pack2(float v) {
    unsigned long long r;
    asm("mov.b64 %0, {%1, %1};" : "=l"(r) : "f"(v));
    return r;
}
__device__ __forceinline__ float ulo(unsigned long long v) {
    return __uint_as_float((unsigned)(v & 0xffffffffull));
}
__device__ __forceinline__ float uhi(unsigned long long v) {
    return __uint_as_float((unsigned)(v >> 32));
}
__device__ __forceinline__ float f2sum(unsigned long long v) { return ulo(v) + uhi(v); }
__device__ __forceinline__ unsigned smem_u32(const void* p) {
    unsigned a;
    asm("{ .reg .u64 t; cvta.to.shared.u64 t, %1; cvt.u32.u64 %0, t; }" : "=r"(a) : "l"(p));
    return a;
}

// ---------------- CNN: frame-pair packed f32x2 ----------------
// 4 frames per block = 2 frame-pairs packed into f32x2 lanes.
// s_ini row stride = 50 floats (12 x-slots x 4 + 2 pad): py-stride 100 = 4 mod 32
// -> phase-1 patch loads at most ~4-way conflicted (was 10-way with stride 48).
#define FPB 4
#define IRS 50
__global__ void __launch_bounds__(128) cnn_kernel(
    const float* __restrict__ obs,
    const float* __restrict__ w1, const float* __restrict__ b1,
    const float* __restrict__ w2, const float* __restrict__ b2)
{
    __shared__ float s_ini[4 * 12 * IRS];      // [ic][y][x-slot*4+f], zero-pad border
    __shared__ float s_p1i[16 * 7 * 7 * 4];    // [oc][r][c][f], zero-padded border
    __shared__ float s_w1[576];
    __shared__ float s_b1[16];
    __shared__ float s_w2t[144 * 33];          // [ic*9+q][oc] padded 33
    __shared__ float s_b2[32];

    int tid = threadIdx.x; // 128
    for (int i = tid; i < 4 * 12 * IRS; i += 128) s_ini[i] = 0.f;
    for (int i = tid; i < 16 * 49 * 4; i += 128) s_p1i[i] = 0.f;
    for (int i = tid; i < 576; i += 128) s_w1[i] = w1[i];
    if (tid < 16) s_b1[tid] = b1[tid];
    for (int i = tid; i < 4608; i += 128) {
        int oc = i / 144, r = i % 144;
        s_w2t[r * 33 + oc] = w2[i];
    }
    if (tid < 32) s_b2[tid] = b2[tid];
    __syncthreads();

    int f0 = blockIdx.x * FPB;
    for (int i = tid; i < FPB * 400; i += 128) {
        int f = i / 400, rem = i % 400;
        int ic = rem / 100, p = rem % 100, y = p / 10, x = p % 10;
        s_ini[(ic * 12 + y + 1) * IRS + (x + 1) * 4 + f] = obs[(long)f0 * 400 + i];
    }
    __syncthreads();

    // phase 1: conv1 (3x3 SAME, 4->16) + relu + maxpool2.
    if (tid < 100) {
        int fp = tid / 50, rem = tid % 50, ocg = rem / 25, pos = rem % 25;
        int py = pos / 5, px = pos % 5;
        unsigned long long acc2[8][4];
#pragma unroll
        for (int o = 0; o < 8; o++) {
            unsigned long long bp = pack2(s_b1[ocg * 8 + o]);
#pragma unroll
            for (int p = 0; p < 4; p++) acc2[o][p] = bp;
        }
#pragma unroll
        for (int ic = 0; ic < 4; ic++) {
            unsigned long long patch2[4][4];
#pragma unroll
            for (int r = 0; r < 4; r++)
#pragma unroll
                for (int cc = 0; cc < 4; cc++)
                    patch2[r][cc] = *(const unsigned long long*)
                        &s_ini[(ic * 12 + 2 * py + r) * IRS + (2 * px + cc) * 4 + fp * 2];
#pragma unroll
            for (int o = 0; o < 8; o++) {
                int oc = ocg * 8 + o;
#pragma unroll
                for (int ky = 0; ky < 3; ky++)
#pragma unroll
                    for (int kx = 0; kx < 3; kx++) {
                        unsigned long long wp = pack2(s_w1[(oc * 4 + ic) * 9 + ky * 3 + kx]);
                        fma2(acc2[o][0], patch2[ky][kx], wp);
                        fma2(acc2[o][1], patch2[ky][kx + 1], wp);
                        fma2(acc2[o][2], patch2[ky + 1][kx], wp);
                        fma2(acc2[o][3], patch2[ky + 1][kx + 1], wp);
                    }
            }
        }
#pragma unroll
        for (int o = 0; o < 8; o++) {
            int oc = ocg * 8 + o;
            float mlo = fmaxf(fmaxf(ulo(acc2[o][0]), ulo(acc2[o][1])),
                              fmaxf(ulo(acc2[o][2]), ulo(acc2[o][3])));
            float mhi = fmaxf(fmaxf(uhi(acc2[o][0]), uhi(acc2[o][1])),
                              fmaxf(uhi(acc2[o][2]), uhi(acc2[o][3])));
            int base = ((oc * 7 + py + 1) * 7 + px + 1) * 4 + fp * 2;
            s_p1i[base] = fmaxf(mlo, 0.f);
            s_p1i[base + 1] = fmaxf(mhi, 0.f);
        }
    }
    __syncthreads();

    // phase 2: conv2 (3x3 SAME, 16->32) + relu + maxpool2(floor -> 4x4 region).
    // (half, fp, oc): input pairs warp-broadcast LDS.64, weights conflict-free.
    {
        int half = tid >> 6, fp = (tid >> 5) & 1, oc = tid & 31;
        unsigned long long acc2[2][4];
        unsigned long long bp = pack2(s_b2[oc]);
#pragma unroll
        for (int yl = 0; yl < 2; yl++)
#pragma unroll
            for (int x = 0; x < 4; x++) acc2[yl][x] = bp;

        for (int ic = 0; ic < 16; ic++) {
            unsigned long long in2[4][6];
#pragma unroll
            for (int rl = 0; rl < 4; rl++)
#pragma unroll
                for (int cc = 0; cc < 6; cc++)
                    in2[rl][cc] = *(const unsigned long long*)
                        &s_p1i[((ic * 7 + 2 * half + rl) * 7 + cc) * 4 + fp * 2];
#pragma unroll
            for (int ky = 0; ky < 3; ky++)
#pragma unroll
                for (int kx = 0; kx < 3; kx++) {
                    unsigned long long wp = pack2(s_w2t[(ic * 9 + ky * 3 + kx) * 33 + oc]);
#pragma unroll
                    for (int yl = 0; yl < 2; yl++)
#pragma unroll
                        for (int x = 0; x < 4; x++)
                            fma2(acc2[yl][x], in2[yl + ky][x + kx], wp);
                }
        }
#pragma unroll
        for (int px = 0; px < 2; px++) {
            float mlo = fmaxf(fmaxf(ulo(acc2[0][2 * px]), ulo(acc2[0][2 * px + 1])),
                              fmaxf(ulo(acc2[1][2 * px]), ulo(acc2[1][2 * px + 1])));
            float mhi = fmaxf(fmaxf(uhi(acc2[0][2 * px]), uhi(acc2[0][2 * px + 1])),
                              fmaxf(uhi(acc2[1][2 * px]), uhi(acc2[1][2 * px + 1])));
            long fr = f0 + fp * 2;
            g_cnn[fr * 128 + oc * 4 + half * 2 + px] = fmaxf(mlo, 0.f);
            g_cnn[(fr + 1) * 128 + oc * 4 + half * 2 + px] = fmaxf(mhi, 0.f);
        }
    }
}

// ---------------- FC stack: fc1+bn1+relu -> fc2+bn2+relu (f32x2, pad-132) ----------------
__global__ void __launch_bounds__(256) fc_kernel(
    const float* __restrict__ fc1w, const float* __restrict__ fc1b,
    const float* __restrict__ g1, const float* __restrict__ be1,
    const float* __restrict__ m1, const float* __restrict__ v1,
    const float* __restrict__ fc2w, const float* __restrict__ fc2b,
    const float* __restrict__ g2, const float* __restrict__ be2,
    const float* __restrict__ m2, const float* __restrict__ v2)
{
    extern __shared__ float sm[];
    float* w1s = sm;                   // 128 rows x WPAD
    float* w2s = w1s + 128 * WPAD;     // 64 rows x WPAD
    float* xs  = w2s + 64 * WPAD;      // 64 x 128 plain
    float* ms  = xs + 64 * 128;        // 64 x 128 plain

    int tid = threadIdx.x;
    long r0 = (long)blockIdx.x * 64;
    for (int i = tid; i < 128 * 128; i += 256) {
        int row = i >> 7, k = i & 127;
        w1s[row * WPAD + k] = fc1w[i];
    }
    for (int i = tid; i < 64 * 128; i += 256) {
        int row = i >> 7, k = i & 127;
        w2s[row * WPAD + k] = fc2w[i];
    }
    for (int i = tid; i < 64 * 128; i += 256) xs[i] = g_cnn[r0 * 128 + i];
    __syncthreads();

    int tj = tid & 31, tr = tid >> 5;
    {
        unsigned long long acc2[4][8];
#pragma unroll
        for (int a = 0; a < 4; a++)
#pragma unroll
            for (int b = 0; b < 8; b++) acc2[a][b] = 0ull;
        for (int kk = 0; kk < 32; kk++) {
            ulonglong2 w2v[4], h2v[8];
#pragma unroll
            for (int a = 0; a < 4; a++)
                w2v[a] = *reinterpret_cast<const ulonglong2*>(&w1s[(tj + 32 * a) * WPAD + (kk << 2)]);
#pragma unroll
            for (int b = 0; b < 8; b++)
                h2v[b] = *reinterpret_cast<const ulonglong2*>(&xs[(tr * 8 + b) * 128 + (kk << 2)]);
#pragma unroll
            for (int a = 0; a < 4; a++)
#pragma unroll
                for (int b = 0; b < 8; b++) {
                    fma2(acc2[a][b], w2v[a].x, h2v[b].x);
                    fma2(acc2[a][b], w2v[a].y, h2v[b].y);
                }
        }
#pragma unroll
        for (int a = 0; a < 4; a++) {
            int j = tj + 32 * a;
            float s = g1[j] * rsqrtf(v1[j] + 1e-5f);
            float bb = (fc1b[j] - m1[j]) * s + be1[j];
#pragma unroll
            for (int b = 0; b < 8; b++)
                ms[(tr * 8 + b) * 128 + j] = fmaxf(f2sum(acc2[a][b]) * s + bb, 0.f);
        }
    }
    __syncthreads();
    {
        unsigned long long acc2[2][8];
#pragma unroll
        for (int a = 0; a < 2; a++)
#pragma unroll
            for (int b = 0; b < 8; b++) acc2[a][b] = 0ull;
        for (int kk = 0; kk < 32; kk++) {
            ulonglong2 w2v[2], h2v[8];
#pragma unroll
            for (int a = 0; a < 2; a++)
                w2v[a] = *reinterpret_cast<const ulonglong2*>(&w2s[(tj + 32 * a) * WPAD + (kk << 2)]);
#pragma unroll
            for (int b = 0; b < 8; b++)
                h2v[b] = *reinterpret_cast<const ulonglong2*>(&ms[(tr * 8 + b) * 128 + (kk << 2)]);
#pragma unroll
            for (int a = 0; a < 2; a++)
#pragma unroll
                for (int b = 0; b < 8; b++) {
                    fma2(acc2[a][b], w2v[a].x, h2v[b].x);
                    fma2(acc2[a][b], w2v[a].y, h2v[b].y);
                }
        }
#pragma unroll
        for (int a = 0; a < 2; a++) {
            int j = tj + 32 * a;
            float s = g2[j] * rsqrtf(v2[j] + 1e-5f);
            float bb = (fc2b[j] - m2[j]) * s + be2[j];
#pragma unroll
            for (int b = 0; b < 8; b++)
                g_feats[(r0 + tr * 8 + b) * 64 + j] = fmaxf(f2sum(acc2[a][b]) * s + bb, 0.f);
        }
    }
}

// ---------------- encoder x-projection GEMM (f32x2, pad, strided n-cols) ----------------
#define BPAD 68   // 68 % 32 == 4
__global__ void __launch_bounds__(512) xproj_kernel(const float* __restrict__ wih,
                                                    const float* __restrict__ eb)
{
    extern __shared__ float sm[];
    float* As = sm;               // [128][64] plain (m-major)
    float* Bs = sm + 128 * 64;    // [128][BPAD] (j-major, padded)

    int tid = threadIdx.x;
    long r0 = (long)blockIdx.x * 128;
    int j0 = blockIdx.y * 128;

    for (int i = tid; i < 128 * 64; i += 512) As[i] = g_feats[r0 * 64 + i];
    for (int i = tid; i < 128 * 64; i += 512) {
        int j = i >> 6, k = i & 63;
        Bs[j * BPAD + k] = wih[(long)(j0 + j) * 64 + k];
    }
    __syncthreads();

    int tx = tid & 15, ty = tid >> 4; // ty 0..31
    int m0 = ty * 4;

    unsigned long long acc2[4][8];
#pragma unroll
    for (int i = 0; i < 4; i++)
#pragma unroll
        for (int j = 0; j < 8; j++) acc2[i][j] = 0ull;

    for (int kk = 0; kk < 16; kk++) {
        ulonglong2 a2[4], b2[8];
#pragma unroll
        for (int i = 0; i < 4; i++)
            a2[i] = *reinterpret_cast<const ulonglong2*>(&As[(m0 + i) * 64 + (kk << 2)]);
#pragma unroll
        for (int j = 0; j < 8; j++)
            b2[j] = *reinterpret_cast<const ulonglong2*>(&Bs[(tx + 16 * j) * BPAD + (kk << 2)]);
#pragma unroll
        for (int i = 0; i < 4; i++)
#pragma unroll
            for (int j = 0; j < 8; j++) {
                fma2(acc2[i][j], a2[i].x, b2[j].x);
                fma2(acc2[i][j], a2[i].y, b2[j].y);
            }
    }

#pragma unroll
    for (int i = 0; i < 4; i++) {
        long row = (r0 + m0 + i) * 512 + j0;
#pragma unroll
        for (int j = 0; j < 8; j++) {
            int col = tx + 16 * j;
            g_xg[row + col] = f2sum(acc2[i][j]) + eb[j0 + col];
        }
    }
}

// ---------------- persistent LSTM: clusters of 4, DSMEM h, pipelined barrier ----------
// grid 128 = 32 clusters x 4 CTAs (u-tiles). 8 warps/CTA, 4 batch rows/warp.
// Next-step xg prefetch issued between barrier arrive and wait.
__global__ void __launch_bounds__(256, 1) __cluster_dims__(4, 1, 1)
lstm_persistent(const float* __restrict__ encw, const float* __restrict__ dwi,
                const float* __restrict__ dwh, const float* __restrict__ decb)
{
    extern __shared__ float sm[];
    float* wse = sm;                   // 128 rows x WPAD encoder slice
    float* wsd = sm + 128 * WPAD;      // 128 rows x WPAD decoder slice (ih+hh)
    float* hs  = sm + 2 * 128 * WPAD;  // 2 buffers x 32 x 128

    int tid = threadIdx.x;
    unsigned rank = blockIdx.x & 3;
    int b0 = (blockIdx.x >> 2) * 32;   // batch tile (per cluster)
    int u0 = rank * 32;                // unit tile (per CTA)

    for (int i = tid; i < 128 * 128; i += 256) {
        int row = i >> 7, k = i & 127;
        int grow = ((row >> 5) * 128) + u0 + (row & 31);
        wse[row * WPAD + k] = encw[grow * 128 + k];
        wsd[row * WPAD + k] = dwi[grow * 128 + k] + dwh[grow * 128 + k];
    }
    for (int i = tid; i < 32 * 128; i += 256) hs[i] = 0.f;  // buffer 0 only

    unsigned hs_local = smem_u32(hs);
    unsigned rb[4];
#pragma unroll
    for (int r = 0; r < 4; r++)
        asm("mapa.shared::cluster.u32 %0, %1, %2;" : "=r"(rb[r]) : "r"(hs_local), "r"(r));

    __syncthreads();
    asm volatile("barrier.cluster.arrive.aligned;" ::: "memory");
    asm volatile("barrier.cluster.wait.aligned;" ::: "memory");

    int tj = tid & 31, tr = tid >> 5;  // 8 warps; batch rows tr + 8b
    int u = u0 + tj;
    float db[4];
#pragma unroll
    for (int a = 0; a < 4; a++) db[a] = decb[a * 128 + u];

    float c[4] = {0.f, 0.f, 0.f, 0.f};

    // prefetch step 0 gate inputs
    float xn[4][4];
#pragma unroll
    for (int b = 0; b < 4; b++) {
        const float* xr = g_xg + ((long)(b0 + tr + 8 * b) * 32 + 0) * 512;
#pragma unroll
        for (int a = 0; a < 4; a++) xn[b][a] = xr[a * 128 + u];
    }

    int pread = 0;
    for (int step = 0; step < 42; step++) {
        const float* ws = (step < 32) ? wse : wsd;
        const float* hsr = hs + pread * (32 * 128);

        unsigned long long acc2[4][4];
#pragma unroll
        for (int a = 0; a < 4; a++)
#pragma unroll
            for (int b = 0; b < 4; b++) acc2[a][b] = 0ull;

        for (int kk = 0; kk < 32; kk++) {
            ulonglong2 w2v[4], h2v[4];
#pragma unroll
            for (int a = 0; a < 4; a++)
                w2v[a] = *reinterpret_cast<const ulonglong2*>(&ws[(a * 32 + tj) * WPAD + (kk << 2)]);
#pragma unroll
            for (int b = 0; b < 4; b++)
                h2v[b] = *reinterpret_cast<const ulonglong2*>(&hsr[(tr + 8 * b) * 128 + (kk << 2)]);
#pragma unroll
            for (int a = 0; a < 4; a++)
#pragma unroll
                for (int b = 0; b < 4; b++) {
                    fma2(acc2[a][b], w2v[a].x, h2v[b].x);
                    fma2(acc2[a][b], w2v[a].y, h2v[b].y);
                }
        }

        unsigned woff = (unsigned)((1 - pread) * (32 * 128 * 4));
#pragma unroll
        for (int b = 0; b < 4; b++) {
            int rloc = tr + 8 * b;
            float gi = f2sum(acc2[0][b]) + xn[b][0];
            float gf = f2sum(acc2[1][b]) + xn[b][1];
            float gg = f2sum(acc2[2][b]) + xn[b][2];
            float go = f2sum(acc2[3][b]) + xn[b][3];
            float si = 1.f / (1.f + __expf(-gi));
            float sf = 1.f / (1.f + __expf(-gf));
            float so = 1.f / (1.f + __expf(-go));
            float tg = tanhf(gg);
            float cn = sf * c[b] + si * tg;
            c[b] = cn;
            float hn = so * tanhf(cn);
            if (step < 41) {
                unsigned eoff = woff + (unsigned)(rloc * 128 + u) * 4u;
#pragma unroll
                for (int r = 0; r < 4; r++)
                    asm volatile("st.shared::cluster.f32 [%0], %1;"
                                 :: "r"(rb[r] + eoff), "f"(hn) : "memory");
            }
            if (step >= 32) g_hdec[step - 32][(b0 + rloc) * 128 + u] = hn;
        }

        if (step < 41) {
            // release our h stores to the cluster, then prefetch next step's
            // gate inputs while peers arrive.
            asm volatile("barrier.cluster.arrive.aligned;" ::: "memory");
            if (step + 1 < 32) {
#pragma unroll
                for (int b = 0; b < 4; b++) {
                    const float* xr = g_xg + ((long)(b0 + tr + 8 * b) * 32 + (step + 1)) * 512;
#pragma unroll
                    for (int a = 0; a < 4; a++) xn[b][a] = xr[a * 128 + u];
                }
            } else {
#pragma unroll
                for (int b = 0; b < 4; b++)
#pragma unroll
                    for (int a = 0; a < 4; a++) xn[b][a] = db[a];
            }
            asm volatile("barrier.cluster.wait.aligned;" ::: "memory");
            pread ^= 1;
        }
    }

    asm volatile("barrier.cluster.arrive.aligned;" ::: "memory");
    asm volatile("barrier.cluster.wait.aligned;" ::: "memory");
}

// ---------------- output head ----------------
__global__ void head_kernel(const float* __restrict__ ow, const float* __restrict__ ob,
                            float* __restrict__ out)
{
    __shared__ float hsm[64 * 129];
    __shared__ float wsm[12 * 129];
    __shared__ float bsm[12];
    int tid = threadIdx.x;
    int s = blockIdx.y, b0 = blockIdx.x * 64;
    for (int i = tid; i < 64 * 128; i += 256) {
        int r = i >> 7, k = i & 127;
        hsm[r * 129 + k] = g_hdec[s][(b0 + r) * 128 + k];
    }
    for (int i = tid; i < 12 * 128; i += 256) {
        int r = i / 128, k = i % 128;
        wsm[r * 129 + k] = ow[i];
    }
    if (tid < 12) bsm[tid] = ob[tid];
    __syncthreads();
    for (int it = tid; it < 64 * 12; it += 256) {
        int b = it / 12, v = it % 12;
        float acc = bsm[v];
        for (int k = 0; k < 128; k++) acc += hsm[b * 129 + k] * wsm[v * 129 + k];
        out[(long)(b0 + b) * 120 + s * 12 + v] = acc;
    }
}

// ---------------- launcher ----------------
extern "C" void kernel_launch(void* const* d_in, const int* in_sizes, int n_in,
                              void* d_out, int out_size)
{
    const float* obs    = (const float*)d_in[0];
    const float* c1w    = (const float*)d_in[1];
    const float* c1b    = (const float*)d_in[2];
    const float* c2w    = (const float*)d_in[3];
    const float* c2b    = (const float*)d_in[4];
    const float* fc1w   = (const float*)d_in[5];
    const float* fc1b   = (const float*)d_in[6];
    const float* bn1g   = (const float*)d_in[7];
    const float* bn1b   = (const float*)d_in[8];
    const float* bn1m   = (const float*)d_in[9];
    const float* bn1v   = (const float*)d_in[10];
    const float* fc2w   = (const float*)d_in[11];
    const float* fc2b   = (const float*)d_in[12];
    const float* bn2g   = (const float*)d_in[13];
    const float* bn2b   = (const float*)d_in[14];
    const float* bn2m   = (const float*)d_in[15];
    const float* bn2v   = (const float*)d_in[16];
    const float* encwih = (const float*)d_in[17];
    const float* encwhh = (const float*)d_in[18];
    const float* encb   = (const float*)d_in[19];
    const float* decwih = (const float*)d_in[20];
    const float* decwhh = (const float*)d_in[21];
    const float* decb   = (const float*)d_in[22];
    const float* outw   = (const float*)d_in[23];
    const float* outb   = (const float*)d_in[24];
    float* out = (float*)d_out;

    const int fc_smem    = (128 * WPAD + 64 * WPAD + 64 * 128 * 2) * 4;
    const int xproj_smem = (128 * 64 + 128 * BPAD) * 4;
    const int lstm_smem  = (2 * 128 * WPAD + 2 * 32 * 128) * 4;   // 167936 B
    cudaFuncSetAttribute(fc_kernel, cudaFuncAttributeMaxDynamicSharedMemorySize, fc_smem);
    cudaFuncSetAttribute(xproj_kernel, cudaFuncAttributeMaxDynamicSharedMemorySize, xproj_smem);
    cudaFuncSetAttribute(lstm_persistent, cudaFuncAttributeMaxDynamicSharedMemorySize, lstm_smem);

    cnn_kernel<<<32768 / FPB, 128>>>(obs, c1w, c1b, c2w, c2b);
    fc_kernel<<<512, 256, fc_smem>>>(fc1w, fc1b, bn1g, bn1b, bn1m, bn1v,
                                     fc2w, fc2b, bn2g, bn2b, bn2m, bn2v);
    dim3 xgrid(256, 4);
    xproj_kernel<<<xgrid, 512, xproj_smem>>>(encwih, encb);

    lstm_persistent<<<128, 256, lstm_smem>>>(encwhh, decwih, decwhh, decb);

    dim3 hgrid(16, 10);
    head_kernel<<<hgrid, 256>>>(outw, outb, out);
}

// round 9
// speedup vs baseline: 4.0119x; 1.1251x over previous
#include <cuda_runtime.h>
#include <math.h>

// ---------------- scratch (static device globals; no allocation) ----------------
__device__ float g_cnn[32768 * 128];     // CNN output per frame
__device__ float g_feats[32768 * 64];    // after FC+BN stack
__device__ float g_xg[32768 * 512];      // precomputed x @ enc_w_ih^T + enc_b
__device__ float g_hdec[10][1024 * 128]; // decoder h history for output head

#define WPAD 132   // weight row pad: 132 % 32 == 4 (conflict-free LDS.128 phases)

__device__ __forceinline__ void fma2(unsigned long long& d,
                                     unsigned long long a, unsigned long long b) {
    asm("fma.rn.f32x2 %0, %1, %2, %0;" : "+l"(d) : "l"(a), "l"(b));
}
__device__ __forceinline__ unsigned long long pack2(float v) {
    unsigned long long r;
    asm("mov.b64 %0, {%1, %1};" : "=l"(r) : "f"(v));
    return r;
}
__device__ __forceinline__ unsigned long long packab(float a, float b) {
    unsigned long long r;
    asm("mov.b64 %0, {%1, %2};" : "=l"(r) : "f"(a), "f"(b));
    return r;
}
__device__ __forceinline__ float ulo(unsigned long long v) {
    return __uint_as_float((unsigned)(v & 0xffffffffull));
}
__device__ __forceinline__ float uhi(unsigned long long v) {
    return __uint_as_float((unsigned)(v >> 32));
}
__device__ __forceinline__ float f2sum(unsigned long long v) { return ulo(v) + uhi(v); }
__device__ __forceinline__ unsigned smem_u32(const void* p) {
    unsigned a;
    asm("{ .reg .u64 t; cvta.to.shared.u64 t, %1; cvt.u32.u64 %0, t; }" : "=r"(a) : "l"(p));
    return a;
}

// ---------------- CNN: persistent, frame-pair packed f32x2 ----------------
// 4 frames per iteration (2 frame-pairs packed into f32x2 lanes), weights staged once.
// s_p1i layout: [oc][r][fp][slot16], slot = c*2 + f_in_pair -> 16B-aligned c-pairs.
#define FPB 4
#define IRS 50
#define CNN_GRID 592
__global__ void __launch_bounds__(128) cnn_kernel(
    const float* __restrict__ obs,
    const float* __restrict__ w1, const float* __restrict__ b1,
    const float* __restrict__ w2, const float* __restrict__ b2)
{
    __shared__ float s_ini[4 * 12 * IRS];      // [ic][y][x-slot*4+f], zero-pad border
    __shared__ float s_p1i[16 * 7 * 2 * 16];   // [oc][r][fp][c*2+f1], zero-pad
    __shared__ float s_w1[576];
    __shared__ float s_b1[16];
    __shared__ float s_w2t[144 * 33];          // [ic*9+q][oc] padded 33
    __shared__ float s_b2[32];

    int tid = threadIdx.x; // 128
    for (int i = tid; i < 4 * 12 * IRS; i += 128) s_ini[i] = 0.f;
    for (int i = tid; i < 16 * 7 * 2 * 16; i += 128) s_p1i[i] = 0.f;
    for (int i = tid; i < 576; i += 128) s_w1[i] = w1[i];
    if (tid < 16) s_b1[tid] = b1[tid];
    for (int i = tid; i < 4608; i += 128) {
        int oc = i / 144, r = i % 144;
        s_w2t[r * 33 + oc] = w2[i];
    }
    if (tid < 32) s_b2[tid] = b2[tid];
    __syncthreads();

    for (long f0 = (long)blockIdx.x * FPB; f0 < 32768; f0 += (long)gridDim.x * FPB) {
        // stage input (interior only; borders stay zero)
        for (int i = tid; i < FPB * 400; i += 128) {
            int f = i / 400, rem = i % 400;
            int ic = rem / 100, p = rem % 100, y = p / 10, x = p % 10;
            s_ini[(ic * 12 + y + 1) * IRS + (x + 1) * 4 + f] = obs[f0 * 400 + i];
        }
        __syncthreads();

        // phase 1: conv1 (3x3 SAME, 4->16) + relu + maxpool2 -> s_p1i interior
        if (tid < 100) {
            int fp = tid / 50, rem = tid % 50, ocg = rem / 25, pos = rem % 25;
            int py = pos / 5, px = pos % 5;
            unsigned long long acc2[8][4];
#pragma unroll
            for (int o = 0; o < 8; o++) {
                unsigned long long bp = pack2(s_b1[ocg * 8 + o]);
#pragma unroll
                for (int p = 0; p < 4; p++) acc2[o][p] = bp;
            }
#pragma unroll
            for (int ic = 0; ic < 4; ic++) {
                unsigned long long patch2[4][4];
#pragma unroll
                for (int r = 0; r < 4; r++)
#pragma unroll
                    for (int cc = 0; cc < 4; cc++)
                        patch2[r][cc] = *(const unsigned long long*)
                            &s_ini[(ic * 12 + 2 * py + r) * IRS + (2 * px + cc) * 4 + fp * 2];
#pragma unroll
                for (int o = 0; o < 8; o++) {
                    int oc = ocg * 8 + o;
#pragma unroll
                    for (int ky = 0; ky < 3; ky++)
#pragma unroll
                        for (int kx = 0; kx < 3; kx++) {
                            unsigned long long wp = pack2(s_w1[(oc * 4 + ic) * 9 + ky * 3 + kx]);
                            fma2(acc2[o][0], patch2[ky][kx], wp);
                            fma2(acc2[o][1], patch2[ky][kx + 1], wp);
                            fma2(acc2[o][2], patch2[ky + 1][kx], wp);
                            fma2(acc2[o][3], patch2[ky + 1][kx + 1], wp);
                        }
                }
            }
#pragma unroll
            for (int o = 0; o < 8; o++) {
                int oc = ocg * 8 + o;
                float mlo = fmaxf(fmaxf(ulo(acc2[o][0]), ulo(acc2[o][1])),
                                  fmaxf(ulo(acc2[o][2]), ulo(acc2[o][3])));
                float mhi = fmaxf(fmaxf(uhi(acc2[o][0]), uhi(acc2[o][1])),
                                  fmaxf(uhi(acc2[o][2]), uhi(acc2[o][3])));
                unsigned long long pk = packab(fmaxf(mlo, 0.f), fmaxf(mhi, 0.f));
                int idx = ((oc * 7 + py + 1) * 2 + fp) * 16 + (px + 1) * 2;
                *(unsigned long long*)&s_p1i[idx] = pk;
            }
        }
        __syncthreads();

        // phase 2: conv2 (3x3 SAME, 16->32) + relu + maxpool2 (floor -> 4x4).
        {
            int half = tid >> 6, fp = (tid >> 5) & 1, oc = tid & 31;
            unsigned long long acc2[2][4];
            unsigned long long bp = pack2(s_b2[oc]);
#pragma unroll
            for (int yl = 0; yl < 2; yl++)
#pragma unroll
                for (int x = 0; x < 4; x++) acc2[yl][x] = bp;

            for (int ic = 0; ic < 16; ic++) {
                unsigned long long in2[4][6];
#pragma unroll
                for (int rl = 0; rl < 4; rl++)
#pragma unroll
                    for (int cp = 0; cp < 3; cp++) {
                        ulonglong2 v = *(const ulonglong2*)
                            &s_p1i[((ic * 7 + 2 * half + rl) * 2 + fp) * 16 + cp * 4];
                        in2[rl][2 * cp] = v.x;
                        in2[rl][2 * cp + 1] = v.y;
                    }
#pragma unroll
                for (int ky = 0; ky < 3; ky++)
#pragma unroll
                    for (int kx = 0; kx < 3; kx++) {
                        unsigned long long wp = pack2(s_w2t[(ic * 9 + ky * 3 + kx) * 33 + oc]);
#pragma unroll
                        for (int yl = 0; yl < 2; yl++)
#pragma unroll
                            for (int x = 0; x < 4; x++)
                                fma2(acc2[yl][x], in2[yl + ky][x + kx], wp);
                    }
            }
#pragma unroll
            for (int px = 0; px < 2; px++) {
                float mlo = fmaxf(fmaxf(ulo(acc2[0][2 * px]), ulo(acc2[0][2 * px + 1])),
                                  fmaxf(ulo(acc2[1][2 * px]), ulo(acc2[1][2 * px + 1])));
                float mhi = fmaxf(fmaxf(uhi(acc2[0][2 * px]), uhi(acc2[0][2 * px + 1])),
                                  fmaxf(uhi(acc2[1][2 * px]), uhi(acc2[1][2 * px + 1])));
                long fr = f0 + fp * 2;
                g_cnn[fr * 128 + oc * 4 + half * 2 + px] = fmaxf(mlo, 0.f);
                g_cnn[(fr + 1) * 128 + oc * 4 + half * 2 + px] = fmaxf(mhi, 0.f);
            }
        }
        __syncthreads();   // protect s_ini/s_p1i rewrite next iteration
    }
}

// ---------------- FC stack: persistent; fc1+bn1+relu -> fc2+bn2+relu ----------------
#define FC_GRID 148
__global__ void __launch_bounds__(256) fc_kernel(
    const float* __restrict__ fc1w, const float* __restrict__ fc1b,
    const float* __restrict__ g1, const float* __restrict__ be1,
    const float* __restrict__ m1, const float* __restrict__ v1,
    const float* __restrict__ fc2w, const float* __restrict__ fc2b,
    const float* __restrict__ g2, const float* __restrict__ be2,
    const float* __restrict__ m2, const float* __restrict__ v2)
{
    extern __shared__ float sm[];
    float* w1s = sm;                   // 128 rows x WPAD
    float* w2s = w1s + 128 * WPAD;     // 64 rows x WPAD
    float* xs  = w2s + 64 * WPAD;      // 64 x 128 plain
    float* ms  = xs + 64 * 128;        // 64 x 128 plain

    int tid = threadIdx.x;
    for (int i = tid; i < 128 * 128; i += 256) {
        int row = i >> 7, k = i & 127;
        w1s[row * WPAD + k] = fc1w[i];
    }
    for (int i = tid; i < 64 * 128; i += 256) {
        int row = i >> 7, k = i & 127;
        w2s[row * WPAD + k] = fc2w[i];
    }
    int tj = tid & 31, tr = tid >> 5;
    // bn scale/shift (per thread's 4 / 2 output cols)
    float s1[4], bb1[4], s2[2], bb2[2];
#pragma unroll
    for (int a = 0; a < 4; a++) {
        int j = tj + 32 * a;
        s1[a] = g1[j] * rsqrtf(v1[j] + 1e-5f);
        bb1[a] = (fc1b[j] - m1[j]) * s1[a] + be1[j];
    }
#pragma unroll
    for (int a = 0; a < 2; a++) {
        int j = tj + 32 * a;
        s2[a] = g2[j] * rsqrtf(v2[j] + 1e-5f);
        bb2[a] = (fc2b[j] - m2[j]) * s2[a] + be2[j];
    }

    for (long t = blockIdx.x; t < 512; t += gridDim.x) {
        long r0 = t * 64;
        for (int i = tid; i < 64 * 128; i += 256) xs[i] = g_cnn[r0 * 128 + i];
        __syncthreads();
        {
            unsigned long long acc2[4][8];
#pragma unroll
            for (int a = 0; a < 4; a++)
#pragma unroll
                for (int b = 0; b < 8; b++) acc2[a][b] = 0ull;
            for (int kk = 0; kk < 32; kk++) {
                ulonglong2 w2v[4], h2v[8];
#pragma unroll
                for (int a = 0; a < 4; a++)
                    w2v[a] = *reinterpret_cast<const ulonglong2*>(&w1s[(tj + 32 * a) * WPAD + (kk << 2)]);
#pragma unroll
                for (int b = 0; b < 8; b++)
                    h2v[b] = *reinterpret_cast<const ulonglong2*>(&xs[(tr * 8 + b) * 128 + (kk << 2)]);
#pragma unroll
                for (int a = 0; a < 4; a++)
#pragma unroll
                    for (int b = 0; b < 8; b++) {
                        fma2(acc2[a][b], w2v[a].x, h2v[b].x);
                        fma2(acc2[a][b], w2v[a].y, h2v[b].y);
                    }
            }
#pragma unroll
            for (int a = 0; a < 4; a++) {
                int j = tj + 32 * a;
#pragma unroll
                for (int b = 0; b < 8; b++)
                    ms[(tr * 8 + b) * 128 + j] = fmaxf(f2sum(acc2[a][b]) * s1[a] + bb1[a], 0.f);
            }
        }
        __syncthreads();
        {
            unsigned long long acc2[2][8];
#pragma unroll
            for (int a = 0; a < 2; a++)
#pragma unroll
                for (int b = 0; b < 8; b++) acc2[a][b] = 0ull;
            for (int kk = 0; kk < 32; kk++) {
                ulonglong2 w2v[2], h2v[8];
#pragma unroll
                for (int a = 0; a < 2; a++)
                    w2v[a] = *reinterpret_cast<const ulonglong2*>(&w2s[(tj + 32 * a) * WPAD + (kk << 2)]);
#pragma unroll
                for (int b = 0; b < 8; b++)
                    h2v[b] = *reinterpret_cast<const ulonglong2*>(&ms[(tr * 8 + b) * 128 + (kk << 2)]);
#pragma unroll
                for (int a = 0; a < 2; a++)
#pragma unroll
                    for (int b = 0; b < 8; b++) {
                        fma2(acc2[a][b], w2v[a].x, h2v[b].x);
                        fma2(acc2[a][b], w2v[a].y, h2v[b].y);
                    }
            }
#pragma unroll
            for (int a = 0; a < 2; a++) {
                int j = tj + 32 * a;
#pragma unroll
                for (int b = 0; b < 8; b++)
                    g_feats[(r0 + tr * 8 + b) * 64 + j] = fmaxf(f2sum(acc2[a][b]) * s2[a] + bb2[a], 0.f);
            }
        }
        __syncthreads();   // ms/xs reused next tile
    }
}

// ---------------- encoder x-projection GEMM: persistent, j-panel staged once --------
#define BPAD 68   // 68 % 32 == 4
#define XP_GROUPS 74
__global__ void __launch_bounds__(512) xproj_kernel(const float* __restrict__ wih,
                                                    const float* __restrict__ eb)
{
    extern __shared__ float sm[];
    float* As = sm;               // [128][64] plain (m-major)
    float* Bs = sm + 128 * 64;    // [128][BPAD] (j-major, padded)

    int tid = threadIdx.x;
    int j0 = (blockIdx.x & 3) * 128;
    int grp = blockIdx.x >> 2;    // 0..73

    for (int i = tid; i < 128 * 64; i += 512) {
        int j = i >> 6, k = i & 63;
        Bs[j * BPAD + k] = wih[(long)(j0 + j) * 64 + k];
    }

    int tx = tid & 15, ty = tid >> 4; // ty 0..31
    int m0 = ty * 4;
    float ebv[8];
#pragma unroll
    for (int j = 0; j < 8; j++) ebv[j] = eb[j0 + tx + 16 * j];

    for (int t = grp; t < 256; t += XP_GROUPS) {
        long r0 = (long)t * 128;
        for (int i = tid; i < 128 * 64; i += 512) As[i] = g_feats[r0 * 64 + i];
        __syncthreads();

        unsigned long long acc2[4][8];
#pragma unroll
        for (int i = 0; i < 4; i++)
#pragma unroll
            for (int j = 0; j < 8; j++) acc2[i][j] = 0ull;

        for (int kk = 0; kk < 16; kk++) {
            ulonglong2 a2[4], b2[8];
#pragma unroll
            for (int i = 0; i < 4; i++)
                a2[i] = *reinterpret_cast<const ulonglong2*>(&As[(m0 + i) * 64 + (kk << 2)]);
#pragma unroll
            for (int j = 0; j < 8; j++)
                b2[j] = *reinterpret_cast<const ulonglong2*>(&Bs[(tx + 16 * j) * BPAD + (kk << 2)]);
#pragma unroll
            for (int i = 0; i < 4; i++)
#pragma unroll
                for (int j = 0; j < 8; j++) {
                    fma2(acc2[i][j], a2[i].x, b2[j].x);
                    fma2(acc2[i][j], a2[i].y, b2[j].y);
                }
        }

#pragma unroll
        for (int i = 0; i < 4; i++) {
            long row = (r0 + m0 + i) * 512 + j0;
#pragma unroll
            for (int j = 0; j < 8; j++)
                g_xg[row + tx + 16 * j] = f2sum(acc2[i][j]) + ebv[j];
        }
        __syncthreads();   // As reused next tile
    }
}

// ---------------- persistent LSTM: clusters of 4, DSMEM h, pipelined barrier ----------
__global__ void __launch_bounds__(256, 1) __cluster_dims__(4, 1, 1)
lstm_persistent(const float* __restrict__ encw, const float* __restrict__ dwi,
                const float* __restrict__ dwh, const float* __restrict__ decb)
{
    extern __shared__ float sm[];
    float* wse = sm;                   // 128 rows x WPAD encoder slice
    float* wsd = sm + 128 * WPAD;      // 128 rows x WPAD decoder slice (ih+hh)
    float* hs  = sm + 2 * 128 * WPAD;  // 2 buffers x 32 x 128

    int tid = threadIdx.x;
    unsigned rank = blockIdx.x & 3;
    int b0 = (blockIdx.x >> 2) * 32;
    int u0 = rank * 32;

    for (int i = tid; i < 128 * 128; i += 256) {
        int row = i >> 7, k = i & 127;
        int grow = ((row >> 5) * 128) + u0 + (row & 31);
        wse[row * WPAD + k] = encw[grow * 128 + k];
        wsd[row * WPAD + k] = dwi[grow * 128 + k] + dwh[grow * 128 + k];
    }
    for (int i = tid; i < 32 * 128; i += 256) hs[i] = 0.f;

    unsigned hs_local = smem_u32(hs);
    unsigned rb[4];
#pragma unroll
    for (int r = 0; r < 4; r++)
        asm("mapa.shared::cluster.u32 %0, %1, %2;" : "=r"(rb[r]) : "r"(hs_local), "r"(r));

    __syncthreads();
    asm volatile("barrier.cluster.arrive.aligned;" ::: "memory");
    asm volatile("barrier.cluster.wait.aligned;" ::: "memory");

    int tj = tid & 31, tr = tid >> 5;
    int u = u0 + tj;
    float db[4];
#pragma unroll
    for (int a = 0; a < 4; a++) db[a] = decb[a * 128 + u];

    float c[4] = {0.f, 0.f, 0.f, 0.f};

    float xn[4][4];
#pragma unroll
    for (int b = 0; b < 4; b++) {
        const float* xr = g_xg + ((long)(b0 + tr + 8 * b) * 32 + 0) * 512;
#pragma unroll
        for (int a = 0; a < 4; a++) xn[b][a] = xr[a * 128 + u];
    }

    int pread = 0;
    for (int step = 0; step < 42; step++) {
        const float* ws = (step < 32) ? wse : wsd;
        const float* hsr = hs + pread * (32 * 128);

        unsigned long long acc2[4][4];
#pragma unroll
        for (int a = 0; a < 4; a++)
#pragma unroll
            for (int b = 0; b < 4; b++) acc2[a][b] = 0ull;

        for (int kk = 0; kk < 32; kk++) {
            ulonglong2 w2v[4], h2v[4];
#pragma unroll
            for (int a = 0; a < 4; a++)
                w2v[a] = *reinterpret_cast<const ulonglong2*>(&ws[(a * 32 + tj) * WPAD + (kk << 2)]);
#pragma unroll
            for (int b = 0; b < 4; b++)
                h2v[b] = *reinterpret_cast<const ulonglong2*>(&hsr[(tr + 8 * b) * 128 + (kk << 2)]);
#pragma unroll
            for (int a = 0; a < 4; a++)
#pragma unroll
                for (int b = 0; b < 4; b++) {
                    fma2(acc2[a][b], w2v[a].x, h2v[b].x);
                    fma2(acc2[a][b], w2v[a].y, h2v[b].y);
                }
        }

        unsigned woff = (unsigned)((1 - pread) * (32 * 128 * 4));
#pragma unroll
        for (int b = 0; b < 4; b++) {
            int rloc = tr + 8 * b;
            float gi = f2sum(acc2[0][b]) + xn[b][0];
            float gf = f2sum(acc2[1][b]) + xn[b][1];
            float gg = f2sum(acc2[2][b]) + xn[b][2];
            float go = f2sum(acc2[3][b]) + xn[b][3];
            float si = 1.f / (1.f + __expf(-gi));
            float sf = 1.f / (1.f + __expf(-gf));
            float so = 1.f / (1.f + __expf(-go));
            float tg = tanhf(gg);
            float cn = sf * c[b] + si * tg;
            c[b] = cn;
            float hn = so * tanhf(cn);
            if (step < 41) {
                unsigned eoff = woff + (unsigned)(rloc * 128 + u) * 4u;
#pragma unroll
                for (int r = 0; r < 4; r++)
                    asm volatile("st.shared::cluster.f32 [%0], %1;"
                                 :: "r"(rb[r] + eoff), "f"(hn) : "memory");
            }
            if (step >= 32) g_hdec[step - 32][(b0 + rloc) * 128 + u] = hn;
        }

        if (step < 41) {
            asm volatile("barrier.cluster.arrive.aligned;" ::: "memory");
            if (step + 1 < 32) {
#pragma unroll
                for (int b = 0; b < 4; b++) {
                    const float* xr = g_xg + ((long)(b0 + tr + 8 * b) * 32 + (step + 1)) * 512;
#pragma unroll
                    for (int a = 0; a < 4; a++) xn[b][a] = xr[a * 128 + u];
                }
            } else {
#pragma unroll
                for (int b = 0; b < 4; b++)
#pragma unroll
                    for (int a = 0; a < 4; a++) xn[b][a] = db[a];
            }
            asm volatile("barrier.cluster.wait.aligned;" ::: "memory");
            pread ^= 1;
        }
    }

    asm volatile("barrier.cluster.arrive.aligned;" ::: "memory");
    asm volatile("barrier.cluster.wait.aligned;" ::: "memory");
}

// ---------------- output head ----------------
__global__ void head_kernel(const float* __restrict__ ow, const float* __restrict__ ob,
                            float* __restrict__ out)
{
    __shared__ float hsm[64 * 129];
    __shared__ float wsm[12 * 129];
    __shared__ float bsm[12];
    int tid = threadIdx.x;
    int s = blockIdx.y, b0 = blockIdx.x * 64;
    for (int i = tid; i < 64 * 128; i += 256) {
        int r = i >> 7, k = i & 127;
        hsm[r * 129 + k] = g_hdec[s][(b0 + r) * 128 + k];
    }
    for (int i = tid; i < 12 * 128; i += 256) {
        int r = i / 128, k = i % 128;
        wsm[r * 129 + k] = ow[i];
    }
    if (tid < 12) bsm[tid] = ob[tid];
    __syncthreads();
    for (int it = tid; it < 64 * 12; it += 256) {
        int b = it / 12, v = it % 12;
        float acc = bsm[v];
        for (int k = 0; k < 128; k++) acc += hsm[b * 129 + k] * wsm[v * 129 + k];
        out[(long)(b0 + b) * 120 + s * 12 + v] = acc;
    }
}

// ---------------- launcher ----------------
extern "C" void kernel_launch(void* const* d_in, const int* in_sizes, int n_in,
                              void* d_out, int out_size)
{
    const float* obs    = (const float*)d_in[0];
    const float* c1w    = (const float*)d_in[1];
    const float* c1b    = (const float*)d_in[2];
    const float* c2w    = (const float*)d_in[3];
    const float* c2b    = (const float*)d_in[4];
    const float* fc1w   = (const float*)d_in[5];
    const float* fc1b   = (const float*)d_in[6];
    const float* bn1g   = (const float*)d_in[7];
    const float* bn1b   = (const float*)d_in[8];
    const float* bn1m   = (const float*)d_in[9];
    const float* bn1v   = (const float*)d_in[10];
    const float* fc2w   = (const float*)d_in[11];
    const float* fc2b   = (const float*)d_in[12];
    const float* bn2g   = (const float*)d_in[13];
    const float* bn2b   = (const float*)d_in[14];
    const float* bn2m   = (const float*)d_in[15];
    const float* bn2v   = (const float*)d_in[16];
    const float* encwih = (const float*)d_in[17];
    const float* encwhh = (const float*)d_in[18];
    const float* encb   = (const float*)d_in[19];
    const float* decwih = (const float*)d_in[20];
    const float* decwhh = (const float*)d_in[21];
    const float* decb   = (const float*)d_in[22];
    const float* outw   = (const float*)d_in[23];
    const float* outb   = (const float*)d_in[24];
    float* out = (float*)d_out;

    const int fc_smem    = (128 * WPAD + 64 * WPAD + 64 * 128 * 2) * 4;
    const int xproj_smem = (128 * 64 + 128 * BPAD) * 4;
    const int lstm_smem  = (2 * 128 * WPAD + 2 * 32 * 128) * 4;   // 167936 B
    cudaFuncSetAttribute(fc_kernel, cudaFuncAttributeMaxDynamicSharedMemorySize, fc_smem);
    cudaFuncSetAttribute(xproj_kernel, cudaFuncAttributeMaxDynamicSharedMemorySize, xproj_smem);
    cudaFuncSetAttribute(lstm_persistent, cudaFuncAttributeMaxDynamicSharedMemorySize, lstm_smem);

    cnn_kernel<<<CNN_GRID, 128>>>(obs, c1w, c1b, c2w, c2b);
    fc_kernel<<<FC_GRID, 256, fc_smem>>>(fc1w, fc1b, bn1g, bn1b, bn1m, bn1v,
                                         fc2w, fc2b, bn2g, bn2b, bn2m, bn2v);
    xproj_kernel<<<XP_GROUPS * 4, 512, xproj_smem>>>(encwih, encb);

    lstm_persistent<<<128, 256, lstm_smem>>>(encwhh, decwih, decwhh, decb);

    dim3 hgrid(16, 10);
    head_kernel<<<hgrid, 256>>>(outw, outb, out);
}

// round 10
// speedup vs baseline: 4.0521x; 1.0100x over previous
#include <cuda_runtime.h>
#include <math.h>

// ---------------- scratch (static device globals; no allocation) ----------------
__device__ float g_cnn[32768 * 128];     // CNN output per frame
__device__ float g_feats[32768 * 64];    // after FC+BN stack
__device__ float g_xg[32768 * 512];      // precomputed x @ enc_w_ih^T + enc_b
__device__ float g_hdec[10][1024 * 128]; // decoder h history for output head

#define WPAD 132   // weight row pad: 132 % 32 == 4 (conflict-free LDS.128 phases)

__device__ __forceinline__ void fma2(unsigned long long& d,
                                     unsigned long long a, unsigned long long b) {
    asm("fma.rn.f32x2 %0, %1, %2, %0;" : "+l"(d) : "l"(a), "l"(b));
}
__device__ __forceinline__ unsigned long long pack2(float v) {
    unsigned long long r;
    asm("mov.b64 %0, {%1, %1};" : "=l"(r) : "f"(v));
    return r;
}
__device__ __forceinline__ unsigned long long packab(float a, float b) {
    unsigned long long r;
    asm("mov.b64 %0, {%1, %2};" : "=l"(r) : "f"(a), "f"(b));
    return r;
}
__device__ __forceinline__ float ulo(unsigned long long v) {
    return __uint_as_float((unsigned)(v & 0xffffffffull));
}
__device__ __forceinline__ float uhi(unsigned long long v) {
    return __uint_as_float((unsigned)(v >> 32));
}
__device__ __forceinline__ float f2sum(unsigned long long v) { return ulo(v) + uhi(v); }
__device__ __forceinline__ unsigned smem_u32(const void* p) {
    unsigned a;
    asm("{ .reg .u64 t; cvta.to.shared.u64 t, %1; cvt.u32.u64 %0, t; }" : "=r"(a) : "l"(p));
    return a;
}

// ---------------- CNN: persistent, frame-pair packed f32x2 ----------------
#define FPB 4
#define IRS 50
#define CNN_GRID 592
__global__ void __launch_bounds__(128) cnn_kernel(
    const float* __restrict__ obs,
    const float* __restrict__ w1, const float* __restrict__ b1,
    const float* __restrict__ w2, const float* __restrict__ b2)
{
    __shared__ float s_ini[4 * 12 * IRS];      // [ic][y][x-slot*4+f], zero-pad border
    __shared__ float s_p1i[16 * 7 * 2 * 16];   // [oc][r][fp][c*2+f1], zero-pad
    __shared__ float s_w1[576];
    __shared__ float s_b1[16];
    __shared__ float s_w2t[144 * 33];          // [ic*9+q][oc] padded 33
    __shared__ float s_b2[32];

    int tid = threadIdx.x; // 128
    for (int i = tid; i < 4 * 12 * IRS; i += 128) s_ini[i] = 0.f;
    for (int i = tid; i < 16 * 7 * 2 * 16; i += 128) s_p1i[i] = 0.f;
    for (int i = tid; i < 576; i += 128) s_w1[i] = w1[i];
    if (tid < 16) s_b1[tid] = b1[tid];
    for (int i = tid; i < 4608; i += 128) {
        int oc = i / 144, r = i % 144;
        s_w2t[r * 33 + oc] = w2[i];
    }
    if (tid < 32) s_b2[tid] = b2[tid];
    __syncthreads();

    for (long f0 = (long)blockIdx.x * FPB; f0 < 32768; f0 += (long)gridDim.x * FPB) {
        for (int i = tid; i < FPB * 400; i += 128) {
            int f = i / 400, rem = i % 400;
            int ic = rem / 100, p = rem % 100, y = p / 10, x = p % 10;
            s_ini[(ic * 12 + y + 1) * IRS + (x + 1) * 4 + f] = obs[f0 * 400 + i];
        }
        __syncthreads();

        if (tid < 100) {
            int fp = tid / 50, rem = tid % 50, ocg = rem / 25, pos = rem % 25;
            int py = pos / 5, px = pos % 5;
            unsigned long long acc2[8][4];
#pragma unroll
            for (int o = 0; o < 8; o++) {
                unsigned long long bp = pack2(s_b1[ocg * 8 + o]);
#pragma unroll
                for (int p = 0; p < 4; p++) acc2[o][p] = bp;
            }
#pragma unroll
            for (int ic = 0; ic < 4; ic++) {
                unsigned long long patch2[4][4];
#pragma unroll
                for (int r = 0; r < 4; r++)
#pragma unroll
                    for (int cc = 0; cc < 4; cc++)
                        patch2[r][cc] = *(const unsigned long long*)
                            &s_ini[(ic * 12 + 2 * py + r) * IRS + (2 * px + cc) * 4 + fp * 2];
#pragma unroll
                for (int o = 0; o < 8; o++) {
                    int oc = ocg * 8 + o;
#pragma unroll
                    for (int ky = 0; ky < 3; ky++)
#pragma unroll
                        for (int kx = 0; kx < 3; kx++) {
                            unsigned long long wp = pack2(s_w1[(oc * 4 + ic) * 9 + ky * 3 + kx]);
                            fma2(acc2[o][0], patch2[ky][kx], wp);
                            fma2(acc2[o][1], patch2[ky][kx + 1], wp);
                            fma2(acc2[o][2], patch2[ky + 1][kx], wp);
                            fma2(acc2[o][3], patch2[ky + 1][kx + 1], wp);
                        }
                }
            }
#pragma unroll
            for (int o = 0; o < 8; o++) {
                int oc = ocg * 8 + o;
                float mlo = fmaxf(fmaxf(ulo(acc2[o][0]), ulo(acc2[o][1])),
                                  fmaxf(ulo(acc2[o][2]), ulo(acc2[o][3])));
                float mhi = fmaxf(fmaxf(uhi(acc2[o][0]), uhi(acc2[o][1])),
                                  fmaxf(uhi(acc2[o][2]), uhi(acc2[o][3])));
                unsigned long long pk = packab(fmaxf(mlo, 0.f), fmaxf(mhi, 0.f));
                int idx = ((oc * 7 + py + 1) * 2 + fp) * 16 + (px + 1) * 2;
                *(unsigned long long*)&s_p1i[idx] = pk;
            }
        }
        __syncthreads();

        {
            int half = tid >> 6, fp = (tid >> 5) & 1, oc = tid & 31;
            unsigned long long acc2[2][4];
            unsigned long long bp = pack2(s_b2[oc]);
#pragma unroll
            for (int yl = 0; yl < 2; yl++)
#pragma unroll
                for (int x = 0; x < 4; x++) acc2[yl][x] = bp;

            for (int ic = 0; ic < 16; ic++) {
                unsigned long long in2[4][6];
#pragma unroll
                for (int rl = 0; rl < 4; rl++)
#pragma unroll
                    for (int cp = 0; cp < 3; cp++) {
                        ulonglong2 v = *(const ulonglong2*)
                            &s_p1i[((ic * 7 + 2 * half + rl) * 2 + fp) * 16 + cp * 4];
                        in2[rl][2 * cp] = v.x;
                        in2[rl][2 * cp + 1] = v.y;
                    }
#pragma unroll
                for (int ky = 0; ky < 3; ky++)
#pragma unroll
                    for (int kx = 0; kx < 3; kx++) {
                        unsigned long long wp = pack2(s_w2t[(ic * 9 + ky * 3 + kx) * 33 + oc]);
#pragma unroll
                        for (int yl = 0; yl < 2; yl++)
#pragma unroll
                            for (int x = 0; x < 4; x++)
                                fma2(acc2[yl][x], in2[yl + ky][x + kx], wp);
                    }
            }
#pragma unroll
            for (int px = 0; px < 2; px++) {
                float mlo = fmaxf(fmaxf(ulo(acc2[0][2 * px]), ulo(acc2[0][2 * px + 1])),
                                  fmaxf(ulo(acc2[1][2 * px]), ulo(acc2[1][2 * px + 1])));
                float mhi = fmaxf(fmaxf(uhi(acc2[0][2 * px]), uhi(acc2[0][2 * px + 1])),
                                  fmaxf(uhi(acc2[1][2 * px]), uhi(acc2[1][2 * px + 1])));
                long fr = f0 + fp * 2;
                g_cnn[fr * 128 + oc * 4 + half * 2 + px] = fmaxf(mlo, 0.f);
                g_cnn[(fr + 1) * 128 + oc * 4 + half * 2 + px] = fmaxf(mhi, 0.f);
            }
        }
        __syncthreads();
    }
}

// ---------------- FC stack: persistent; fc1+bn1+relu -> fc2+bn2+relu ----------------
#define FC_GRID 148
__global__ void __launch_bounds__(256) fc_kernel(
    const float* __restrict__ fc1w, const float* __restrict__ fc1b,
    const float* __restrict__ g1, const float* __restrict__ be1,
    const float* __restrict__ m1, const float* __restrict__ v1,
    const float* __restrict__ fc2w, const float* __restrict__ fc2b,
    const float* __restrict__ g2, const float* __restrict__ be2,
    const float* __restrict__ m2, const float* __restrict__ v2)
{
    extern __shared__ float sm[];
    float* w1s = sm;                   // 128 rows x WPAD
    float* w2s = w1s + 128 * WPAD;     // 64 rows x WPAD
    float* xs  = w2s + 64 * WPAD;      // 64 x 128 plain
    float* ms  = xs + 64 * 128;        // 64 x 128 plain

    int tid = threadIdx.x;
    for (int i = tid; i < 128 * 128; i += 256) {
        int row = i >> 7, k = i & 127;
        w1s[row * WPAD + k] = fc1w[i];
    }
    for (int i = tid; i < 64 * 128; i += 256) {
        int row = i >> 7, k = i & 127;
        w2s[row * WPAD + k] = fc2w[i];
    }
    int tj = tid & 31, tr = tid >> 5;
    float s1[4], bb1[4], s2[2], bb2[2];
#pragma unroll
    for (int a = 0; a < 4; a++) {
        int j = tj + 32 * a;
        s1[a] = g1[j] * rsqrtf(v1[j] + 1e-5f);
        bb1[a] = (fc1b[j] - m1[j]) * s1[a] + be1[j];
    }
#pragma unroll
    for (int a = 0; a < 2; a++) {
        int j = tj + 32 * a;
        s2[a] = g2[j] * rsqrtf(v2[j] + 1e-5f);
        bb2[a] = (fc2b[j] - m2[j]) * s2[a] + be2[j];
    }

    for (long t = blockIdx.x; t < 512; t += gridDim.x) {
        long r0 = t * 64;
        for (int i = tid; i < 64 * 128; i += 256) xs[i] = g_cnn[r0 * 128 + i];
        __syncthreads();
        {
            unsigned long long acc2[4][8];
#pragma unroll
            for (int a = 0; a < 4; a++)
#pragma unroll
                for (int b = 0; b < 8; b++) acc2[a][b] = 0ull;
            for (int kk = 0; kk < 32; kk++) {
                ulonglong2 w2v[4], h2v[8];
#pragma unroll
                for (int a = 0; a < 4; a++)
                    w2v[a] = *reinterpret_cast<const ulonglong2*>(&w1s[(tj + 32 * a) * WPAD + (kk << 2)]);
#pragma unroll
                for (int b = 0; b < 8; b++)
                    h2v[b] = *reinterpret_cast<const ulonglong2*>(&xs[(tr * 8 + b) * 128 + (kk << 2)]);
#pragma unroll
                for (int a = 0; a < 4; a++)
#pragma unroll
                    for (int b = 0; b < 8; b++) {
                        fma2(acc2[a][b], w2v[a].x, h2v[b].x);
                        fma2(acc2[a][b], w2v[a].y, h2v[b].y);
                    }
            }
#pragma unroll
            for (int a = 0; a < 4; a++) {
                int j = tj + 32 * a;
#pragma unroll
                for (int b = 0; b < 8; b++)
                    ms[(tr * 8 + b) * 128 + j] = fmaxf(f2sum(acc2[a][b]) * s1[a] + bb1[a], 0.f);
            }
        }
        __syncthreads();
        {
            unsigned long long acc2[2][8];
#pragma unroll
            for (int a = 0; a < 2; a++)
#pragma unroll
                for (int b = 0; b < 8; b++) acc2[a][b] = 0ull;
            for (int kk = 0; kk < 32; kk++) {
                ulonglong2 w2v[2], h2v[8];
#pragma unroll
                for (int a = 0; a < 2; a++)
                    w2v[a] = *reinterpret_cast<const ulonglong2*>(&w2s[(tj + 32 * a) * WPAD + (kk << 2)]);
#pragma unroll
                for (int b = 0; b < 8; b++)
                    h2v[b] = *reinterpret_cast<const ulonglong2*>(&ms[(tr * 8 + b) * 128 + (kk << 2)]);
#pragma unroll
                for (int a = 0; a < 2; a++)
#pragma unroll
                    for (int b = 0; b < 8; b++) {
                        fma2(acc2[a][b], w2v[a].x, h2v[b].x);
                        fma2(acc2[a][b], w2v[a].y, h2v[b].y);
                    }
            }
#pragma unroll
            for (int a = 0; a < 2; a++) {
                int j = tj + 32 * a;
#pragma unroll
                for (int b = 0; b < 8; b++)
                    g_feats[(r0 + tr * 8 + b) * 64 + j] = fmaxf(f2sum(acc2[a][b]) * s2[a] + bb2[a], 0.f);
            }
        }
        __syncthreads();
    }
}

// ---------------- encoder x-projection GEMM: persistent, j-panel staged once --------
#define BPAD 68   // 68 % 32 == 4
#define XP_GROUPS 74
__global__ void __launch_bounds__(512) xproj_kernel(const float* __restrict__ wih,
                                                    const float* __restrict__ eb)
{
    extern __shared__ float sm[];
    float* As = sm;               // [128][64] plain (m-major)
    float* Bs = sm + 128 * 64;    // [128][BPAD] (j-major, padded)

    int tid = threadIdx.x;
    int j0 = (blockIdx.x & 3) * 128;
    int grp = blockIdx.x >> 2;    // 0..73

    for (int i = tid; i < 128 * 64; i += 512) {
        int j = i >> 6, k = i & 63;
        Bs[j * BPAD + k] = wih[(long)(j0 + j) * 64 + k];
    }

    int tx = tid & 15, ty = tid >> 4; // ty 0..31
    int m0 = ty * 4;
    float ebv[8];
#pragma unroll
    for (int j = 0; j < 8; j++) ebv[j] = eb[j0 + tx + 16 * j];

    for (int t = grp; t < 256; t += XP_GROUPS) {
        long r0 = (long)t * 128;
        for (int i = tid; i < 128 * 64; i += 512) As[i] = g_feats[r0 * 64 + i];
        __syncthreads();

        unsigned long long acc2[4][8];
#pragma unroll
        for (int i = 0; i < 4; i++)
#pragma unroll
            for (int j = 0; j < 8; j++) acc2[i][j] = 0ull;

        for (int kk = 0; kk < 16; kk++) {
            ulonglong2 a2[4], b2[8];
#pragma unroll
            for (int i = 0; i < 4; i++)
                a2[i] = *reinterpret_cast<const ulonglong2*>(&As[(m0 + i) * 64 + (kk << 2)]);
#pragma unroll
            for (int j = 0; j < 8; j++)
                b2[j] = *reinterpret_cast<const ulonglong2*>(&Bs[(tx + 16 * j) * BPAD + (kk << 2)]);
#pragma unroll
            for (int i = 0; i < 4; i++)
#pragma unroll
                for (int j = 0; j < 8; j++) {
                    fma2(acc2[i][j], a2[i].x, b2[j].x);
                    fma2(acc2[i][j], a2[i].y, b2[j].y);
                }
        }

#pragma unroll
        for (int i = 0; i < 4; i++) {
            long row = (r0 + m0 + i) * 512 + j0;
#pragma unroll
            for (int j = 0; j < 8; j++)
                g_xg[row + tx + 16 * j] = f2sum(acc2[i][j]) + ebv[j];
        }
        __syncthreads();
    }
}

// ---------------- persistent LSTM: clusters of 4, DSMEM h, k-split 16 warps ----------
// grid 128 = 32 clusters x 4 CTAs (u-tiles). 512 threads: warps 0-7 k-low half,
// warps 8-15 k-high half; same weight crossbar traffic, 2x warps/SMSP.
#define SRSTRIDE 17
__global__ void __launch_bounds__(512, 1) __cluster_dims__(4, 1, 1)
lstm_persistent(const float* __restrict__ encw, const float* __restrict__ dwi,
                const float* __restrict__ dwh, const float* __restrict__ decb)
{
    extern __shared__ float sm[];
    float* wse = sm;                     // 128 rows x WPAD encoder slice
    float* wsd = sm + 128 * WPAD;        // 128 rows x WPAD decoder slice (ih+hh)
    float* hs  = sm + 2 * 128 * WPAD;    // 2 buffers x 32 x 128
    float* sred = hs + 2 * 32 * 128;     // 256 x SRSTRIDE reduce pad

    int tid = threadIdx.x;
    unsigned rank = blockIdx.x & 3;
    int b0 = (blockIdx.x >> 2) * 32;
    int u0 = rank * 32;

    for (int i = tid; i < 128 * 128; i += 512) {
        int row = i >> 7, k = i & 127;
        int grow = ((row >> 5) * 128) + u0 + (row & 31);
        wse[row * WPAD + k] = encw[grow * 128 + k];
        wsd[row * WPAD + k] = dwi[grow * 128 + k] + dwh[grow * 128 + k];
    }
    for (int i = tid; i < 32 * 128; i += 512) hs[i] = 0.f;

    unsigned hs_local = smem_u32(hs);
    unsigned rb[4];
#pragma unroll
    for (int r = 0; r < 4; r++)
        asm("mapa.shared::cluster.u32 %0, %1, %2;" : "=r"(rb[r]) : "r"(hs_local), "r"(r));

    __syncthreads();
    asm volatile("barrier.cluster.arrive.aligned;" ::: "memory");
    asm volatile("barrier.cluster.wait.aligned;" ::: "memory");

    int tj = tid & 31;
    int w  = tid >> 5;          // 0..15
    int kh = w >> 3;            // 0 = k-low half, 1 = k-high half
    int tr = w & 7;             // batch rows tr + 8*b
    int u = u0 + tj;
    float db[4];
#pragma unroll
    for (int a = 0; a < 4; a++) db[a] = decb[a * 128 + u];

    float c[4] = {0.f, 0.f, 0.f, 0.f};

    // gate-input prefetch (consumed by kh==0 warps only)
    float xn[4][4];
    if (kh == 0) {
#pragma unroll
        for (int b = 0; b < 4; b++) {
            const float* xr = g_xg + ((long)(b0 + tr + 8 * b) * 32 + 0) * 512;
#pragma unroll
            for (int a = 0; a < 4; a++) xn[b][a] = xr[a * 128 + u];
        }
    }

    int kbase = kh * 16;   // kk-chunk offset (units of 4 floats)
    int pread = 0;
    for (int step = 0; step < 42; step++) {
        const float* ws = (step < 32) ? wse : wsd;
        const float* hsr = hs + pread * (32 * 128);

        unsigned long long acc2[4][4];
#pragma unroll
        for (int a = 0; a < 4; a++)
#pragma unroll
            for (int b = 0; b < 4; b++) acc2[a][b] = 0ull;

        for (int kk = kbase; kk < kbase + 16; kk++) {
            ulonglong2 w2v[4], h2v[4];
#pragma unroll
            for (int a = 0; a < 4; a++)
                w2v[a] = *reinterpret_cast<const ulonglong2*>(&ws[(a * 32 + tj) * WPAD + (kk << 2)]);
#pragma unroll
            for (int b = 0; b < 4; b++)
                h2v[b] = *reinterpret_cast<const ulonglong2*>(&hsr[(tr + 8 * b) * 128 + (kk << 2)]);
#pragma unroll
            for (int a = 0; a < 4; a++)
#pragma unroll
                for (int b = 0; b < 4; b++) {
                    fma2(acc2[a][b], w2v[a].x, h2v[b].x);
                    fma2(acc2[a][b], w2v[a].y, h2v[b].y);
                }
        }

        // k-high warps publish partials; k-low warps reduce + gate math
        if (kh == 1) {
            float* dst = sred + (tid - 256) * SRSTRIDE;
#pragma unroll
            for (int a = 0; a < 4; a++)
#pragma unroll
                for (int b = 0; b < 4; b++) dst[a * 4 + b] = f2sum(acc2[a][b]);
        }
        __syncthreads();

        if (kh == 0) {
            const float* src = sred + tid * SRSTRIDE;
            unsigned woff = (unsigned)((1 - pread) * (32 * 128 * 4));
#pragma unroll
            for (int b = 0; b < 4; b++) {
                int rloc = tr + 8 * b;
                float gi = f2sum(acc2[0][b]) + src[0 * 4 + b] + xn[b][0];
                float gf = f2sum(acc2[1][b]) + src[1 * 4 + b] + xn[b][1];
                float gg = f2sum(acc2[2][b]) + src[2 * 4 + b] + xn[b][2];
                float go = f2sum(acc2[3][b]) + src[3 * 4 + b] + xn[b][3];
                float si = 1.f / (1.f + __expf(-gi));
                float sf = 1.f / (1.f + __expf(-gf));
                float so = 1.f / (1.f + __expf(-go));
                float tg = tanhf(gg);
                float cn = sf * c[b] + si * tg;
                c[b] = cn;
                float hn = so * tanhf(cn);
                if (step < 41) {
                    unsigned eoff = woff + (unsigned)(rloc * 128 + u) * 4u;
#pragma unroll
                    for (int r = 0; r < 4; r++)
                        asm volatile("st.shared::cluster.f32 [%0], %1;"
                                     :: "r"(rb[r] + eoff), "f"(hn) : "memory");
                }
                if (step >= 32) g_hdec[step - 32][(b0 + rloc) * 128 + u] = hn;
            }
        }

        if (step < 41) {
            asm volatile("barrier.cluster.arrive.aligned;" ::: "memory");
            if (kh == 0) {
                if (step + 1 < 32) {
#pragma unroll
                    for (int b = 0; b < 4; b++) {
                        const float* xr = g_xg + ((long)(b0 + tr + 8 * b) * 32 + (step + 1)) * 512;
#pragma unroll
                        for (int a = 0; a < 4; a++) xn[b][a] = xr[a * 128 + u];
                    }
                } else {
#pragma unroll
                    for (int b = 0; b < 4; b++)
#pragma unroll
                        for (int a = 0; a < 4; a++) xn[b][a] = db[a];
                }
            }
            asm volatile("barrier.cluster.wait.aligned;" ::: "memory");
            pread ^= 1;
        }
    }

    asm volatile("barrier.cluster.arrive.aligned;" ::: "memory");
    asm volatile("barrier.cluster.wait.aligned;" ::: "memory");
}

// ---------------- output head ----------------
__global__ void head_kernel(const float* __restrict__ ow, const float* __restrict__ ob,
                            float* __restrict__ out)
{
    __shared__ float hsm[64 * 129];
    __shared__ float wsm[12 * 129];
    __shared__ float bsm[12];
    int tid = threadIdx.x;
    int s = blockIdx.y, b0 = blockIdx.x * 64;
    for (int i = tid; i < 64 * 128; i += 256) {
        int r = i >> 7, k = i & 127;
        hsm[r * 129 + k] = g_hdec[s][(b0 + r) * 128 + k];
    }
    for (int i = tid; i < 12 * 128; i += 256) {
        int r = i / 128, k = i % 128;
        wsm[r * 129 + k] = ow[i];
    }
    if (tid < 12) bsm[tid] = ob[tid];
    __syncthreads();
    for (int it = tid; it < 64 * 12; it += 256) {
        int b = it / 12, v = it % 12;
        float acc = bsm[v];
        for (int k = 0; k < 128; k++) acc += hsm[b * 129 + k] * wsm[v * 129 + k];
        out[(long)(b0 + b) * 120 + s * 12 + v] = acc;
    }
}

// ---------------- launcher ----------------
extern "C" void kernel_launch(void* const* d_in, const int* in_sizes, int n_in,
                              void* d_out, int out_size)
{
    const float* obs    = (const float*)d_in[0];
    const float* c1w    = (const float*)d_in[1];
    const float* c1b    = (const float*)d_in[2];
    const float* c2w    = (const float*)d_in[3];
    const float* c2b    = (const float*)d_in[4];
    const float* fc1w   = (const float*)d_in[5];
    const float* fc1b   = (const float*)d_in[6];
    const float* bn1g   = (const float*)d_in[7];
    const float* bn1b   = (const float*)d_in[8];
    const float* bn1m   = (const float*)d_in[9];
    const float* bn1v   = (const float*)d_in[10];
    const float* fc2w   = (const float*)d_in[11];
    const float* fc2b   = (const float*)d_in[12];
    const float* bn2g   = (const float*)d_in[13];
    const float* bn2b   = (const float*)d_in[14];
    const float* bn2m   = (const float*)d_in[15];
    const float* bn2v   = (const float*)d_in[16];
    const float* encwih = (const float*)d_in[17];
    const float* encwhh = (const float*)d_in[18];
    const float* encb   = (const float*)d_in[19];
    const float* decwih = (const float*)d_in[20];
    const float* decwhh = (const float*)d_in[21];
    const float* decb   = (const float*)d_in[22];
    const float* outw   = (const float*)d_in[23];
    const float* outb   = (const float*)d_in[24];
    float* out = (float*)d_out;

    const int fc_smem    = (128 * WPAD + 64 * WPAD + 64 * 128 * 2) * 4;
    const int xproj_smem = (128 * 64 + 128 * BPAD) * 4;
    const int lstm_smem  = (2 * 128 * WPAD + 2 * 32 * 128 + 256 * SRSTRIDE) * 4; // ~185 KB
    cudaFuncSetAttribute(fc_kernel, cudaFuncAttributeMaxDynamicSharedMemorySize, fc_smem);
    cudaFuncSetAttribute(xproj_kernel, cudaFuncAttributeMaxDynamicSharedMemorySize, xproj_smem);
    cudaFuncSetAttribute(lstm_persistent, cudaFuncAttributeMaxDynamicSharedMemorySize, lstm_smem);

    cnn_kernel<<<CNN_GRID, 128>>>(obs, c1w, c1b, c2w, c2b);
    fc_kernel<<<FC_GRID, 256, fc_smem>>>(fc1w, fc1b, bn1g, bn1b, bn1m, bn1v,
                                         fc2w, fc2b, bn2g, bn2b, bn2m, bn2v);
    xproj_kernel<<<XP_GROUPS * 4, 512, xproj_smem>>>(encwih, encb);

    lstm_persistent<<<128, 512, lstm_smem>>>(encwhh, decwih, decwhh, decb);

    dim3 hgrid(16, 10);
    head_kernel<<<hgrid, 256>>>(outw, outb, out);
}